// round 1
// baseline (speedup 1.0000x reference)
#include <cuda_runtime.h>
#include <cuda_bf16.h>
#include <math.h>

// ----------------------------------------------------------------------------
// HyperGraphModel: X0 = per-type proj(emb); two hypergraph-conv layers;
// out = softmax(fusion_w) . [X0, X1, X2]
//
// All heavy GEMMs have N-dim = 128 exactly (D=128), so the GEMM kernel is
// specialized: CTA tile 128(M) x 128(N) x 32(K), 8 warps, warp tile 32x64,
// mma.sync.m16n8k8 tf32 with fp32 accumulation.
// ----------------------------------------------------------------------------

#define BM 128
#define BN 128
#define BK 32

// scratch: X0, X1, X2, Y (each N*D) + m (E*D)
// 4*20000*128 + 8000*128 = 11,264,000 floats
__device__ float g_buf[11264000];

__device__ __forceinline__ unsigned f2tf32(float x) {
    unsigned r;
    asm("cvt.rna.tf32.f32 %0, %1;" : "=r"(r) : "f"(x));
    return r;
}

__device__ __forceinline__ void mma_tf32(float* c, const unsigned* a, const unsigned* b) {
    asm volatile(
        "mma.sync.aligned.m16n8k8.row.col.f32.tf32.tf32.f32 "
        "{%0,%1,%2,%3}, {%4,%5,%6,%7}, {%8,%9}, {%0,%1,%2,%3};\n"
        : "+f"(c[0]), "+f"(c[1]), "+f"(c[2]), "+f"(c[3])
        : "r"(a[0]), "r"(a[1]), "r"(a[2]), "r"(a[3]),
          "r"(b[0]), "r"(b[1]));
}

// C[M,128] = op(A)[M,K] * B[K,128]
//   TRANS_A=false: A row-major [M,K], element (m,k) = A[m*lda + k]   (lda=K)
//   TRANS_A=true : A stored [K,M], element (m,k) = A[k*lda + m]      (lda=M stride, e.g. H with lda=E)
// ATOMIC=true : atomicAdd rowscale[m]*acc into C (split-K; C must be pre-zeroed; bias unused)
// ATOMIC=false: C[m,n] = rowscale[m] * (acc + bias[n]);  optional row select (rowsel[m]==blockIdx.z)
// blockIdx.z offsets B by ldbz and bias by biasz (used for per-type projections).
template <bool TRANS_A, bool ATOMIC>
__global__ void __launch_bounds__(256, 2)
gemm128(const float* __restrict__ A, const float* __restrict__ B,
        float* __restrict__ C, int M, int K, int lda,
        const float* __restrict__ bias, const float* __restrict__ rowscale,
        const int* __restrict__ rowsel,
        int ldbz, int biasz, int kChunk)
{
    __shared__ float As[BM][BK + 4];   // +4 pad: conflict-free a-frag LDS
    __shared__ float Bs[BK][BN + 8];   // +8 pad: conflict-free b-frag LDS

    const int m0 = blockIdx.x * BM;
    const int kBegin = blockIdx.y * kChunk;
    const int kEnd = min(K, kBegin + kChunk);
    if (kBegin >= K) return;

    const int zt = blockIdx.z;
    B += (size_t)zt * ldbz;
    if (bias) bias += (size_t)zt * biasz;

    const int tidx = threadIdx.x;
    const int lane = tidx & 31;
    const int g  = lane >> 2;     // groupID 0..7
    const int tg = lane & 3;      // thread-in-group 0..3
    const int wm = (tidx >> 5) & 3;   // warp row 0..3 (32 M-rows each)
    const int wn = (tidx >> 7);       // warp col 0..1 (64 N-cols each)

    float acc[2][8][4];
#pragma unroll
    for (int mi = 0; mi < 2; mi++)
#pragma unroll
        for (int ni = 0; ni < 8; ni++)
#pragma unroll
            for (int j = 0; j < 4; j++) acc[mi][ni][j] = 0.f;

    for (int kt = kBegin; kt < kEnd; kt += BK) {
        // ---- load A tile -> As[m][k] ----
        if (!TRANS_A) {
#pragma unroll
            for (int i = 0; i < 4; i++) {
                int idx = tidx + i * 256;          // 0..1023 float4 slots
                int m  = idx >> 3;                 // 0..127
                int k4 = (idx & 7) << 2;           // 0,4,...,28
                float4 v = make_float4(0.f, 0.f, 0.f, 0.f);
                if (m0 + m < M)
                    v = *(const float4*)&A[(size_t)(m0 + m) * lda + kt + k4];
                As[m][k4 + 0] = v.x; As[m][k4 + 1] = v.y;
                As[m][k4 + 2] = v.z; As[m][k4 + 3] = v.w;
            }
        } else {
#pragma unroll
            for (int i = 0; i < 4; i++) {
                int idx = tidx + i * 256;
                int k  = idx >> 5;                 // 0..31
                int m4 = (idx & 31) << 2;          // 0,4,...,124
                int gm = m0 + m4;
                const float* src = &A[(size_t)(kt + k) * lda + gm];
                float4 v = make_float4(0.f, 0.f, 0.f, 0.f);
                if (gm + 3 < M) {
                    v = *(const float4*)src;
                } else {
                    if (gm + 0 < M) v.x = src[0];
                    if (gm + 1 < M) v.y = src[1];
                    if (gm + 2 < M) v.z = src[2];
                    if (gm + 3 < M) v.w = src[3];
                }
                As[m4 + 0][k] = v.x; As[m4 + 1][k] = v.y;
                As[m4 + 2][k] = v.z; As[m4 + 3][k] = v.w;
            }
        }
        // ---- load B tile -> Bs[k][n] ----
#pragma unroll
        for (int i = 0; i < 4; i++) {
            int idx = tidx + i * 256;
            int k  = idx >> 5;                     // 0..31
            int n4 = (idx & 31) << 2;              // 0..124
            float4 v = *(const float4*)&B[(size_t)(kt + k) * 128 + n4];
            Bs[k][n4 + 0] = v.x; Bs[k][n4 + 1] = v.y;
            Bs[k][n4 + 2] = v.z; Bs[k][n4 + 3] = v.w;
        }
        __syncthreads();

        // ---- compute: 4 k-steps of m16n8k8 ----
#pragma unroll
        for (int kk = 0; kk < BK; kk += 8) {
            unsigned af[2][4];
#pragma unroll
            for (int mi = 0; mi < 2; mi++) {
                int bm = wm * 32 + mi * 16;
                af[mi][0] = f2tf32(As[bm + g    ][kk + tg    ]);
                af[mi][1] = f2tf32(As[bm + g + 8][kk + tg    ]);
                af[mi][2] = f2tf32(As[bm + g    ][kk + tg + 4]);
                af[mi][3] = f2tf32(As[bm + g + 8][kk + tg + 4]);
            }
            unsigned bf[8][2];
#pragma unroll
            for (int ni = 0; ni < 8; ni++) {
                int bn = wn * 64 + ni * 8;
                bf[ni][0] = f2tf32(Bs[kk + tg    ][bn + g]);
                bf[ni][1] = f2tf32(Bs[kk + tg + 4][bn + g]);
            }
#pragma unroll
            for (int mi = 0; mi < 2; mi++)
#pragma unroll
                for (int ni = 0; ni < 8; ni++)
                    mma_tf32(acc[mi][ni], af[mi], bf[ni]);
        }
        __syncthreads();
    }

    // ---- epilogue ----
#pragma unroll
    for (int mi = 0; mi < 2; mi++) {
#pragma unroll
        for (int h = 0; h < 2; h++) {
            int r = m0 + wm * 32 + mi * 16 + g + h * 8;
            if (r >= M) continue;
            if (!ATOMIC && rowsel && rowsel[r] != zt) continue;
            float rs = rowscale ? rowscale[r] : 1.f;
#pragma unroll
            for (int ni = 0; ni < 8; ni++) {
                int cc = wn * 64 + ni * 8 + tg * 2;
                float v0 = acc[mi][ni][h * 2 + 0];
                float v1 = acc[mi][ni][h * 2 + 1];
                if (ATOMIC) {
                    atomicAdd(&C[(size_t)r * 128 + cc    ], v0 * rs);
                    atomicAdd(&C[(size_t)r * 128 + cc + 1], v1 * rs);
                } else {
                    if (bias) { v0 += bias[cc]; v1 += bias[cc + 1]; }
                    v0 *= rs; v1 *= rs;
                    C[(size_t)r * 128 + cc    ] = v0;
                    C[(size_t)r * 128 + cc + 1] = v1;
                }
            }
        }
    }
}

__global__ void zero_kernel(float* __restrict__ p, int n) {
    int i = blockIdx.x * blockDim.x + threadIdx.x;
    if (i < n) p[i] = 0.f;
}

__global__ void fusion_kernel(const float* __restrict__ fw,
                              const float* __restrict__ X0,
                              const float* __restrict__ X1,
                              const float* __restrict__ X2,
                              float* __restrict__ out, int n) {
    float f0 = fw[0], f1 = fw[1], f2 = fw[2];
    float mx = fmaxf(f0, fmaxf(f1, f2));
    float e0 = expf(f0 - mx), e1 = expf(f1 - mx), e2 = expf(f2 - mx);
    float inv = 1.f / (e0 + e1 + e2);
    float w0 = e0 * inv, w1 = e1 * inv, w2 = e2 * inv;
    int i = blockIdx.x * blockDim.x + threadIdx.x;
    if (i < n) out[i] = w0 * X0[i] + w1 * X1[i] + w2 * X2[i];
}

static inline int chunk_for(int K, int S) {
    // k-chunk per split, multiple of BK
    int tiles = (K + BK - 1) / BK;
    int per = (tiles + S - 1) / S;
    return per * BK;
}

extern "C" void kernel_launch(void* const* d_in, const int* in_sizes, int n_in,
                              void* d_out, int out_size) {
    const float* emb = (const float*)d_in[0];
    const float* Wt  = (const float*)d_in[1];
    const float* bt  = (const float*)d_in[2];
    const float* W1  = (const float*)d_in[3];
    const float* b1  = (const float*)d_in[4];
    const float* W2  = (const float*)d_in[5];
    const float* b2  = (const float*)d_in[6];
    const float* fw  = (const float*)d_in[7];
    const float* H   = (const float*)d_in[8];
    const float* dv  = (const float*)d_in[9];
    const float* de  = (const float*)d_in[10];
    const int*   tid = (const int*)d_in[11];

    const int D = in_sizes[4];          // 128
    const int N = in_sizes[9];          // 20000
    const int E = in_sizes[10];         // 8000
    const int T = in_sizes[2] / D;      // 5

    float* buf = nullptr;
    cudaGetSymbolAddress((void**)&buf, g_buf);
    size_t nd = (size_t)N * D, ed = (size_t)E * D;
    float* X0 = buf;
    float* X1 = X0 + nd;
    float* X2 = X1 + nd;
    float* Y  = X2 + nd;
    float* Mm = Y + nd;

    dim3 blk(256);
    int mt_n = (N + BM - 1) / BM;       // 157
    int mt_e = (E + BM - 1) / BM;       // 63
    const int S1 = 8;                   // split-K for H^T @ Y (K = N)
    const int S2 = 4;                   // split-K for H @ m   (K = E)
    int ch1 = chunk_for(N, S1);
    int ch2 = chunk_for(E, S2);
    int zthreads = 256;

    // ---- X0: per-type projection with fused type-select ----
    gemm128<false, false><<<dim3(mt_n, 1, T), blk>>>(
        emb, Wt, X0, N, D, D, bt, nullptr, tid, D * D, D, D);

    // ======== hgc layer 1 ========
    // Y = dv * (X0 @ W1 + b1)
    gemm128<false, false><<<dim3(mt_n, 1, 1), blk>>>(
        X0, W1, Y, N, D, D, b1, dv, nullptr, 0, 0, D);
    // m = de * (H^T @ Y)
    zero_kernel<<<(int)((ed + zthreads - 1) / zthreads), zthreads>>>(Mm, (int)ed);
    gemm128<true, true><<<dim3(mt_e, S1, 1), blk>>>(
        H, Y, Mm, E, N, E, nullptr, de, nullptr, 0, 0, ch1);
    // X1 = dv * (H @ m)
    zero_kernel<<<(int)((nd + zthreads - 1) / zthreads), zthreads>>>(X1, (int)nd);
    gemm128<false, true><<<dim3(mt_n, S2, 1), blk>>>(
        H, Mm, X1, N, E, E, nullptr, dv, nullptr, 0, 0, ch2);

    // ======== hgc layer 2 ========
    gemm128<false, false><<<dim3(mt_n, 1, 1), blk>>>(
        X1, W2, Y, N, D, D, b2, dv, nullptr, 0, 0, D);
    zero_kernel<<<(int)((ed + zthreads - 1) / zthreads), zthreads>>>(Mm, (int)ed);
    gemm128<true, true><<<dim3(mt_e, S1, 1), blk>>>(
        H, Y, Mm, E, N, E, nullptr, de, nullptr, 0, 0, ch1);
    zero_kernel<<<(int)((nd + zthreads - 1) / zthreads), zthreads>>>(X2, (int)nd);
    gemm128<false, true><<<dim3(mt_n, S2, 1), blk>>>(
        H, Mm, X2, N, E, E, nullptr, dv, nullptr, 0, 0, ch2);

    // ---- fusion ----
    fusion_kernel<<<(int)((nd + zthreads - 1) / zthreads), zthreads>>>(
        fw, X0, X1, X2, (float*)d_out, (int)nd);
}

// round 2
// speedup vs baseline: 1.0011x; 1.0011x over previous
#include <cuda_runtime.h>
#include <cuda_bf16.h>
#include <math.h>

// ----------------------------------------------------------------------------
// HyperGraphModel: X0 = per-type proj(emb); two hypergraph-conv layers;
// out = softmax(fusion_w) . [X0, X1, X2]
//
// All heavy GEMMs have N-dim = 128 exactly (D=128), so the GEMM kernel is
// specialized: CTA tile 128(M) x 128(N) x 32(K), 8 warps, warp tile 32x64,
// mma.sync.m16n8k8 tf32 with fp32 accumulation.
// ----------------------------------------------------------------------------

#define BM 128
#define BN 128
#define BK 32

// scratch: X0, X1, X2, Y (each N*D) + m (E*D)
// 4*20000*128 + 8000*128 = 11,264,000 floats
__device__ float g_buf[11264000];

__device__ __forceinline__ unsigned f2tf32(float x) {
    unsigned r;
    asm("cvt.rna.tf32.f32 %0, %1;" : "=r"(r) : "f"(x));
    return r;
}

__device__ __forceinline__ void mma_tf32(float* c, const unsigned* a, const unsigned* b) {
    asm volatile(
        "mma.sync.aligned.m16n8k8.row.col.f32.tf32.tf32.f32 "
        "{%0,%1,%2,%3}, {%4,%5,%6,%7}, {%8,%9}, {%0,%1,%2,%3};\n"
        : "+f"(c[0]), "+f"(c[1]), "+f"(c[2]), "+f"(c[3])
        : "r"(a[0]), "r"(a[1]), "r"(a[2]), "r"(a[3]),
          "r"(b[0]), "r"(b[1]));
}

// C[M,128] = op(A)[M,K] * B[K,128]
//   TRANS_A=false: A row-major [M,K], element (m,k) = A[m*lda + k]   (lda=K)
//   TRANS_A=true : A stored [K,M], element (m,k) = A[k*lda + m]      (lda=M stride, e.g. H with lda=E)
// ATOMIC=true : atomicAdd rowscale[m]*acc into C (split-K; C must be pre-zeroed; bias unused)
// ATOMIC=false: C[m,n] = rowscale[m] * (acc + bias[n]);  optional row select (rowsel[m]==blockIdx.z)
// blockIdx.z offsets B by ldbz and bias by biasz (used for per-type projections).
template <bool TRANS_A, bool ATOMIC>
__global__ void __launch_bounds__(256, 2)
gemm128(const float* __restrict__ A, const float* __restrict__ B,
        float* __restrict__ C, int M, int K, int lda,
        const float* __restrict__ bias, const float* __restrict__ rowscale,
        const int* __restrict__ rowsel,
        int ldbz, int biasz, int kChunk)
{
    __shared__ float As[BM][BK + 4];   // +4 pad: conflict-free a-frag LDS
    __shared__ float Bs[BK][BN + 8];   // +8 pad: conflict-free b-frag LDS

    const int m0 = blockIdx.x * BM;
    const int kBegin = blockIdx.y * kChunk;
    const int kEnd = min(K, kBegin + kChunk);
    if (kBegin >= K) return;

    const int zt = blockIdx.z;
    B += (size_t)zt * ldbz;
    if (bias) bias += (size_t)zt * biasz;

    const int tidx = threadIdx.x;
    const int lane = tidx & 31;
    const int g  = lane >> 2;     // groupID 0..7
    const int tg = lane & 3;      // thread-in-group 0..3
    const int wm = (tidx >> 5) & 3;   // warp row 0..3 (32 M-rows each)
    const int wn = (tidx >> 7);       // warp col 0..1 (64 N-cols each)

    float acc[2][8][4];
#pragma unroll
    for (int mi = 0; mi < 2; mi++)
#pragma unroll
        for (int ni = 0; ni < 8; ni++)
#pragma unroll
            for (int j = 0; j < 4; j++) acc[mi][ni][j] = 0.f;

    for (int kt = kBegin; kt < kEnd; kt += BK) {
        // ---- load A tile -> As[m][k] ----
        if (!TRANS_A) {
#pragma unroll
            for (int i = 0; i < 4; i++) {
                int idx = tidx + i * 256;          // 0..1023 float4 slots
                int m  = idx >> 3;                 // 0..127
                int k4 = (idx & 7) << 2;           // 0,4,...,28
                float4 v = make_float4(0.f, 0.f, 0.f, 0.f);
                if (m0 + m < M)
                    v = *(const float4*)&A[(size_t)(m0 + m) * lda + kt + k4];
                As[m][k4 + 0] = v.x; As[m][k4 + 1] = v.y;
                As[m][k4 + 2] = v.z; As[m][k4 + 3] = v.w;
            }
        } else {
#pragma unroll
            for (int i = 0; i < 4; i++) {
                int idx = tidx + i * 256;
                int k  = idx >> 5;                 // 0..31
                int m4 = (idx & 31) << 2;          // 0,4,...,124
                int gm = m0 + m4;
                const float* src = &A[(size_t)(kt + k) * lda + gm];
                float4 v = make_float4(0.f, 0.f, 0.f, 0.f);
                if (gm + 3 < M) {
                    v = *(const float4*)src;
                } else {
                    if (gm + 0 < M) v.x = src[0];
                    if (gm + 1 < M) v.y = src[1];
                    if (gm + 2 < M) v.z = src[2];
                    if (gm + 3 < M) v.w = src[3];
                }
                As[m4 + 0][k] = v.x; As[m4 + 1][k] = v.y;
                As[m4 + 2][k] = v.z; As[m4 + 3][k] = v.w;
            }
        }
        // ---- load B tile -> Bs[k][n] ----
#pragma unroll
        for (int i = 0; i < 4; i++) {
            int idx = tidx + i * 256;
            int k  = idx >> 5;                     // 0..31
            int n4 = (idx & 31) << 2;              // 0..124
            float4 v = *(const float4*)&B[(size_t)(kt + k) * 128 + n4];
            Bs[k][n4 + 0] = v.x; Bs[k][n4 + 1] = v.y;
            Bs[k][n4 + 2] = v.z; Bs[k][n4 + 3] = v.w;
        }
        __syncthreads();

        // ---- compute: 4 k-steps of m16n8k8 ----
#pragma unroll
        for (int kk = 0; kk < BK; kk += 8) {
            unsigned af[2][4];
#pragma unroll
            for (int mi = 0; mi < 2; mi++) {
                int bm = wm * 32 + mi * 16;
                af[mi][0] = f2tf32(As[bm + g    ][kk + tg    ]);
                af[mi][1] = f2tf32(As[bm + g + 8][kk + tg    ]);
                af[mi][2] = f2tf32(As[bm + g    ][kk + tg + 4]);
                af[mi][3] = f2tf32(As[bm + g + 8][kk + tg + 4]);
            }
            unsigned bf[8][2];
#pragma unroll
            for (int ni = 0; ni < 8; ni++) {
                int bn = wn * 64 + ni * 8;
                bf[ni][0] = f2tf32(Bs[kk + tg    ][bn + g]);
                bf[ni][1] = f2tf32(Bs[kk + tg + 4][bn + g]);
            }
#pragma unroll
            for (int mi = 0; mi < 2; mi++)
#pragma unroll
                for (int ni = 0; ni < 8; ni++)
                    mma_tf32(acc[mi][ni], af[mi], bf[ni]);
        }
        __syncthreads();
    }

    // ---- epilogue ----
#pragma unroll
    for (int mi = 0; mi < 2; mi++) {
#pragma unroll
        for (int h = 0; h < 2; h++) {
            int r = m0 + wm * 32 + mi * 16 + g + h * 8;
            if (r >= M) continue;
            if (!ATOMIC && rowsel && rowsel[r] != zt) continue;
            float rs = rowscale ? rowscale[r] : 1.f;
#pragma unroll
            for (int ni = 0; ni < 8; ni++) {
                int cc = wn * 64 + ni * 8 + tg * 2;
                float v0 = acc[mi][ni][h * 2 + 0];
                float v1 = acc[mi][ni][h * 2 + 1];
                if (ATOMIC) {
                    atomicAdd(&C[(size_t)r * 128 + cc    ], v0 * rs);
                    atomicAdd(&C[(size_t)r * 128 + cc + 1], v1 * rs);
                } else {
                    if (bias) { v0 += bias[cc]; v1 += bias[cc + 1]; }
                    v0 *= rs; v1 *= rs;
                    C[(size_t)r * 128 + cc    ] = v0;
                    C[(size_t)r * 128 + cc + 1] = v1;
                }
            }
        }
    }
}

__global__ void zero_kernel(float* __restrict__ p, int n) {
    int i = blockIdx.x * blockDim.x + threadIdx.x;
    if (i < n) p[i] = 0.f;
}

__global__ void fusion_kernel(const float* __restrict__ fw,
                              const float* __restrict__ X0,
                              const float* __restrict__ X1,
                              const float* __restrict__ X2,
                              float* __restrict__ out, int n) {
    float f0 = fw[0], f1 = fw[1], f2 = fw[2];
    float mx = fmaxf(f0, fmaxf(f1, f2));
    float e0 = expf(f0 - mx), e1 = expf(f1 - mx), e2 = expf(f2 - mx);
    float inv = 1.f / (e0 + e1 + e2);
    float w0 = e0 * inv, w1 = e1 * inv, w2 = e2 * inv;
    int i = blockIdx.x * blockDim.x + threadIdx.x;
    if (i < n) out[i] = w0 * X0[i] + w1 * X1[i] + w2 * X2[i];
}

static inline int chunk_for(int K, int S) {
    // k-chunk per split, multiple of BK
    int tiles = (K + BK - 1) / BK;
    int per = (tiles + S - 1) / S;
    return per * BK;
}

extern "C" void kernel_launch(void* const* d_in, const int* in_sizes, int n_in,
                              void* d_out, int out_size) {
    const float* emb = (const float*)d_in[0];
    const float* Wt  = (const float*)d_in[1];
    const float* bt  = (const float*)d_in[2];
    const float* W1  = (const float*)d_in[3];
    const float* b1  = (const float*)d_in[4];
    const float* W2  = (const float*)d_in[5];
    const float* b2  = (const float*)d_in[6];
    const float* fw  = (const float*)d_in[7];
    const float* H   = (const float*)d_in[8];
    const float* dv  = (const float*)d_in[9];
    const float* de  = (const float*)d_in[10];
    const int*   tid = (const int*)d_in[11];

    const int D = in_sizes[4];          // 128
    const int N = in_sizes[9];          // 20000
    const int E = in_sizes[10];         // 8000
    const int T = in_sizes[2] / D;      // 5

    float* buf = nullptr;
    cudaGetSymbolAddress((void**)&buf, g_buf);
    size_t nd = (size_t)N * D, ed = (size_t)E * D;
    float* X0 = buf;
    float* X1 = X0 + nd;
    float* X2 = X1 + nd;
    float* Y  = X2 + nd;
    float* Mm = Y + nd;

    dim3 blk(256);
    int mt_n = (N + BM - 1) / BM;       // 157
    int mt_e = (E + BM - 1) / BM;       // 63
    const int S1 = 8;                   // split-K for H^T @ Y (K = N)
    const int S2 = 4;                   // split-K for H @ m   (K = E)
    int ch1 = chunk_for(N, S1);
    int ch2 = chunk_for(E, S2);
    int zthreads = 256;

    // ---- X0: per-type projection with fused type-select ----
    gemm128<false, false><<<dim3(mt_n, 1, T), blk>>>(
        emb, Wt, X0, N, D, D, bt, nullptr, tid, D * D, D, D);

    // ======== hgc layer 1 ========
    // Y = dv * (X0 @ W1 + b1)
    gemm128<false, false><<<dim3(mt_n, 1, 1), blk>>>(
        X0, W1, Y, N, D, D, b1, dv, nullptr, 0, 0, D);
    // m = de * (H^T @ Y)
    zero_kernel<<<(int)((ed + zthreads - 1) / zthreads), zthreads>>>(Mm, (int)ed);
    gemm128<true, true><<<dim3(mt_e, S1, 1), blk>>>(
        H, Y, Mm, E, N, E, nullptr, de, nullptr, 0, 0, ch1);
    // X1 = dv * (H @ m)
    zero_kernel<<<(int)((nd + zthreads - 1) / zthreads), zthreads>>>(X1, (int)nd);
    gemm128<false, true><<<dim3(mt_n, S2, 1), blk>>>(
        H, Mm, X1, N, E, E, nullptr, dv, nullptr, 0, 0, ch2);

    // ======== hgc layer 2 ========
    gemm128<false, false><<<dim3(mt_n, 1, 1), blk>>>(
        X1, W2, Y, N, D, D, b2, dv, nullptr, 0, 0, D);
    zero_kernel<<<(int)((ed + zthreads - 1) / zthreads), zthreads>>>(Mm, (int)ed);
    gemm128<true, true><<<dim3(mt_e, S1, 1), blk>>>(
        H, Y, Mm, E, N, E, nullptr, de, nullptr, 0, 0, ch1);
    zero_kernel<<<(int)((nd + zthreads - 1) / zthreads), zthreads>>>(X2, (int)nd);
    gemm128<false, true><<<dim3(mt_n, S2, 1), blk>>>(
        H, Mm, X2, N, E, E, nullptr, dv, nullptr, 0, 0, ch2);

    // ---- fusion ----
    fusion_kernel<<<(int)((nd + zthreads - 1) / zthreads), zthreads>>>(
        fw, X0, X1, X2, (float*)d_out, (int)nd);
}

// round 3
// speedup vs baseline: 1.2183x; 1.2169x over previous
#include <cuda_runtime.h>
#include <cuda_bf16.h>
#include <math.h>

// ----------------------------------------------------------------------------
// HyperGraphModel: X0 = per-type proj(emb); two hypergraph-conv layers;
// out = softmax(fusion_w) . [X0, X1, X2]
//
// GEMM kernel: CTA tile 128x128x32, 8 warps, warp tile 32x64,
// mma.sync.m16n8k8 tf32, fp32 accum. SMEM holds pre-converted tf32 words.
// TRANS_A uses a [k][m] SMEM layout so both the coalesced global load and the
// SMEM store/read paths are bank-conflict free.
// ----------------------------------------------------------------------------

#define BM 128
#define BN 128
#define BK 32

// scratch: X0, X1, X2, Y (each N*D) + m (E*D)
__device__ float g_buf[11264000];

__device__ __forceinline__ unsigned f2tf32(float x) {
    unsigned r;
    asm("cvt.rna.tf32.f32 %0, %1;" : "=r"(r) : "f"(x));
    return r;
}

__device__ __forceinline__ void mma_tf32(float* c, const unsigned* a, const unsigned* b) {
    asm volatile(
        "mma.sync.aligned.m16n8k8.row.col.f32.tf32.tf32.f32 "
        "{%0,%1,%2,%3}, {%4,%5,%6,%7}, {%8,%9}, {%0,%1,%2,%3};\n"
        : "+f"(c[0]), "+f"(c[1]), "+f"(c[2]), "+f"(c[3])
        : "r"(a[0]), "r"(a[1]), "r"(a[2]), "r"(a[3]),
          "r"(b[0]), "r"(b[1]));
}

// C[M,128] = op(A)[M,K] * B[K,128]
//   TRANS_A=false: A row-major [M,K]   (lda = K)
//   TRANS_A=true : A stored [K,M], element (m,k) = A[k*lda + m]  (lda = row stride)
// ATOMIC=true : atomicAdd rowscale[m]*acc into pre-zeroed C (split-K)
// ATOMIC=false: C[m,n] = rowscale[m]*(acc + bias[n]); optional rowsel gating.
// blockIdx.z offsets B by ldbz and bias by biasz (per-type projections).
template <bool TRANS_A, bool ATOMIC>
__global__ void __launch_bounds__(256, 2)
gemm128(const float* __restrict__ A, const float* __restrict__ B,
        float* __restrict__ C, int M, int K, int lda,
        const float* __restrict__ bias, const float* __restrict__ rowscale,
        const int* __restrict__ rowsel,
        int ldbz, int biasz, int kChunk)
{
    // A tile: TRANS -> [BK][BM+8] (pitch 136), else [BM][BK+4] (pitch 36)
    __shared__ __align__(16) unsigned As[TRANS_A ? BK * (BM + 8) : BM * (BK + 4)];
    __shared__ __align__(16) unsigned Bs[BK * (BN + 8)];

    const int m0 = blockIdx.x * BM;
    const int kBegin = blockIdx.y * kChunk;
    const int kEnd = min(K, kBegin + kChunk);
    if (kBegin >= K) return;

    const int zt = blockIdx.z;
    B += (size_t)zt * ldbz;
    if (bias) bias += (size_t)zt * biasz;

    const int tidx = threadIdx.x;
    const int lane = tidx & 31;
    const int g  = lane >> 2;         // 0..7
    const int tg = lane & 3;          // 0..3
    const int wm = (tidx >> 5) & 3;   // warp row (32 M-rows)
    const int wn = (tidx >> 7);       // warp col (64 N-cols)

    float acc[2][8][4];
#pragma unroll
    for (int mi = 0; mi < 2; mi++)
#pragma unroll
        for (int ni = 0; ni < 8; ni++)
#pragma unroll
            for (int j = 0; j < 4; j++) acc[mi][ni][j] = 0.f;

    for (int kt = kBegin; kt < kEnd; kt += BK) {
        // ---- load + convert A tile ----
        if (!TRANS_A) {
            // A row-major: float4 along k; store As[m][k4..k4+3] (STS.128)
#pragma unroll
            for (int i = 0; i < 4; i++) {
                int idx = tidx + i * 256;
                int m  = idx >> 3;               // 0..127
                int k4 = (idx & 7) << 2;         // 0..28
                float4 v = make_float4(0.f, 0.f, 0.f, 0.f);
                if (m0 + m < M)
                    v = *(const float4*)&A[(size_t)(m0 + m) * lda + kt + k4];
                uint4 u = make_uint4(f2tf32(v.x), f2tf32(v.y), f2tf32(v.z), f2tf32(v.w));
                *(uint4*)&As[m * (BK + 4) + k4] = u;
            }
        } else {
            // A column-of-C-major: float4 along m; store As_T[k][m4..m4+3] (STS.128,
            // lanes consecutive in m -> conflict-free)
#pragma unroll
            for (int i = 0; i < 4; i++) {
                int idx = tidx + i * 256;
                int k  = idx >> 5;               // 0..31 (uniform per warp)
                int m4 = (idx & 31) << 2;        // lane*4
                int gm = m0 + m4;
                const float* src = &A[(size_t)(kt + k) * lda + gm];
                float4 v = make_float4(0.f, 0.f, 0.f, 0.f);
                if (gm + 3 < M) {
                    v = *(const float4*)src;
                } else {
                    if (gm + 0 < M) v.x = src[0];
                    if (gm + 1 < M) v.y = src[1];
                    if (gm + 2 < M) v.z = src[2];
                }
                uint4 u = make_uint4(f2tf32(v.x), f2tf32(v.y), f2tf32(v.z), f2tf32(v.w));
                *(uint4*)&As[k * (BM + 8) + m4] = u;
            }
        }
        // ---- load + convert B tile -> Bs[k][n] (STS.128 conflict-free) ----
#pragma unroll
        for (int i = 0; i < 4; i++) {
            int idx = tidx + i * 256;
            int k  = idx >> 5;
            int n4 = (idx & 31) << 2;
            float4 v = *(const float4*)&B[(size_t)(kt + k) * 128 + n4];
            uint4 u = make_uint4(f2tf32(v.x), f2tf32(v.y), f2tf32(v.z), f2tf32(v.w));
            *(uint4*)&Bs[k * (BN + 8) + n4] = u;
        }
        __syncthreads();

        // ---- compute: 4 k-steps of m16n8k8 (pure LDS + HMMA, conflict-free) ----
#pragma unroll
        for (int kk = 0; kk < BK; kk += 8) {
            unsigned af[2][4];
#pragma unroll
            for (int mi = 0; mi < 2; mi++) {
                int bm = wm * 32 + mi * 16;
                if (!TRANS_A) {
                    af[mi][0] = As[(bm + g    ) * (BK + 4) + kk + tg    ];
                    af[mi][1] = As[(bm + g + 8) * (BK + 4) + kk + tg    ];
                    af[mi][2] = As[(bm + g    ) * (BK + 4) + kk + tg + 4];
                    af[mi][3] = As[(bm + g + 8) * (BK + 4) + kk + tg + 4];
                } else {
                    af[mi][0] = As[(kk + tg    ) * (BM + 8) + bm + g    ];
                    af[mi][1] = As[(kk + tg    ) * (BM + 8) + bm + g + 8];
                    af[mi][2] = As[(kk + tg + 4) * (BM + 8) + bm + g    ];
                    af[mi][3] = As[(kk + tg + 4) * (BM + 8) + bm + g + 8];
                }
            }
            unsigned bf[8][2];
#pragma unroll
            for (int ni = 0; ni < 8; ni++) {
                int bn = wn * 64 + ni * 8;
                bf[ni][0] = Bs[(kk + tg    ) * (BN + 8) + bn + g];
                bf[ni][1] = Bs[(kk + tg + 4) * (BN + 8) + bn + g];
            }
#pragma unroll
            for (int mi = 0; mi < 2; mi++)
#pragma unroll
                for (int ni = 0; ni < 8; ni++)
                    mma_tf32(acc[mi][ni], af[mi], bf[ni]);
        }
        __syncthreads();
    }

    // ---- epilogue ----
#pragma unroll
    for (int mi = 0; mi < 2; mi++) {
#pragma unroll
        for (int h = 0; h < 2; h++) {
            int r = m0 + wm * 32 + mi * 16 + g + h * 8;
            if (r >= M) continue;
            if (!ATOMIC && rowsel && rowsel[r] != zt) continue;
            float rs = rowscale ? rowscale[r] : 1.f;
#pragma unroll
            for (int ni = 0; ni < 8; ni++) {
                int cc = wn * 64 + ni * 8 + tg * 2;
                float v0 = acc[mi][ni][h * 2 + 0];
                float v1 = acc[mi][ni][h * 2 + 1];
                if (ATOMIC) {
                    atomicAdd(&C[(size_t)r * 128 + cc    ], v0 * rs);
                    atomicAdd(&C[(size_t)r * 128 + cc + 1], v1 * rs);
                } else {
                    if (bias) { v0 += bias[cc]; v1 += bias[cc + 1]; }
                    v0 *= rs; v1 *= rs;
                    C[(size_t)r * 128 + cc    ] = v0;
                    C[(size_t)r * 128 + cc + 1] = v1;
                }
            }
        }
    }
}

__global__ void zero_kernel(float* __restrict__ p, int n) {
    int i = blockIdx.x * blockDim.x + threadIdx.x;
    if (i < n) p[i] = 0.f;
}

__global__ void fusion_kernel(const float* __restrict__ fw,
                              const float* __restrict__ X0,
                              const float* __restrict__ X1,
                              const float* __restrict__ X2,
                              float* __restrict__ out, int n) {
    float f0 = fw[0], f1 = fw[1], f2 = fw[2];
    float mx = fmaxf(f0, fmaxf(f1, f2));
    float e0 = expf(f0 - mx), e1 = expf(f1 - mx), e2 = expf(f2 - mx);
    float inv = 1.f / (e0 + e1 + e2);
    float w0 = e0 * inv, w1 = e1 * inv, w2 = e2 * inv;
    int i = blockIdx.x * blockDim.x + threadIdx.x;
    if (i < n) out[i] = w0 * X0[i] + w1 * X1[i] + w2 * X2[i];
}

static inline int chunk_for(int K, int S) {
    int tiles = (K + BK - 1) / BK;
    int per = (tiles + S - 1) / S;
    return per * BK;
}

extern "C" void kernel_launch(void* const* d_in, const int* in_sizes, int n_in,
                              void* d_out, int out_size) {
    const float* emb = (const float*)d_in[0];
    const float* Wt  = (const float*)d_in[1];
    const float* bt  = (const float*)d_in[2];
    const float* W1  = (const float*)d_in[3];
    const float* b1  = (const float*)d_in[4];
    const float* W2  = (const float*)d_in[5];
    const float* b2  = (const float*)d_in[6];
    const float* fw  = (const float*)d_in[7];
    const float* H   = (const float*)d_in[8];
    const float* dv  = (const float*)d_in[9];
    const float* de  = (const float*)d_in[10];
    const int*   tid = (const int*)d_in[11];

    const int D = in_sizes[4];          // 128
    const int N = in_sizes[9];          // 20000
    const int E = in_sizes[10];         // 8000
    const int T = in_sizes[2] / D;      // 5

    float* buf = nullptr;
    cudaGetSymbolAddress((void**)&buf, g_buf);
    size_t nd = (size_t)N * D, ed = (size_t)E * D;
    float* X0 = buf;
    float* X1 = X0 + nd;
    float* X2 = X1 + nd;
    float* Y  = X2 + nd;
    float* Mm = Y + nd;

    dim3 blk(256);
    int mt_n = (N + BM - 1) / BM;       // 157
    int mt_e = (E + BM - 1) / BM;       // 63
    const int S1 = 12;                  // split-K for H^T @ Y (K = N)
    const int S2 = 6;                   // split-K for H @ m   (K = E)
    int ch1 = chunk_for(N, S1);
    int ch2 = chunk_for(E, S2);
    int zthreads = 256;

    // ---- X0: per-type projection with fused type-select ----
    gemm128<false, false><<<dim3(mt_n, 1, T), blk>>>(
        emb, Wt, X0, N, D, D, bt, nullptr, tid, D * D, D, D);

    // ======== hgc layer 1 ========
    gemm128<false, false><<<dim3(mt_n, 1, 1), blk>>>(
        X0, W1, Y, N, D, D, b1, dv, nullptr, 0, 0, D);
    zero_kernel<<<(int)((ed + zthreads - 1) / zthreads), zthreads>>>(Mm, (int)ed);
    gemm128<true, true><<<dim3(mt_e, S1, 1), blk>>>(
        H, Y, Mm, E, N, E, nullptr, de, nullptr, 0, 0, ch1);
    zero_kernel<<<(int)((nd + zthreads - 1) / zthreads), zthreads>>>(X1, (int)nd);
    gemm128<false, true><<<dim3(mt_n, S2, 1), blk>>>(
        H, Mm, X1, N, E, E, nullptr, dv, nullptr, 0, 0, ch2);

    // ======== hgc layer 2 ========
    gemm128<false, false><<<dim3(mt_n, 1, 1), blk>>>(
        X1, W2, Y, N, D, D, b2, dv, nullptr, 0, 0, D);
    zero_kernel<<<(int)((ed + zthreads - 1) / zthreads), zthreads>>>(Mm, (int)ed);
    gemm128<true, true><<<dim3(mt_e, S1, 1), blk>>>(
        H, Y, Mm, E, N, E, nullptr, de, nullptr, 0, 0, ch1);
    zero_kernel<<<(int)((nd + zthreads - 1) / zthreads), zthreads>>>(X2, (int)nd);
    gemm128<false, true><<<dim3(mt_n, S2, 1), blk>>>(
        H, Mm, X2, N, E, E, nullptr, dv, nullptr, 0, 0, ch2);

    // ---- fusion ----
    fusion_kernel<<<(int)((nd + zthreads - 1) / zthreads), zthreads>>>(
        fw, X0, X1, X2, (float*)d_out, (int)nd);
}

// round 5
// speedup vs baseline: 1.5696x; 1.2884x over previous
#include <cuda_runtime.h>
#include <cuda_bf16.h>
#include <math.h>

// ----------------------------------------------------------------------------
// HyperGraphModel on GB300: tf32 mma.sync GEMMs with 3-stage cp.async pipeline.
// CTA tile 128x128x32, 8 warps, warp tile 32x64, m16n8k8 tf32, fp32 accum.
// SMEM holds raw fp32 (direct LDGSTS); fragments are rounded to tf32 with
// cvt.rna right before the MMA (round-to-nearest is required: HW truncation
// has coherent bias that blows up over K=20000 of all-positive H).
// ----------------------------------------------------------------------------

#define BM 128
#define BN 128
#define BK 32
#define STAGES 3

// scratch: X0, X1, X2, Y (each N*D) + m (E*D)
__device__ float g_buf[11264000];

__device__ __forceinline__ unsigned f2tf32(unsigned x) {
    unsigned r;
    asm("cvt.rna.tf32.f32 %0, %1;" : "=r"(r) : "r"(x));
    return r;
}

__device__ __forceinline__ void mma_tf32(float* c, const unsigned* a, const unsigned* b) {
    asm volatile(
        "mma.sync.aligned.m16n8k8.row.col.f32.tf32.tf32.f32 "
        "{%0,%1,%2,%3}, {%4,%5,%6,%7}, {%8,%9}, {%0,%1,%2,%3};\n"
        : "+f"(c[0]), "+f"(c[1]), "+f"(c[2]), "+f"(c[3])
        : "r"(a[0]), "r"(a[1]), "r"(a[2]), "r"(a[3]),
          "r"(b[0]), "r"(b[1]));
}

__device__ __forceinline__ void cpa16(unsigned* dst, const float* src, bool pred) {
    unsigned daddr = (unsigned)__cvta_generic_to_shared(dst);
    int sz = pred ? 16 : 0;
    asm volatile("cp.async.cg.shared.global [%0], [%1], 16, %2;\n"
                 :: "r"(daddr), "l"(src), "r"(sz));
}
__device__ __forceinline__ void cpa_commit() {
    asm volatile("cp.async.commit_group;\n");
}

// C[M,128] = op(A)[M,K] * B[K,128]
//   TRANS_A=false: A row-major [M,K]   (lda = K)
//   TRANS_A=true : A stored [K,M], element (m,k) = A[k*lda + m]  (lda = row stride)
// Requires: K-chunk multiple of BK; M % 4 == 0.
// ATOMIC=true : atomicAdd rowscale[m]*acc into pre-zeroed C (split-K)
// ATOMIC=false: C[m,n] = rowscale[m]*(acc + bias[n]); optional rowsel gating.
// blockIdx.z offsets B by ldbz and bias by biasz (per-type projections).
template <bool TRANS_A, bool ATOMIC>
__global__ void __launch_bounds__(256, 2)
gemm128p(const float* __restrict__ A, const float* __restrict__ B,
         float* __restrict__ C, int M, int K, int lda,
         const float* __restrict__ bias, const float* __restrict__ rowscale,
         const int* __restrict__ rowsel,
         int ldbz, int biasz, int kChunk)
{
    constexpr int APITCH = TRANS_A ? (BM + 4) : (BK + 4);
    constexpr int ASZ = TRANS_A ? BK * (BM + 4) : BM * (BK + 4);
    constexpr int BPITCH = BN + 4;
    constexpr int BSZ = BK * BPITCH;
    extern __shared__ unsigned sm[];

    const int m0 = blockIdx.x * BM;
    const int kBegin = blockIdx.y * kChunk;
    const int kEnd = min(K, kBegin + kChunk);
    if (kBegin >= K) return;
    const int kTiles = (kEnd - kBegin) / BK;

    const int zt = blockIdx.z;
    B += (size_t)zt * ldbz;
    if (bias) bias += (size_t)zt * biasz;

    const int tidx = threadIdx.x;
    const int lane = tidx & 31;
    const int g  = lane >> 2;         // 0..7
    const int tg = lane & 3;          // 0..3
    const int wm = (tidx >> 5) & 3;   // warp row (32 M-rows)
    const int wn = (tidx >> 7);       // warp col (64 N-cols)

    float acc[2][8][4];
#pragma unroll
    for (int mi = 0; mi < 2; mi++)
#pragma unroll
        for (int ni = 0; ni < 8; ni++)
#pragma unroll
            for (int j = 0; j < 4; j++) acc[mi][ni][j] = 0.f;

    // ---- tile loader: issues cp.async for k-tile t into given stage ----
    auto load_tile = [&](int t, int stage) {
        int kt = kBegin + t * BK;
        unsigned* as = sm + stage * (ASZ + BSZ);
        unsigned* bs = as + ASZ;
        if (!TRANS_A) {
#pragma unroll
            for (int i = 0; i < 4; i++) {
                int idx = tidx + i * 256;
                int m  = idx >> 3;               // 0..127
                int k4 = (idx & 7) << 2;         // 0..28
                bool p = (m0 + m < M);
                const float* src = p ? &A[(size_t)(m0 + m) * lda + kt + k4] : A;
                cpa16(&as[m * APITCH + k4], src, p);
            }
        } else {
#pragma unroll
            for (int i = 0; i < 4; i++) {
                int idx = tidx + i * 256;
                int k  = idx >> 5;               // 0..31
                int m4 = (idx & 31) << 2;        // lane*4
                int gm = m0 + m4;
                bool p = (gm + 3 < M);           // M%4==0 -> no straddle
                const float* src = p ? &A[(size_t)(kt + k) * lda + gm] : A;
                cpa16(&as[k * APITCH + m4], src, p);
            }
        }
#pragma unroll
        for (int i = 0; i < 4; i++) {
            int idx = tidx + i * 256;
            int k  = idx >> 5;
            int n4 = (idx & 31) << 2;
            cpa16(&bs[k * BPITCH + n4], &B[(size_t)(kt + k) * 128 + n4], true);
        }
        cpa_commit();
    };

    // ---- prologue: prefetch STAGES-1 tiles ----
    int pre = kTiles < (STAGES - 1) ? kTiles : (STAGES - 1);
    for (int t = 0; t < pre; t++) load_tile(t, t % STAGES);
    for (int t = pre; t < STAGES - 1; t++) cpa_commit();  // keep group count aligned

    // ---- main loop ----
    for (int t = 0; t < kTiles; t++) {
        if (t + STAGES - 1 < kTiles) load_tile(t + STAGES - 1, (t + STAGES - 1) % STAGES);
        else cpa_commit();
        asm volatile("cp.async.wait_group %0;\n" :: "n"(STAGES - 1));
        __syncthreads();

        const unsigned* as = sm + (t % STAGES) * (ASZ + BSZ);
        const unsigned* bs = as + ASZ;

#pragma unroll
        for (int kk = 0; kk < BK; kk += 8) {
            unsigned af[2][4];
#pragma unroll
            for (int mi = 0; mi < 2; mi++) {
                int bm = wm * 32 + mi * 16;
                if (!TRANS_A) {
                    af[mi][0] = f2tf32(as[(bm + g    ) * APITCH + kk + tg    ]);
                    af[mi][1] = f2tf32(as[(bm + g + 8) * APITCH + kk + tg    ]);
                    af[mi][2] = f2tf32(as[(bm + g    ) * APITCH + kk + tg + 4]);
                    af[mi][3] = f2tf32(as[(bm + g + 8) * APITCH + kk + tg + 4]);
                } else {
                    af[mi][0] = f2tf32(as[(kk + tg    ) * APITCH + bm + g    ]);
                    af[mi][1] = f2tf32(as[(kk + tg    ) * APITCH + bm + g + 8]);
                    af[mi][2] = f2tf32(as[(kk + tg + 4) * APITCH + bm + g    ]);
                    af[mi][3] = f2tf32(as[(kk + tg + 4) * APITCH + bm + g + 8]);
                }
            }
            unsigned bf[8][2];
#pragma unroll
            for (int ni = 0; ni < 8; ni++) {
                int bn = wn * 64 + ni * 8;
                bf[ni][0] = f2tf32(bs[(kk + tg    ) * BPITCH + bn + g]);
                bf[ni][1] = f2tf32(bs[(kk + tg + 4) * BPITCH + bn + g]);
            }
#pragma unroll
            for (int mi = 0; mi < 2; mi++)
#pragma unroll
                for (int ni = 0; ni < 8; ni++)
                    mma_tf32(acc[mi][ni], af[mi], bf[ni]);
        }
        __syncthreads();
    }

    // ---- epilogue ----
#pragma unroll
    for (int mi = 0; mi < 2; mi++) {
#pragma unroll
        for (int h = 0; h < 2; h++) {
            int r = m0 + wm * 32 + mi * 16 + g + h * 8;
            if (r >= M) continue;
            if (!ATOMIC && rowsel && rowsel[r] != zt) continue;
            float rs = rowscale ? rowscale[r] : 1.f;
#pragma unroll
            for (int ni = 0; ni < 8; ni++) {
                int cc = wn * 64 + ni * 8 + tg * 2;
                float v0 = acc[mi][ni][h * 2 + 0];
                float v1 = acc[mi][ni][h * 2 + 1];
                if (ATOMIC) {
                    atomicAdd(&C[(size_t)r * 128 + cc    ], v0 * rs);
                    atomicAdd(&C[(size_t)r * 128 + cc + 1], v1 * rs);
                } else {
                    if (bias) { v0 += bias[cc]; v1 += bias[cc + 1]; }
                    v0 *= rs; v1 *= rs;
                    C[(size_t)r * 128 + cc    ] = v0;
                    C[(size_t)r * 128 + cc + 1] = v1;
                }
            }
        }
    }
}

__global__ void zero_kernel(float* __restrict__ p, int n) {
    int i = blockIdx.x * blockDim.x + threadIdx.x;
    if (i < n) p[i] = 0.f;
}

__global__ void fusion_kernel(const float* __restrict__ fw,
                              const float* __restrict__ X0,
                              const float* __restrict__ X1,
                              const float* __restrict__ X2,
                              float* __restrict__ out, int n) {
    float f0 = fw[0], f1 = fw[1], f2 = fw[2];
    float mx = fmaxf(f0, fmaxf(f1, f2));
    float e0 = expf(f0 - mx), e1 = expf(f1 - mx), e2 = expf(f2 - mx);
    float inv = 1.f / (e0 + e1 + e2);
    float w0 = e0 * inv, w1 = e1 * inv, w2 = e2 * inv;
    int i = blockIdx.x * blockDim.x + threadIdx.x;
    if (i < n) out[i] = w0 * X0[i] + w1 * X1[i] + w2 * X2[i];
}

static inline int chunk_for(int K, int S) {
    int tiles = (K + BK - 1) / BK;
    int per = (tiles + S - 1) / S;
    return per * BK;
}

extern "C" void kernel_launch(void* const* d_in, const int* in_sizes, int n_in,
                              void* d_out, int out_size) {
    const float* emb = (const float*)d_in[0];
    const float* Wt  = (const float*)d_in[1];
    const float* bt  = (const float*)d_in[2];
    const float* W1  = (const float*)d_in[3];
    const float* b1  = (const float*)d_in[4];
    const float* W2  = (const float*)d_in[5];
    const float* b2  = (const float*)d_in[6];
    const float* fw  = (const float*)d_in[7];
    const float* H   = (const float*)d_in[8];
    const float* dv  = (const float*)d_in[9];
    const float* de  = (const float*)d_in[10];
    const int*   tid = (const int*)d_in[11];

    const int D = in_sizes[4];          // 128
    const int N = in_sizes[9];          // 20000
    const int E = in_sizes[10];         // 8000
    const int T = in_sizes[2] / D;      // 5

    float* buf = nullptr;
    cudaGetSymbolAddress((void**)&buf, g_buf);
    size_t nd = (size_t)N * D, ed = (size_t)E * D;
    float* X0 = buf;
    float* X1 = X0 + nd;
    float* X2 = X1 + nd;
    float* Y  = X2 + nd;
    float* Mm = Y + nd;

    // dynamic smem: STAGES * (A tile + B tile)
    const int smemT = STAGES * (BK * (BM + 4) + BK * (BN + 4)) * 4;   // trans
    const int smemN = STAGES * (BM * (BK + 4) + BK * (BN + 4)) * 4;   // non-trans
    static bool attr_done = false;
    if (!attr_done) {
        cudaFuncSetAttribute(gemm128p<false, false>,
                             cudaFuncAttributeMaxDynamicSharedMemorySize, smemN);
        cudaFuncSetAttribute(gemm128p<false, true>,
                             cudaFuncAttributeMaxDynamicSharedMemorySize, smemN);
        cudaFuncSetAttribute(gemm128p<true, true>,
                             cudaFuncAttributeMaxDynamicSharedMemorySize, smemT);
        attr_done = true;
    }

    dim3 blk(256);
    int mt_n = (N + BM - 1) / BM;       // 157
    int mt_e = (E + BM - 1) / BM;       // 63
    const int S1 = 9;                   // split-K for H^T @ Y (K = N): 567 CTAs ~ 2 waves
    const int S2 = 4;                   // split-K for H @ m   (K = E): 628 CTAs ~ 2 waves
    int ch1 = chunk_for(N, S1);
    int ch2 = chunk_for(E, S2);
    int zthreads = 256;

    // ---- X0: per-type projection with fused type-select ----
    gemm128p<false, false><<<dim3(mt_n, 1, T), blk, smemN>>>(
        emb, Wt, X0, N, D, D, bt, nullptr, tid, D * D, D, D);

    // ======== hgc layer 1 ========
    gemm128p<false, false><<<dim3(mt_n, 1, 1), blk, smemN>>>(
        X0, W1, Y, N, D, D, b1, dv, nullptr, 0, 0, D);
    zero_kernel<<<(int)((ed + zthreads - 1) / zthreads), zthreads>>>(Mm, (int)ed);
    gemm128p<true, true><<<dim3(mt_e, S1, 1), blk, smemT>>>(
        H, Y, Mm, E, N, E, nullptr, de, nullptr, 0, 0, ch1);
    zero_kernel<<<(int)((nd + zthreads - 1) / zthreads), zthreads>>>(X1, (int)nd);
    gemm128p<false, true><<<dim3(mt_n, S2, 1), blk, smemN>>>(
        H, Mm, X1, N, E, E, nullptr, dv, nullptr, 0, 0, ch2);

    // ======== hgc layer 2 ========
    gemm128p<false, false><<<dim3(mt_n, 1, 1), blk, smemN>>>(
        X1, W2, Y, N, D, D, b2, dv, nullptr, 0, 0, D);
    zero_kernel<<<(int)((ed + zthreads - 1) / zthreads), zthreads>>>(Mm, (int)ed);
    gemm128p<true, true><<<dim3(mt_e, S1, 1), blk, smemT>>>(
        H, Y, Mm, E, N, E, nullptr, de, nullptr, 0, 0, ch1);
    zero_kernel<<<(int)((nd + zthreads - 1) / zthreads), zthreads>>>(X2, (int)nd);
    gemm128p<false, true><<<dim3(mt_n, S2, 1), blk, smemN>>>(
        H, Mm, X2, N, E, E, nullptr, dv, nullptr, 0, 0, ch2);

    // ---- fusion ----
    fusion_kernel<<<(int)((nd + zthreads - 1) / zthreads), zthreads>>>(
        fw, X0, X1, X2, (float*)d_out, (int)nd);
}

// round 6
// speedup vs baseline: 1.6979x; 1.0818x over previous
#include <cuda_runtime.h>
#include <cuda_bf16.h>
#include <math.h>

// ----------------------------------------------------------------------------
// HyperGraphModel on GB300: tf32 mma.sync GEMMs, 3-stage cp.async pipeline.
// CTA tile 256x128x32, 8 warps, warp tile 64x64, m16n8k8 tf32, fp32 accum.
// B operands are pre-rounded to tf32 (producer epilogue / tiny passes), so only
// A-side fragments need cvt.rna in the hot loop.
// ----------------------------------------------------------------------------

#define BM 256
#define BN 128
#define BK 32
#define STAGES 3

// scratch: X0,X1,X2,Y (each N*D) + Mm (E*D) + Wtr + W1r + W2r
__device__ float g_buf[11400000];

__device__ __forceinline__ unsigned f2tf32(unsigned x) {
    unsigned r;
    asm("cvt.rna.tf32.f32 %0, %1;" : "=r"(r) : "r"(x));
    return r;
}
__device__ __forceinline__ float roundtf(float x) {
    return __uint_as_float(f2tf32(__float_as_uint(x)));
}

__device__ __forceinline__ void mma_tf32(float* c, const unsigned* a, const unsigned* b) {
    asm volatile(
        "mma.sync.aligned.m16n8k8.row.col.f32.tf32.tf32.f32 "
        "{%0,%1,%2,%3}, {%4,%5,%6,%7}, {%8,%9}, {%0,%1,%2,%3};\n"
        : "+f"(c[0]), "+f"(c[1]), "+f"(c[2]), "+f"(c[3])
        : "r"(a[0]), "r"(a[1]), "r"(a[2]), "r"(a[3]),
          "r"(b[0]), "r"(b[1]));
}

__device__ __forceinline__ void cpa16(unsigned* dst, const float* src, bool pred) {
    unsigned daddr = (unsigned)__cvta_generic_to_shared(dst);
    int sz = pred ? 16 : 0;
    asm volatile("cp.async.cg.shared.global [%0], [%1], 16, %2;\n"
                 :: "r"(daddr), "l"(src), "r"(sz));
}
__device__ __forceinline__ void cpa_commit() {
    asm volatile("cp.async.commit_group;\n");
}

// C[M,128] = op(A)[M,K] * B[K,128]   (B must be pre-rounded to tf32)
//   TRANS_A=false: A row-major [M,K] (lda=K);  TRANS_A=true: A[k*lda+m]
// Requires: K-chunk multiple of BK; M % 4 == 0.
// ATOMIC: atomicAdd rowscale[m]*acc into pre-zeroed C (split-K).
// else:   C[m,n] = rowscale[m]*(acc+bias[n]) (tf32-rounded if ROUND_C);
//         optional rowsel gating; blockIdx.z offsets B by ldbz, bias by biasz.
template <bool TRANS_A, bool ATOMIC, bool ROUND_C>
__global__ void __launch_bounds__(256, 1)
gemm256(const float* __restrict__ A, const float* __restrict__ B,
        float* __restrict__ C, int M, int K, int lda,
        const float* __restrict__ bias, const float* __restrict__ rowscale,
        const int* __restrict__ rowsel,
        int ldbz, int biasz, int kChunk)
{
    constexpr int APITCH = TRANS_A ? (BM + 8) : (BK + 4);
    constexpr int ASZ = TRANS_A ? BK * (BM + 8) : BM * (BK + 4);
    constexpr int BPITCH = BN + 8;
    constexpr int BSZ = BK * BPITCH;
    extern __shared__ unsigned sm[];

    const int m0 = blockIdx.x * BM;
    const int kBegin = blockIdx.y * kChunk;
    const int kEnd = min(K, kBegin + kChunk);
    if (kBegin >= K) return;
    const int kTiles = (kEnd - kBegin) / BK;

    const int zt = blockIdx.z;
    B += (size_t)zt * ldbz;
    if (bias) bias += (size_t)zt * biasz;

    const int tidx = threadIdx.x;
    const int lane = tidx & 31;
    const int g  = lane >> 2;         // 0..7
    const int tg = lane & 3;          // 0..3
    const int wm = (tidx >> 5) & 3;   // warp row (64 M-rows)
    const int wn = (tidx >> 7);       // warp col (64 N-cols)

    float acc[4][8][4];
#pragma unroll
    for (int mi = 0; mi < 4; mi++)
#pragma unroll
        for (int ni = 0; ni < 8; ni++)
#pragma unroll
            for (int j = 0; j < 4; j++) acc[mi][ni][j] = 0.f;

    // ---- tile loader: cp.async k-tile t into stage ----
    auto load_tile = [&](int t, int stage) {
        int kt = kBegin + t * BK;
        unsigned* as = sm + stage * (ASZ + BSZ);
        unsigned* bs = as + ASZ;
        if (!TRANS_A) {
#pragma unroll
            for (int i = 0; i < 8; i++) {
                int idx = tidx + i * 256;
                int m  = idx >> 3;               // 0..255
                int k4 = (idx & 7) << 2;         // 0..28
                bool p = (m0 + m < M);
                const float* src = p ? &A[(size_t)(m0 + m) * lda + kt + k4] : A;
                cpa16(&as[m * APITCH + k4], src, p);
            }
        } else {
#pragma unroll
            for (int i = 0; i < 8; i++) {
                int idx = tidx + i * 256;
                int k  = idx >> 6;               // 0..31
                int m4 = (idx & 63) << 2;        // 0..252
                int gm = m0 + m4;
                bool p = (gm + 3 < M);           // M%4==0 -> no straddle
                const float* src = p ? &A[(size_t)(kt + k) * lda + gm] : A;
                cpa16(&as[k * APITCH + m4], src, p);
            }
        }
#pragma unroll
        for (int i = 0; i < 4; i++) {
            int idx = tidx + i * 256;
            int k  = idx >> 5;
            int n4 = (idx & 31) << 2;
            cpa16(&bs[k * BPITCH + n4], &B[(size_t)(kt + k) * 128 + n4], true);
        }
        cpa_commit();
    };

    // ---- prologue ----
    int pre = kTiles < (STAGES - 1) ? kTiles : (STAGES - 1);
    for (int t = 0; t < pre; t++) load_tile(t, t % STAGES);
    for (int t = pre; t < STAGES - 1; t++) cpa_commit();

    // ---- main loop ----
    for (int t = 0; t < kTiles; t++) {
        if (t + STAGES - 1 < kTiles) load_tile(t + STAGES - 1, (t + STAGES - 1) % STAGES);
        else cpa_commit();
        asm volatile("cp.async.wait_group %0;\n" :: "n"(STAGES - 1));
        __syncthreads();

        const unsigned* as = sm + (t % STAGES) * (ASZ + BSZ);
        const unsigned* bs = as + ASZ;

#pragma unroll
        for (int kk = 0; kk < BK; kk += 8) {
            unsigned af[4][4];
#pragma unroll
            for (int mi = 0; mi < 4; mi++) {
                int bm = wm * 64 + mi * 16;
                if (!TRANS_A) {
                    af[mi][0] = f2tf32(as[(bm + g    ) * APITCH + kk + tg    ]);
                    af[mi][1] = f2tf32(as[(bm + g + 8) * APITCH + kk + tg    ]);
                    af[mi][2] = f2tf32(as[(bm + g    ) * APITCH + kk + tg + 4]);
                    af[mi][3] = f2tf32(as[(bm + g + 8) * APITCH + kk + tg + 4]);
                } else {
                    af[mi][0] = f2tf32(as[(kk + tg    ) * APITCH + bm + g    ]);
                    af[mi][1] = f2tf32(as[(kk + tg    ) * APITCH + bm + g + 8]);
                    af[mi][2] = f2tf32(as[(kk + tg + 4) * APITCH + bm + g    ]);
                    af[mi][3] = f2tf32(as[(kk + tg + 4) * APITCH + bm + g + 8]);
                }
            }
            unsigned bf[8][2];
#pragma unroll
            for (int ni = 0; ni < 8; ni++) {
                int bn = wn * 64 + ni * 8;
                bf[ni][0] = bs[(kk + tg    ) * BPITCH + bn + g];
                bf[ni][1] = bs[(kk + tg + 4) * BPITCH + bn + g];
            }
#pragma unroll
            for (int mi = 0; mi < 4; mi++)
#pragma unroll
                for (int ni = 0; ni < 8; ni++)
                    mma_tf32(acc[mi][ni], af[mi], bf[ni]);
        }
        __syncthreads();
    }

    // ---- epilogue ----
#pragma unroll
    for (int mi = 0; mi < 4; mi++) {
#pragma unroll
        for (int h = 0; h < 2; h++) {
            int r = m0 + wm * 64 + mi * 16 + g + h * 8;
            if (r >= M) continue;
            if (!ATOMIC && rowsel && rowsel[r] != zt) continue;
            float rs = rowscale ? rowscale[r] : 1.f;
#pragma unroll
            for (int ni = 0; ni < 8; ni++) {
                int cc = wn * 64 + ni * 8 + tg * 2;
                float v0 = acc[mi][ni][h * 2 + 0];
                float v1 = acc[mi][ni][h * 2 + 1];
                if (ATOMIC) {
                    atomicAdd(&C[(size_t)r * 128 + cc    ], v0 * rs);
                    atomicAdd(&C[(size_t)r * 128 + cc + 1], v1 * rs);
                } else {
                    if (bias) { v0 += bias[cc]; v1 += bias[cc + 1]; }
                    v0 *= rs; v1 *= rs;
                    if (ROUND_C) { v0 = roundtf(v0); v1 = roundtf(v1); }
                    C[(size_t)r * 128 + cc    ] = v0;
                    C[(size_t)r * 128 + cc + 1] = v1;
                }
            }
        }
    }
}

__global__ void zero_kernel(float* __restrict__ p, int n) {
    int i = blockIdx.x * blockDim.x + threadIdx.x;
    if (i < n) p[i] = 0.f;
}

// dst = round_to_tf32(src), 4-wide; dst may alias src. n4 = n/4.
__global__ void round_tf32_kernel(float* __restrict__ dst, const float* __restrict__ src, int n4) {
    int i = blockIdx.x * blockDim.x + threadIdx.x;
    if (i < n4) {
        float4 v = ((const float4*)src)[i];
        v.x = roundtf(v.x); v.y = roundtf(v.y);
        v.z = roundtf(v.z); v.w = roundtf(v.w);
        ((float4*)dst)[i] = v;
    }
}

__global__ void fusion_kernel(const float* __restrict__ fw,
                              const float* __restrict__ X0,
                              const float* __restrict__ X1,
                              const float* __restrict__ X2,
                              float* __restrict__ out, int n) {
    float f0 = fw[0], f1 = fw[1], f2 = fw[2];
    float mx = fmaxf(f0, fmaxf(f1, f2));
    float e0 = expf(f0 - mx), e1 = expf(f1 - mx), e2 = expf(f2 - mx);
    float inv = 1.f / (e0 + e1 + e2);
    float w0 = e0 * inv, w1 = e1 * inv, w2 = e2 * inv;
    int i = blockIdx.x * blockDim.x + threadIdx.x;
    if (i < n) out[i] = w0 * X0[i] + w1 * X1[i] + w2 * X2[i];
}

static inline int chunk_for(int K, int S) {
    int tiles = (K + BK - 1) / BK;
    int per = (tiles + S - 1) / S;
    return per * BK;
}

extern "C" void kernel_launch(void* const* d_in, const int* in_sizes, int n_in,
                              void* d_out, int out_size) {
    const float* emb = (const float*)d_in[0];
    const float* Wt  = (const float*)d_in[1];
    const float* bt  = (const float*)d_in[2];
    const float* W1  = (const float*)d_in[3];
    const float* b1  = (const float*)d_in[4];
    const float* W2  = (const float*)d_in[5];
    const float* b2  = (const float*)d_in[6];
    const float* fw  = (const float*)d_in[7];
    const float* H   = (const float*)d_in[8];
    const float* dv  = (const float*)d_in[9];
    const float* de  = (const float*)d_in[10];
    const int*   tid = (const int*)d_in[11];

    const int D = in_sizes[4];          // 128
    const int N = in_sizes[9];          // 20000
    const int E = in_sizes[10];         // 8000
    const int T = in_sizes[2] / D;      // 5

    float* buf = nullptr;
    cudaGetSymbolAddress((void**)&buf, g_buf);
    size_t nd = (size_t)N * D, ed = (size_t)E * D;
    float* X0  = buf;
    float* X1  = X0 + nd;
    float* X2  = X1 + nd;
    float* Y   = X2 + nd;
    float* Mm  = Y + nd;
    float* Wtr = Mm + ed;
    float* W1r = Wtr + (size_t)T * D * D;
    float* W2r = W1r + (size_t)D * D;

    // dynamic smem
    const int smemT = STAGES * (BK * (BM + 8) + BK * (BN + 8)) * 4;
    const int smemN = STAGES * (BM * (BK + 4) + BK * (BN + 8)) * 4;
    static bool attr_done = false;
    if (!attr_done) {
        cudaFuncSetAttribute(gemm256<false, false, false>,
                             cudaFuncAttributeMaxDynamicSharedMemorySize, smemN);
        cudaFuncSetAttribute(gemm256<false, false, true>,
                             cudaFuncAttributeMaxDynamicSharedMemorySize, smemN);
        cudaFuncSetAttribute(gemm256<false, true, false>,
                             cudaFuncAttributeMaxDynamicSharedMemorySize, smemN);
        cudaFuncSetAttribute(gemm256<true, true, false>,
                             cudaFuncAttributeMaxDynamicSharedMemorySize, smemT);
        attr_done = true;
    }

    dim3 blk(256);
    int mt_n = (N + BM - 1) / BM;       // 79
    int mt_e = (E + BM - 1) / BM;       // 32
    const int S1 = 9;                   // split-K for H^T @ Y: 288 CTAs ~ 2 waves
    const int S2 = 4;                   // split-K for H @ m:   316 CTAs ~ 2 waves
    int ch1 = chunk_for(N, S1);
    int ch2 = chunk_for(E, S2);
    int zt_ = 256;

    // ---- pre-round weights (B operands) to tf32 ----
    int wt_n4 = T * D * D / 4, w_n4 = D * D / 4;
    round_tf32_kernel<<<(wt_n4 + 255) / 256, 256>>>(Wtr, Wt, wt_n4);
    round_tf32_kernel<<<(w_n4 + 255) / 256, 256>>>(W1r, W1, w_n4);
    round_tf32_kernel<<<(w_n4 + 255) / 256, 256>>>(W2r, W2, w_n4);

    // ---- X0: per-type projection with fused type-select (plain output) ----
    gemm256<false, false, false><<<dim3(mt_n, 1, T), blk, smemN>>>(
        emb, Wtr, X0, N, D, D, bt, nullptr, tid, D * D, D, D);

    // ======== hgc layer 1 ========
    // Y = round(dv * (X0 @ W1 + b1))
    gemm256<false, false, true><<<dim3(mt_n, 1, 1), blk, smemN>>>(
        X0, W1r, Y, N, D, D, b1, dv, nullptr, 0, 0, D);
    // Mm = de * (H^T @ Y), then round
    zero_kernel<<<(int)((ed + zt_ - 1) / zt_), zt_>>>(Mm, (int)ed);
    gemm256<true, true, false><<<dim3(mt_e, S1, 1), blk, smemT>>>(
        H, Y, Mm, E, N, E, nullptr, de, nullptr, 0, 0, ch1);
    round_tf32_kernel<<<(int)((ed / 4 + 255) / 256), 256>>>(Mm, Mm, (int)(ed / 4));
    // X1 = dv * (H @ Mm)   (plain: feeds fusion; layer-2 GEMM cvts A-side)
    zero_kernel<<<(int)((nd + zt_ - 1) / zt_), zt_>>>(X1, (int)nd);
    gemm256<false, true, false><<<dim3(mt_n, S2, 1), blk, smemN>>>(
        H, Mm, X1, N, E, E, nullptr, dv, nullptr, 0, 0, ch2);

    // ======== hgc layer 2 ========
    gemm256<false, false, true><<<dim3(mt_n, 1, 1), blk, smemN>>>(
        X1, W2r, Y, N, D, D, b2, dv, nullptr, 0, 0, D);
    zero_kernel<<<(int)((ed + zt_ - 1) / zt_), zt_>>>(Mm, (int)ed);
    gemm256<true, true, false><<<dim3(mt_e, S1, 1), blk, smemT>>>(
        H, Y, Mm, E, N, E, nullptr, de, nullptr, 0, 0, ch1);
    round_tf32_kernel<<<(int)((ed / 4 + 255) / 256), 256>>>(Mm, Mm, (int)(ed / 4));
    zero_kernel<<<(int)((nd + zt_ - 1) / zt_), zt_>>>(X2, (int)nd);
    gemm256<false, true, false><<<dim3(mt_n, S2, 1), blk, smemN>>>(
        H, Mm, X2, N, E, E, nullptr, dv, nullptr, 0, 0, ch2);

    // ---- fusion ----
    fusion_kernel<<<(int)((nd + zt_ - 1) / zt_), zt_>>>(
        fw, X0, X1, X2, (float*)d_out, (int)nd);
}

// round 9
// speedup vs baseline: 2.2301x; 1.3134x over previous
#include <cuda_runtime.h>
#include <cuda_fp16.h>
#include <math.h>

// ----------------------------------------------------------------------------
// HyperGraphModel on GB300.
//  - 4 big H-GEMMs in fp16 (HMMA m16n8k16, fp32 accum, ldmatrix fragments,
//    4-stage cp.async pipeline). H pre-converted once to fp16 (exact-range).
//  - fp16 intermediates use DYNAMIC power-of-2 scaling: absmax reduction on
//    the fp32 tensor -> s = 2^-k with absmax*s <= 16384; consuming GEMM
//    epilogue multiplies by 2^k (read from device). Exponent-only => exact.
//    (Static scales failed twice: |Y2| ~ 3e6, |Mm2| ~ 1e10 — mean-dominated
//    growth through all-positive H.)
//  - small D x D GEMMs stay tf32 mma.sync (pre-rounded B weights).
// ----------------------------------------------------------------------------

#define BM 256
#define BN 128
#define BK 32
#define STAGES 3          // tf32 kernel
#define HST 4             // fp16 kernel stages

// fp32 scratch: X0,X1,X2,Yf (4*N*D) + Mm (E*D) + Wtr + W1r + W2r
__device__ float g_buf[11400000];
// fp16 scratch: Hh (N*E) + Yh (N*D) + Mmh (E*D)
__device__ __align__(256) __half g_hbuf[163600000];
// scale slots: [0]=amaxY bits, [1]=sY, [2]=uY, [3]=amaxM, [4]=sM, [5]=uM
__device__ unsigned g_sc[8];

// ---------------- common helpers ----------------
__device__ __forceinline__ unsigned f2tf32(unsigned x) {
    unsigned r;
    asm("cvt.rna.tf32.f32 %0, %1;" : "=r"(r) : "r"(x));
    return r;
}
__device__ __forceinline__ float roundtf(float x) {
    return __uint_as_float(f2tf32(__float_as_uint(x)));
}
__device__ __forceinline__ void mma_tf32(float* c, const unsigned* a, const unsigned* b) {
    asm volatile(
        "mma.sync.aligned.m16n8k8.row.col.f32.tf32.tf32.f32 "
        "{%0,%1,%2,%3}, {%4,%5,%6,%7}, {%8,%9}, {%0,%1,%2,%3};\n"
        : "+f"(c[0]), "+f"(c[1]), "+f"(c[2]), "+f"(c[3])
        : "r"(a[0]), "r"(a[1]), "r"(a[2]), "r"(a[3]), "r"(b[0]), "r"(b[1]));
}
__device__ __forceinline__ void mma_f16(float* c, const unsigned* a, const unsigned* b) {
    asm volatile(
        "mma.sync.aligned.m16n8k16.row.col.f32.f16.f16.f32 "
        "{%0,%1,%2,%3}, {%4,%5,%6,%7}, {%8,%9}, {%0,%1,%2,%3};\n"
        : "+f"(c[0]), "+f"(c[1]), "+f"(c[2]), "+f"(c[3])
        : "r"(a[0]), "r"(a[1]), "r"(a[2]), "r"(a[3]), "r"(b[0]), "r"(b[1]));
}
__device__ __forceinline__ void cpa16(void* dst, const void* src, bool pred) {
    unsigned daddr = (unsigned)__cvta_generic_to_shared(dst);
    int sz = pred ? 16 : 0;
    asm volatile("cp.async.cg.shared.global [%0], [%1], 16, %2;\n"
                 :: "r"(daddr), "l"(src), "r"(sz));
}
__device__ __forceinline__ void cpa_commit() {
    asm volatile("cp.async.commit_group;\n");
}
__device__ __forceinline__ void ldsm_x4(unsigned* r, unsigned a) {
    asm volatile("ldmatrix.sync.aligned.m8n8.x4.shared.b16 {%0,%1,%2,%3}, [%4];"
                 : "=r"(r[0]), "=r"(r[1]), "=r"(r[2]), "=r"(r[3]) : "r"(a));
}
__device__ __forceinline__ void ldsm_x4t(unsigned* r, unsigned a) {
    asm volatile("ldmatrix.sync.aligned.m8n8.x4.trans.shared.b16 {%0,%1,%2,%3}, [%4];"
                 : "=r"(r[0]), "=r"(r[1]), "=r"(r[2]), "=r"(r[3]) : "r"(a));
}

// ============================================================================
// fp16 GEMM: C[M,128] += (*undoPtr) * rowscale[m] * (op(A)[M,K] @ B[K,128]),
// atomic split-K into pre-zeroed fp32 C.
//  TRANS_A=false: A row-major [M,K] fp16 (lda = K)
//  TRANS_A=true : A stored [K,M] fp16, element (m,k) = A[k*lda+m]
// Requires: kChunk % 32 == 0, K % 32 == 0, M % 8 == 0.
// ============================================================================
template <bool TRANS_A>
__global__ void __launch_bounds__(256, 1)
hgemm(const __half* __restrict__ A, const __half* __restrict__ B,
      float* __restrict__ C, int M, int K, int lda,
      const float* __restrict__ rowscale, const float* __restrict__ undoPtr,
      int kChunk)
{
    constexpr int APITCH = TRANS_A ? (BM + 8) : (BK + 8);     // halves
    constexpr int ASZ = TRANS_A ? BK * (BM + 8) : BM * (BK + 8);
    constexpr int BPITCH = BN + 8;
    constexpr int BSZ = BK * BPITCH;
    extern __shared__ char smraw[];
    __half* hsm = (__half*)smraw;

    const int m0 = blockIdx.x * BM;
    const int kBegin = blockIdx.y * kChunk;
    const int kEnd = min(K, kBegin + kChunk);
    if (kBegin >= K) return;
    const int kTiles = (kEnd - kBegin) / BK;

    const int tidx = threadIdx.x;
    const int lane = tidx & 31;
    const int g  = lane >> 2;
    const int tg = lane & 3;
    const int wm = (tidx >> 5) & 3;   // warp row (64 M)
    const int wn = (tidx >> 7);       // warp col (64 N)
    const int lt = lane >> 3;         // ldmatrix tile id 0..3
    const int lr = lane & 7;          // ldmatrix row in tile

    float acc[4][8][4];
#pragma unroll
    for (int mi = 0; mi < 4; mi++)
#pragma unroll
        for (int ni = 0; ni < 8; ni++)
#pragma unroll
            for (int j = 0; j < 4; j++) acc[mi][ni][j] = 0.f;

    auto load_tile = [&](int t, int stage) {
        int kt = kBegin + t * BK;
        __half* as = hsm + stage * (ASZ + BSZ);
        __half* bs = as + ASZ;
        if (!TRANS_A) {
#pragma unroll
            for (int i = 0; i < 4; i++) {
                int idx = tidx + i * 256;
                int m  = idx >> 2;               // 0..255
                int k8 = (idx & 3) << 3;         // 0,8,16,24
                bool p = (m0 + m < M);
                const __half* src = p ? &A[(size_t)(m0 + m) * lda + kt + k8] : A;
                cpa16(&as[m * APITCH + k8], src, p);
            }
        } else {
#pragma unroll
            for (int i = 0; i < 4; i++) {
                int idx = tidx + i * 256;
                int k  = idx >> 5;               // 0..31
                int m8 = (idx & 31) << 3;        // 0..248
                int gm = m0 + m8;
                bool p = (gm < M);               // M % 8 == 0
                const __half* src = p ? &A[(size_t)(kt + k) * lda + gm] : A;
                cpa16(&as[k * APITCH + m8], src, p);
            }
        }
#pragma unroll
        for (int i = 0; i < 2; i++) {
            int idx = tidx + i * 256;
            int k  = idx >> 4;
            int n8 = (idx & 15) << 3;
            cpa16(&bs[k * BPITCH + n8], &B[(size_t)(kt + k) * 128 + n8], true);
        }
        cpa_commit();
    };

    int pre = kTiles < (HST - 1) ? kTiles : (HST - 1);
    for (int t = 0; t < pre; t++) load_tile(t, t % HST);
    for (int t = pre; t < HST - 1; t++) cpa_commit();

    unsigned smBase = (unsigned)__cvta_generic_to_shared(hsm);

    for (int t = 0; t < kTiles; t++) {
        if (t + HST - 1 < kTiles) load_tile(t + HST - 1, (t + HST - 1) % HST);
        else cpa_commit();
        asm volatile("cp.async.wait_group %0;\n" :: "n"(HST - 1));
        __syncthreads();

        unsigned as_u = smBase + (unsigned)((t % HST) * (ASZ + BSZ) * 2);
        unsigned bs_u = as_u + ASZ * 2;

#pragma unroll
        for (int kk = 0; kk < BK; kk += 16) {
            unsigned af[4][4];
#pragma unroll
            for (int mi = 0; mi < 4; mi++) {
                int bm = wm * 64 + mi * 16;
                if (!TRANS_A) {
                    unsigned a = as_u + (unsigned)(((bm + (lt & 1) * 8 + lr) * APITCH
                                                   + kk + (lt >> 1) * 8) * 2);
                    ldsm_x4(af[mi], a);
                } else {
                    unsigned a = as_u + (unsigned)(((kk + (lt >> 1) * 8 + lr) * APITCH
                                                   + bm + (lt & 1) * 8) * 2);
                    ldsm_x4t(af[mi], a);
                }
            }
            unsigned bf[8][2];
#pragma unroll
            for (int nj = 0; nj < 4; nj++) {
                unsigned r[4];
                unsigned a = bs_u + (unsigned)(((kk + (lt & 1) * 8 + lr) * BPITCH
                                               + wn * 64 + nj * 16 + (lt >> 1) * 8) * 2);
                ldsm_x4t(r, a);
                bf[2 * nj    ][0] = r[0]; bf[2 * nj    ][1] = r[1];
                bf[2 * nj + 1][0] = r[2]; bf[2 * nj + 1][1] = r[3];
            }
#pragma unroll
            for (int mi = 0; mi < 4; mi++)
#pragma unroll
                for (int ni = 0; ni < 8; ni++)
                    mma_f16(acc[mi][ni], af[mi], bf[ni]);
        }
        __syncthreads();
    }

    // ---- epilogue: atomic split-K with rowscale * dynamic undo-scale ----
    const float undo = *undoPtr;
#pragma unroll
    for (int mi = 0; mi < 4; mi++) {
#pragma unroll
        for (int h = 0; h < 2; h++) {
            int r = m0 + wm * 64 + mi * 16 + g + h * 8;
            if (r >= M) continue;
            float rs = rowscale[r] * undo;
#pragma unroll
            for (int ni = 0; ni < 8; ni++) {
                int cc = wn * 64 + ni * 8 + tg * 2;
                atomicAdd(&C[(size_t)r * 128 + cc    ], acc[mi][ni][h * 2 + 0] * rs);
                atomicAdd(&C[(size_t)r * 128 + cc + 1], acc[mi][ni][h * 2 + 1] * rs);
            }
        }
    }
}

// ============================================================================
// tf32 GEMM for the small K=128 GEMMs (fp32 out).
// C[m,n] = rowscale[m]*(A[M,128] @ B[128,128] + bias); rowsel gating with
// blockIdx.z selecting B/bias slabs.
// ============================================================================
__global__ void __launch_bounds__(256, 1)
gemm256(const float* __restrict__ A, const float* __restrict__ B,
        float* __restrict__ C, int M,
        const float* __restrict__ bias, const float* __restrict__ rowscale,
        const int* __restrict__ rowsel, int ldbz, int biasz)
{
    constexpr int K = 128;
    constexpr int APITCH = BK + 4;
    constexpr int ASZ = BM * APITCH;
    constexpr int BPITCH = BN + 8;
    constexpr int BSZ = BK * BPITCH;
    extern __shared__ char smraw[];
    unsigned* sm = (unsigned*)smraw;

    const int m0 = blockIdx.x * BM;
    const int zt = blockIdx.z;
    B += (size_t)zt * ldbz;
    if (bias) bias += (size_t)zt * biasz;

    const int tidx = threadIdx.x;
    const int lane = tidx & 31;
    const int g  = lane >> 2;
    const int tg = lane & 3;
    const int wm = (tidx >> 5) & 3;
    const int wn = (tidx >> 7);

    float acc[4][8][4];
#pragma unroll
    for (int mi = 0; mi < 4; mi++)
#pragma unroll
        for (int ni = 0; ni < 8; ni++)
#pragma unroll
            for (int j = 0; j < 4; j++) acc[mi][ni][j] = 0.f;

    auto load_tile = [&](int t, int stage) {
        int kt = t * BK;
        unsigned* as = sm + stage * (ASZ + BSZ);
        unsigned* bs = as + ASZ;
#pragma unroll
        for (int i = 0; i < 8; i++) {
            int idx = tidx + i * 256;
            int m  = idx >> 3;
            int k4 = (idx & 7) << 2;
            bool p = (m0 + m < M);
            const float* src = p ? &A[(size_t)(m0 + m) * K + kt + k4] : A;
            cpa16(&as[m * APITCH + k4], src, p);
        }
#pragma unroll
        for (int i = 0; i < 4; i++) {
            int idx = tidx + i * 256;
            int k  = idx >> 5;
            int n4 = (idx & 31) << 2;
            cpa16(&bs[k * BPITCH + n4], &B[(size_t)(kt + k) * 128 + n4], true);
        }
        cpa_commit();
    };

    const int kTiles = K / BK;   // 4
    int pre = kTiles < (STAGES - 1) ? kTiles : (STAGES - 1);
    for (int t = 0; t < pre; t++) load_tile(t, t % STAGES);
    for (int t = pre; t < STAGES - 1; t++) cpa_commit();

    for (int t = 0; t < kTiles; t++) {
        if (t + STAGES - 1 < kTiles) load_tile(t + STAGES - 1, (t + STAGES - 1) % STAGES);
        else cpa_commit();
        asm volatile("cp.async.wait_group %0;\n" :: "n"(STAGES - 1));
        __syncthreads();

        const unsigned* as = sm + (t % STAGES) * (ASZ + BSZ);
        const unsigned* bs = as + ASZ;

#pragma unroll
        for (int kk = 0; kk < BK; kk += 8) {
            unsigned af[4][4];
#pragma unroll
            for (int mi = 0; mi < 4; mi++) {
                int bm = wm * 64 + mi * 16;
                af[mi][0] = f2tf32(as[(bm + g    ) * APITCH + kk + tg    ]);
                af[mi][1] = f2tf32(as[(bm + g + 8) * APITCH + kk + tg    ]);
                af[mi][2] = f2tf32(as[(bm + g    ) * APITCH + kk + tg + 4]);
                af[mi][3] = f2tf32(as[(bm + g + 8) * APITCH + kk + tg + 4]);
            }
            unsigned bf[8][2];
#pragma unroll
            for (int ni = 0; ni < 8; ni++) {
                int bn = wn * 64 + ni * 8;
                bf[ni][0] = bs[(kk + tg    ) * BPITCH + bn + g];
                bf[ni][1] = bs[(kk + tg + 4) * BPITCH + bn + g];
            }
#pragma unroll
            for (int mi = 0; mi < 4; mi++)
#pragma unroll
                for (int ni = 0; ni < 8; ni++)
                    mma_tf32(acc[mi][ni], af[mi], bf[ni]);
        }
        __syncthreads();
    }

#pragma unroll
    for (int mi = 0; mi < 4; mi++) {
#pragma unroll
        for (int h = 0; h < 2; h++) {
            int r = m0 + wm * 64 + mi * 16 + g + h * 8;
            if (r >= M) continue;
            if (rowsel && rowsel[r] != zt) continue;
            float rs = rowscale ? rowscale[r] : 1.f;
#pragma unroll
            for (int ni = 0; ni < 8; ni++) {
                int cc = wn * 64 + ni * 8 + tg * 2;
                float v0 = acc[mi][ni][h * 2 + 0];
                float v1 = acc[mi][ni][h * 2 + 1];
                if (bias) { v0 += bias[cc]; v1 += bias[cc + 1]; }
                C[(size_t)r * 128 + cc    ] = v0 * rs;
                C[(size_t)r * 128 + cc + 1] = v1 * rs;
            }
        }
    }
}

// ---------------- small kernels ----------------
__global__ void zero_kernel(float* __restrict__ p, int n) {
    int i = blockIdx.x * blockDim.x + threadIdx.x;
    if (i < n) p[i] = 0.f;
}
__global__ void reset_amax(unsigned* slot) { *slot = 0u; }

// absmax over n4 float4's -> atomicMax on float bits (non-negative => monotone)
__global__ void absmax_kernel(const float* __restrict__ x, long long n4,
                              unsigned* __restrict__ out) {
    float m = 0.f;
    for (long long i = (long long)blockIdx.x * blockDim.x + threadIdx.x;
         i < n4; i += (long long)gridDim.x * blockDim.x) {
        float4 v = ((const float4*)x)[i];
        m = fmaxf(m, fmaxf(fmaxf(fabsf(v.x), fabsf(v.y)),
                           fmaxf(fabsf(v.z), fabsf(v.w))));
    }
#pragma unroll
    for (int o = 16; o; o >>= 1) m = fmaxf(m, __shfl_xor_sync(~0u, m, o));
    if ((threadIdx.x & 31) == 0) atomicMax(out, __float_as_uint(m));
}

// s = 2^-k so absmax*s <= 16384 (4x margin to 65504); undo = 2^k. Exact.
__global__ void make_scale(const unsigned* __restrict__ amax,
                           float* __restrict__ s, float* __restrict__ undo) {
    float m = __uint_as_float(*amax);
    int k = 0;
    if (m > 16384.f) k = (int)ceilf(log2f(m * (1.f / 16384.f))) ;
    if (k < 0) k = 0;
    *s = ldexpf(1.f, -k);
    *undo = ldexpf(1.f, k);
}

// fp32 -> fp16 (RN) with dynamic scale, 8 elems/thread
__global__ void f2h_dyn(__half* __restrict__ dst, const float* __restrict__ src,
                        long long n8, const float* __restrict__ sPtr) {
    float s = sPtr ? *sPtr : 1.f;
    long long i = (long long)blockIdx.x * blockDim.x + threadIdx.x;
    if (i < n8) {
        float4 a = ((const float4*)src)[2 * i];
        float4 b = ((const float4*)src)[2 * i + 1];
        __half2 h[4];
        h[0] = __floats2half2_rn(a.x * s, a.y * s);
        h[1] = __floats2half2_rn(a.z * s, a.w * s);
        h[2] = __floats2half2_rn(b.x * s, b.y * s);
        h[3] = __floats2half2_rn(b.z * s, b.w * s);
        ((uint4*)dst)[i] = *(uint4*)h;
    }
}

__global__ void round_tf32_kernel(float* __restrict__ dst, const float* __restrict__ src, int n4) {
    int i = blockIdx.x * blockDim.x + threadIdx.x;
    if (i < n4) {
        float4 v = ((const float4*)src)[i];
        v.x = roundtf(v.x); v.y = roundtf(v.y);
        v.z = roundtf(v.z); v.w = roundtf(v.w);
        ((float4*)dst)[i] = v;
    }
}

__global__ void fusion_kernel(const float* __restrict__ fw,
                              const float* __restrict__ X0,
                              const float* __restrict__ X1,
                              const float* __restrict__ X2,
                              float* __restrict__ out, int n) {
    float f0 = fw[0], f1 = fw[1], f2 = fw[2];
    float mx = fmaxf(f0, fmaxf(f1, f2));
    float e0 = expf(f0 - mx), e1 = expf(f1 - mx), e2 = expf(f2 - mx);
    float inv = 1.f / (e0 + e1 + e2);
    float w0 = e0 * inv, w1 = e1 * inv, w2 = e2 * inv;
    int i = blockIdx.x * blockDim.x + threadIdx.x;
    if (i < n) out[i] = w0 * X0[i] + w1 * X1[i] + w2 * X2[i];
}

static inline int chunk_for(int K, int S) {
    int tiles = (K + BK - 1) / BK;
    int per = (tiles + S - 1) / S;
    return per * BK;
}

extern "C" void kernel_launch(void* const* d_in, const int* in_sizes, int n_in,
                              void* d_out, int out_size) {
    const float* emb = (const float*)d_in[0];
    const float* Wt  = (const float*)d_in[1];
    const float* bt  = (const float*)d_in[2];
    const float* W1  = (const float*)d_in[3];
    const float* b1  = (const float*)d_in[4];
    const float* W2  = (const float*)d_in[5];
    const float* b2  = (const float*)d_in[6];
    const float* fw  = (const float*)d_in[7];
    const float* H   = (const float*)d_in[8];
    const float* dv  = (const float*)d_in[9];
    const float* de  = (const float*)d_in[10];
    const int*   tid = (const int*)d_in[11];

    const int D = in_sizes[4];          // 128
    const int N = in_sizes[9];          // 20000
    const int E = in_sizes[10];         // 8000
    const int T = in_sizes[2] / D;      // 5

    float* buf = nullptr;
    cudaGetSymbolAddress((void**)&buf, g_buf);
    __half* hb = nullptr;
    cudaGetSymbolAddress((void**)&hb, g_hbuf);
    unsigned* sc = nullptr;
    cudaGetSymbolAddress((void**)&sc, g_sc);

    size_t nd = (size_t)N * D, ed = (size_t)E * D, ne = (size_t)N * E;
    float* X0  = buf;
    float* X1  = X0 + nd;
    float* X2  = X1 + nd;
    float* Yf  = X2 + nd;
    float* Mm  = Yf + nd;
    float* Wtr = Mm + ed;
    float* W1r = Wtr + (size_t)T * D * D;
    float* W2r = W1r + (size_t)D * D;
    __half* Hh  = hb;
    __half* Yh  = Hh + ne;
    __half* Mmh = Yh + nd;

    unsigned* amaxY = sc + 0;
    float* sY = (float*)(sc + 1);
    float* uY = (float*)(sc + 2);
    unsigned* amaxM = sc + 3;
    float* sM = (float*)(sc + 4);
    float* uM = (float*)(sc + 5);

    // dynamic smem sizes
    const int smemG = STAGES * (BM * (BK + 4) + BK * (BN + 8)) * 4;     // tf32
    const int smemHT = HST * (BK * (BM + 8) + BK * (BN + 8)) * 2;       // fp16 trans
    const int smemHN = HST * (BM * (BK + 8) + BK * (BN + 8)) * 2;       // fp16 non-trans
    static bool attr_done = false;
    if (!attr_done) {
        cudaFuncSetAttribute(gemm256,      cudaFuncAttributeMaxDynamicSharedMemorySize, smemG);
        cudaFuncSetAttribute(hgemm<true>,  cudaFuncAttributeMaxDynamicSharedMemorySize, smemHT);
        cudaFuncSetAttribute(hgemm<false>, cudaFuncAttributeMaxDynamicSharedMemorySize, smemHN);
        attr_done = true;
    }

    dim3 blk(256);
    int mt_n = (N + BM - 1) / BM;       // 79
    int mt_e = (E + BM - 1) / BM;       // 32
    const int S1 = 9;                   // split-K for Hh^T @ Yh (K=N)
    const int S2 = 4;                   // split-K for Hh @ Mmh  (K=E)
    int ch1 = chunk_for(N, S1);
    int ch2 = chunk_for(E, S2);
    int zt_ = 256;
    const int RB = 1024;                // absmax reduce blocks

    // ---- prep: round weights (tf32 B operands); convert H -> fp16 (exact range) ----
    int wt_n4 = T * D * D / 4, w_n4 = D * D / 4;
    round_tf32_kernel<<<(wt_n4 + 255) / 256, 256>>>(Wtr, Wt, wt_n4);
    round_tf32_kernel<<<(w_n4 + 255) / 256, 256>>>(W1r, W1, w_n4);
    round_tf32_kernel<<<(w_n4 + 255) / 256, 256>>>(W2r, W2, w_n4);
    long long h8 = (long long)(ne / 8);
    f2h_dyn<<<(int)((h8 + 255) / 256), 256>>>(Hh, H, h8, nullptr);

    // ---- X0: per-type projection with fused type-select ----
    gemm256<<<dim3(mt_n, 1, T), blk, smemG>>>(
        emb, Wtr, X0, N, bt, nullptr, tid, D * D, D);

    for (int layer = 0; layer < 2; layer++) {
        const float* Xin = (layer == 0) ? X0 : X1;
        float* Xout      = (layer == 0) ? X1 : X2;
        const float* W   = (layer == 0) ? W1r : W2r;
        const float* b   = (layer == 0) ? b1 : b2;

        // Yf = dv * (Xin @ W + b)
        gemm256<<<dim3(mt_n, 1, 1), blk, smemG>>>(
            Xin, W, Yf, N, b, dv, nullptr, 0, 0);
        // dynamic scale + convert Y
        reset_amax<<<1, 1>>>(amaxY);
        absmax_kernel<<<RB, 256>>>(Yf, (long long)(nd / 4), amaxY);
        make_scale<<<1, 1>>>(amaxY, sY, uY);
        f2h_dyn<<<(int)((nd / 8 + 255) / 256), 256>>>(Yh, Yf, (long long)(nd / 8), sY);
        // Mm = de * (Hh^T @ Yh) * undoY
        zero_kernel<<<(int)((ed + zt_ - 1) / zt_), zt_>>>(Mm, (int)ed);
        hgemm<true><<<dim3(mt_e, S1, 1), blk, smemHT>>>(Hh, Yh, Mm, E, N, E, de, uY, ch1);
        // dynamic scale + convert Mm
        reset_amax<<<1, 1>>>(amaxM);
        absmax_kernel<<<RB, 256>>>(Mm, (long long)(ed / 4), amaxM);
        make_scale<<<1, 1>>>(amaxM, sM, uM);
        f2h_dyn<<<(int)((ed / 8 + 255) / 256), 256>>>(Mmh, Mm, (long long)(ed / 8), sM);
        // Xout = dv * (Hh @ Mmh) * undoM
        zero_kernel<<<(int)((nd + zt_ - 1) / zt_), zt_>>>(Xout, (int)nd);
        hgemm<false><<<dim3(mt_n, S2, 1), blk, smemHN>>>(Hh, Mmh, Xout, N, E, E, dv, uM, ch2);
    }

    // ---- fusion ----
    fusion_kernel<<<(int)((nd + zt_ - 1) / zt_), zt_>>>(
        fw, X0, X1, X2, (float*)d_out, (int)nd);
}

// round 10
// speedup vs baseline: 2.5464x; 1.1419x over previous
#include <cuda_runtime.h>
#include <cuda_fp16.h>
#include <math.h>

// ----------------------------------------------------------------------------
// HyperGraphModel on GB300.
//  - 4 big H-GEMMs in fp16 (HMMA m16n8k16, fp32 accum, ldmatrix fragments,
//    3-stage BK=64 cp.async pipeline, ONE barrier per k-tile).
//  - fp16 intermediates use DYNAMIC power-of-2 scaling (absmax -> 2^-k,
//    undone in consuming epilogue; exponent-only => exact).
//  - small D x D GEMMs stay tf32 mma.sync (pre-rounded B weights).
// ----------------------------------------------------------------------------

#define BM 256
#define BN 128
#define BK 32            // tf32 kernel k-tile
#define HBK 64           // fp16 kernel k-tile
#define STAGES 3         // tf32 stages
#define HST 3            // fp16 stages

// fp32 scratch: X0,X1,X2,Yf (4*N*D) + Mm (E*D) + Wtr + W1r + W2r
__device__ float g_buf[11400000];
// fp16 scratch: Hh (N*E) + Yh (N*D) + Mmh (E*D)
__device__ __align__(256) __half g_hbuf[163600000];
// scale slots: [0]=amaxY bits, [1]=sY, [2]=uY, [3]=amaxM, [4]=sM, [5]=uM
__device__ unsigned g_sc[8];

// ---------------- common helpers ----------------
__device__ __forceinline__ unsigned f2tf32(unsigned x) {
    unsigned r;
    asm("cvt.rna.tf32.f32 %0, %1;" : "=r"(r) : "r"(x));
    return r;
}
__device__ __forceinline__ float roundtf(float x) {
    return __uint_as_float(f2tf32(__float_as_uint(x)));
}
__device__ __forceinline__ void mma_tf32(float* c, const unsigned* a, const unsigned* b) {
    asm volatile(
        "mma.sync.aligned.m16n8k8.row.col.f32.tf32.tf32.f32 "
        "{%0,%1,%2,%3}, {%4,%5,%6,%7}, {%8,%9}, {%0,%1,%2,%3};\n"
        : "+f"(c[0]), "+f"(c[1]), "+f"(c[2]), "+f"(c[3])
        : "r"(a[0]), "r"(a[1]), "r"(a[2]), "r"(a[3]), "r"(b[0]), "r"(b[1]));
}
__device__ __forceinline__ void mma_f16(float* c, const unsigned* a, const unsigned* b) {
    asm volatile(
        "mma.sync.aligned.m16n8k16.row.col.f32.f16.f16.f32 "
        "{%0,%1,%2,%3}, {%4,%5,%6,%7}, {%8,%9}, {%0,%1,%2,%3};\n"
        : "+f"(c[0]), "+f"(c[1]), "+f"(c[2]), "+f"(c[3])
        : "r"(a[0]), "r"(a[1]), "r"(a[2]), "r"(a[3]), "r"(b[0]), "r"(b[1]));
}
__device__ __forceinline__ void cpa16(void* dst, const void* src, bool pred) {
    unsigned daddr = (unsigned)__cvta_generic_to_shared(dst);
    int sz = pred ? 16 : 0;   // sz=0 -> 16B zero-fill (used for M/K edges)
    asm volatile("cp.async.cg.shared.global [%0], [%1], 16, %2;\n"
                 :: "r"(daddr), "l"(src), "r"(sz));
}
__device__ __forceinline__ void cpa_commit() {
    asm volatile("cp.async.commit_group;\n");
}
__device__ __forceinline__ void ldsm_x4(unsigned* r, unsigned a) {
    asm volatile("ldmatrix.sync.aligned.m8n8.x4.shared.b16 {%0,%1,%2,%3}, [%4];"
                 : "=r"(r[0]), "=r"(r[1]), "=r"(r[2]), "=r"(r[3]) : "r"(a));
}
__device__ __forceinline__ void ldsm_x4t(unsigned* r, unsigned a) {
    asm volatile("ldmatrix.sync.aligned.m8n8.x4.trans.shared.b16 {%0,%1,%2,%3}, [%4];"
                 : "=r"(r[0]), "=r"(r[1]), "=r"(r[2]), "=r"(r[3]) : "r"(a));
}

// ============================================================================
// fp16 GEMM: C[M,128] += (*undoPtr) * rowscale[m] * (op(A)[M,K] @ B[K,128]),
// atomic split-K into pre-zeroed fp32 C.
//  TRANS_A=false: A row-major [M,K] fp16 (lda = K)
//  TRANS_A=true : A stored [K,M] fp16, element (m,k) = A[k*lda+m]
// Requires: kChunk % 64 == 0, K % 32 == 0, M % 8 == 0. K edges zero-filled.
// ============================================================================
template <bool TRANS_A>
__global__ void __launch_bounds__(256, 1)
hgemm(const __half* __restrict__ A, const __half* __restrict__ B,
      float* __restrict__ C, int M, int K, int lda,
      const float* __restrict__ rowscale, const float* __restrict__ undoPtr,
      int kChunk)
{
    constexpr int APITCH = TRANS_A ? (BM + 8) : (HBK + 8);    // halves
    constexpr int ASZ = TRANS_A ? HBK * (BM + 8) : BM * (HBK + 8);
    constexpr int BPITCH = BN + 8;
    constexpr int BSZ = HBK * BPITCH;
    extern __shared__ char smraw[];
    __half* hsm = (__half*)smraw;

    const int m0 = blockIdx.x * BM;
    const int kBegin = blockIdx.y * kChunk;
    const int kEnd = min(K, kBegin + kChunk);
    if (kBegin >= K) return;
    const int kTiles = (kEnd - kBegin + HBK - 1) / HBK;

    const int tidx = threadIdx.x;
    const int lane = tidx & 31;
    const int g  = lane >> 2;
    const int tg = lane & 3;
    const int wm = (tidx >> 5) & 3;   // warp row (64 M)
    const int wn = (tidx >> 7);       // warp col (64 N)
    const int lt = lane >> 3;         // ldmatrix tile id 0..3
    const int lr = lane & 7;          // ldmatrix row in tile

    float acc[4][8][4];
#pragma unroll
    for (int mi = 0; mi < 4; mi++)
#pragma unroll
        for (int ni = 0; ni < 8; ni++)
#pragma unroll
            for (int j = 0; j < 4; j++) acc[mi][ni][j] = 0.f;

    auto load_tile = [&](int t, int stage) {
        int kt = kBegin + t * HBK;
        __half* as = hsm + stage * (ASZ + BSZ);
        __half* bs = as + ASZ;
        if (!TRANS_A) {
            // A [m][k]: 256 rows x 64 halves = 2048 x 16B chunks
#pragma unroll
            for (int i = 0; i < 8; i++) {
                int idx = tidx + i * 256;
                int m  = idx >> 3;               // 0..255
                int k8 = (idx & 7) << 3;         // 0..56
                bool p = (m0 + m < M) && (kt + k8 < kEnd);
                const __half* src = p ? &A[(size_t)(m0 + m) * lda + kt + k8] : A;
                cpa16(&as[m * APITCH + k8], src, p);
            }
        } else {
            // A [k][m]: 64 rows x 256 halves
#pragma unroll
            for (int i = 0; i < 8; i++) {
                int idx = tidx + i * 256;
                int k  = idx >> 5;               // 0..63
                int m8 = (idx & 31) << 3;        // 0..248
                int gm = m0 + m8;
                bool p = (gm < M) && (kt + k < kEnd);
                const __half* src = p ? &A[(size_t)(kt + k) * lda + gm] : A;
                cpa16(&as[k * APITCH + m8], src, p);
            }
        }
        // B [k][n]: 64 x 128 halves = 1024 chunks
#pragma unroll
        for (int i = 0; i < 4; i++) {
            int idx = tidx + i * 256;
            int k  = idx >> 4;                   // 0..63
            int n8 = (idx & 15) << 3;
            bool p = (kt + k < kEnd);
            const __half* src = p ? &B[(size_t)(kt + k) * 128 + n8] : (const __half*)B;
            cpa16(&bs[k * BPITCH + n8], src, p);
        }
        cpa_commit();
    };

    // prologue: HST-1 groups in flight
    int pre = kTiles < (HST - 1) ? kTiles : (HST - 1);
    for (int t = 0; t < pre; t++) load_tile(t, t % HST);
    for (int t = pre; t < HST - 1; t++) cpa_commit();

    unsigned smBase = (unsigned)__cvta_generic_to_shared(hsm);

    for (int t = 0; t < kTiles; t++) {
        // retire tile t; one barrier per tile (all warps done reading stage (t-1)%HST)
        asm volatile("cp.async.wait_group %0;\n" :: "n"(HST - 2));
        __syncthreads();
        if (t + HST - 1 < kTiles) load_tile(t + HST - 1, (t + HST - 1) % HST);
        else cpa_commit();

        unsigned as_u = smBase + (unsigned)((t % HST) * (ASZ + BSZ) * 2);
        unsigned bs_u = as_u + ASZ * 2;

#pragma unroll
        for (int kk = 0; kk < HBK; kk += 16) {
            unsigned af[4][4];
#pragma unroll
            for (int mi = 0; mi < 4; mi++) {
                int bm = wm * 64 + mi * 16;
                if (!TRANS_A) {
                    unsigned a = as_u + (unsigned)(((bm + (lt & 1) * 8 + lr) * APITCH
                                                   + kk + (lt >> 1) * 8) * 2);
                    ldsm_x4(af[mi], a);
                } else {
                    unsigned a = as_u + (unsigned)(((kk + (lt >> 1) * 8 + lr) * APITCH
                                                   + bm + (lt & 1) * 8) * 2);
                    ldsm_x4t(af[mi], a);
                }
            }
            unsigned bf[8][2];
#pragma unroll
            for (int nj = 0; nj < 4; nj++) {
                unsigned r[4];
                unsigned a = bs_u + (unsigned)(((kk + (lt & 1) * 8 + lr) * BPITCH
                                               + wn * 64 + nj * 16 + (lt >> 1) * 8) * 2);
                ldsm_x4t(r, a);
                bf[2 * nj    ][0] = r[0]; bf[2 * nj    ][1] = r[1];
                bf[2 * nj + 1][0] = r[2]; bf[2 * nj + 1][1] = r[3];
            }
#pragma unroll
            for (int mi = 0; mi < 4; mi++)
#pragma unroll
                for (int ni = 0; ni < 8; ni++)
                    mma_f16(acc[mi][ni], af[mi], bf[ni]);
        }
    }

    // ---- epilogue: atomic split-K with rowscale * dynamic undo-scale ----
    const float undo = *undoPtr;
#pragma unroll
    for (int mi = 0; mi < 4; mi++) {
#pragma unroll
        for (int h = 0; h < 2; h++) {
            int r = m0 + wm * 64 + mi * 16 + g + h * 8;
            if (r >= M) continue;
            float rs = rowscale[r] * undo;
#pragma unroll
            for (int ni = 0; ni < 8; ni++) {
                int cc = wn * 64 + ni * 8 + tg * 2;
                atomicAdd(&C[(size_t)r * 128 + cc    ], acc[mi][ni][h * 2 + 0] * rs);
                atomicAdd(&C[(size_t)r * 128 + cc + 1], acc[mi][ni][h * 2 + 1] * rs);
            }
        }
    }
}

// ============================================================================
// tf32 GEMM for the small K=128 GEMMs (fp32 out).
// C[m,n] = rowscale[m]*(A[M,128] @ B[128,128] + bias); rowsel gating with
// blockIdx.z selecting B/bias slabs.
// ============================================================================
__global__ void __launch_bounds__(256, 1)
gemm256(const float* __restrict__ A, const float* __restrict__ B,
        float* __restrict__ C, int M,
        const float* __restrict__ bias, const float* __restrict__ rowscale,
        const int* __restrict__ rowsel, int ldbz, int biasz)
{
    constexpr int K = 128;
    constexpr int APITCH = BK + 4;
    constexpr int ASZ = BM * APITCH;
    constexpr int BPITCH = BN + 8;
    constexpr int BSZ = BK * BPITCH;
    extern __shared__ char smraw[];
    unsigned* sm = (unsigned*)smraw;

    const int m0 = blockIdx.x * BM;
    const int zt = blockIdx.z;
    B += (size_t)zt * ldbz;
    if (bias) bias += (size_t)zt * biasz;

    const int tidx = threadIdx.x;
    const int lane = tidx & 31;
    const int g  = lane >> 2;
    const int tg = lane & 3;
    const int wm = (tidx >> 5) & 3;
    const int wn = (tidx >> 7);

    float acc[4][8][4];
#pragma unroll
    for (int mi = 0; mi < 4; mi++)
#pragma unroll
        for (int ni = 0; ni < 8; ni++)
#pragma unroll
            for (int j = 0; j < 4; j++) acc[mi][ni][j] = 0.f;

    auto load_tile = [&](int t, int stage) {
        int kt = t * BK;
        unsigned* as = sm + stage * (ASZ + BSZ);
        unsigned* bs = as + ASZ;
#pragma unroll
        for (int i = 0; i < 8; i++) {
            int idx = tidx + i * 256;
            int m  = idx >> 3;
            int k4 = (idx & 7) << 2;
            bool p = (m0 + m < M);
            const float* src = p ? &A[(size_t)(m0 + m) * K + kt + k4] : A;
            cpa16(&as[m * APITCH + k4], src, p);
        }
#pragma unroll
        for (int i = 0; i < 4; i++) {
            int idx = tidx + i * 256;
            int k  = idx >> 5;
            int n4 = (idx & 31) << 2;
            cpa16(&bs[k * BPITCH + n4], &B[(size_t)(kt + k) * 128 + n4], true);
        }
        cpa_commit();
    };

    const int kTiles = K / BK;   // 4
    int pre = kTiles < (STAGES - 1) ? kTiles : (STAGES - 1);
    for (int t = 0; t < pre; t++) load_tile(t, t % STAGES);
    for (int t = pre; t < STAGES - 1; t++) cpa_commit();

    for (int t = 0; t < kTiles; t++) {
        asm volatile("cp.async.wait_group %0;\n" :: "n"(STAGES - 2));
        __syncthreads();
        if (t + STAGES - 1 < kTiles) load_tile(t + STAGES - 1, (t + STAGES - 1) % STAGES);
        else cpa_commit();

        const unsigned* as = sm + (t % STAGES) * (ASZ + BSZ);
        const unsigned* bs = as + ASZ;

#pragma unroll
        for (int kk = 0; kk < BK; kk += 8) {
            unsigned af[4][4];
#pragma unroll
            for (int mi = 0; mi < 4; mi++) {
                int bm = wm * 64 + mi * 16;
                af[mi][0] = f2tf32(as[(bm + g    ) * APITCH + kk + tg    ]);
                af[mi][1] = f2tf32(as[(bm + g + 8) * APITCH + kk + tg    ]);
                af[mi][2] = f2tf32(as[(bm + g    ) * APITCH + kk + tg + 4]);
                af[mi][3] = f2tf32(as[(bm + g + 8) * APITCH + kk + tg + 4]);
            }
            unsigned bf[8][2];
#pragma unroll
            for (int ni = 0; ni < 8; ni++) {
                int bn = wn * 64 + ni * 8;
                bf[ni][0] = bs[(kk + tg    ) * BPITCH + bn + g];
                bf[ni][1] = bs[(kk + tg + 4) * BPITCH + bn + g];
            }
#pragma unroll
            for (int mi = 0; mi < 4; mi++)
#pragma unroll
                for (int ni = 0; ni < 8; ni++)
                    mma_tf32(acc[mi][ni], af[mi], bf[ni]);
        }
    }

#pragma unroll
    for (int mi = 0; mi < 4; mi++) {
#pragma unroll
        for (int h = 0; h < 2; h++) {
            int r = m0 + wm * 64 + mi * 16 + g + h * 8;
            if (r >= M) continue;
            if (rowsel && rowsel[r] != zt) continue;
            float rs = rowscale ? rowscale[r] : 1.f;
#pragma unroll
            for (int ni = 0; ni < 8; ni++) {
                int cc = wn * 64 + ni * 8 + tg * 2;
                float v0 = acc[mi][ni][h * 2 + 0];
                float v1 = acc[mi][ni][h * 2 + 1];
                if (bias) { v0 += bias[cc]; v1 += bias[cc + 1]; }
                C[(size_t)r * 128 + cc    ] = v0 * rs;
                C[(size_t)r * 128 + cc + 1] = v1 * rs;
            }
        }
    }
}

// ---------------- small kernels ----------------
__global__ void zero_kernel(float* __restrict__ p, int n) {
    int i = blockIdx.x * blockDim.x + threadIdx.x;
    if (i < n) p[i] = 0.f;
}
__global__ void reset_amax(unsigned* slot) { *slot = 0u; }

__global__ void absmax_kernel(const float* __restrict__ x, long long n4,
                              unsigned* __restrict__ out) {
    float m = 0.f;
    for (long long i = (long long)blockIdx.x * blockDim.x + threadIdx.x;
         i < n4; i += (long long)gridDim.x * blockDim.x) {
        float4 v = ((const float4*)x)[i];
        m = fmaxf(m, fmaxf(fmaxf(fabsf(v.x), fabsf(v.y)),
                           fmaxf(fabsf(v.z), fabsf(v.w))));
    }
#pragma unroll
    for (int o = 16; o; o >>= 1) m = fmaxf(m, __shfl_xor_sync(~0u, m, o));
    if ((threadIdx.x & 31) == 0) atomicMax(out, __float_as_uint(m));
}

// s = 2^-k so absmax*s <= 16384 (4x margin to 65504); undo = 2^k. Exact.
__global__ void make_scale(const unsigned* __restrict__ amax,
                           float* __restrict__ s, float* __restrict__ undo) {
    float m = __uint_as_float(*amax);
    int k = 0;
    if (m > 16384.f) k = (int)ceilf(log2f(m * (1.f / 16384.f)));
    if (k < 0) k = 0;
    *s = ldexpf(1.f, -k);
    *undo = ldexpf(1.f, k);
}

__global__ void f2h_dyn(__half* __restrict__ dst, const float* __restrict__ src,
                        long long n8, const float* __restrict__ sPtr) {
    float s = sPtr ? *sPtr : 1.f;
    long long i = (long long)blockIdx.x * blockDim.x + threadIdx.x;
    if (i < n8) {
        float4 a = ((const float4*)src)[2 * i];
        float4 b = ((const float4*)src)[2 * i + 1];
        __half2 h[4];
        h[0] = __floats2half2_rn(a.x * s, a.y * s);
        h[1] = __floats2half2_rn(a.z * s, a.w * s);
        h[2] = __floats2half2_rn(b.x * s, b.y * s);
        h[3] = __floats2half2_rn(b.z * s, b.w * s);
        ((uint4*)dst)[i] = *(uint4*)h;
    }
}

__global__ void round_tf32_kernel(float* __restrict__ dst, const float* __restrict__ src, int n4) {
    int i = blockIdx.x * blockDim.x + threadIdx.x;
    if (i < n4) {
        float4 v = ((const float4*)src)[i];
        v.x = roundtf(v.x); v.y = roundtf(v.y);
        v.z = roundtf(v.z); v.w = roundtf(v.w);
        ((float4*)dst)[i] = v;
    }
}

__global__ void fusion_kernel(const float* __restrict__ fw,
                              const float* __restrict__ X0,
                              const float* __restrict__ X1,
                              const float* __restrict__ X2,
                              float* __restrict__ out, int n) {
    float f0 = fw[0], f1 = fw[1], f2 = fw[2];
    float mx = fmaxf(f0, fmaxf(f1, f2));
    float e0 = expf(f0 - mx), e1 = expf(f1 - mx), e2 = expf(f2 - mx);
    float inv = 1.f / (e0 + e1 + e2);
    float w0 = e0 * inv, w1 = e1 * inv, w2 = e2 * inv;
    int i = blockIdx.x * blockDim.x + threadIdx.x;
    if (i < n) out[i] = w0 * X0[i] + w1 * X1[i] + w2 * X2[i];
}

static inline int chunk64(int K, int S) {
    int tiles = (K + HBK - 1) / HBK;
    int per = (tiles + S - 1) / S;
    return per * HBK;
}

extern "C" void kernel_launch(void* const* d_in, const int* in_sizes, int n_in,
                              void* d_out, int out_size) {
    const float* emb = (const float*)d_in[0];
    const float* Wt  = (const float*)d_in[1];
    const float* bt  = (const float*)d_in[2];
    const float* W1  = (const float*)d_in[3];
    const float* b1  = (const float*)d_in[4];
    const float* W2  = (const float*)d_in[5];
    const float* b2  = (const float*)d_in[6];
    const float* fw  = (const float*)d_in[7];
    const float* H   = (const float*)d_in[8];
    const float* dv  = (const float*)d_in[9];
    const float* de  = (const float*)d_in[10];
    const int*   tid = (const int*)d_in[11];

    const int D = in_sizes[4];          // 128
    const int N = in_sizes[9];          // 20000
    const int E = in_sizes[10];         // 8000
    const int T = in_sizes[2] / D;      // 5

    float* buf = nullptr;
    cudaGetSymbolAddress((void**)&buf, g_buf);
    __half* hb = nullptr;
    cudaGetSymbolAddress((void**)&hb, g_hbuf);
    unsigned* sc = nullptr;
    cudaGetSymbolAddress((void**)&sc, g_sc);

    size_t nd = (size_t)N * D, ed = (size_t)E * D, ne = (size_t)N * E;
    float* X0  = buf;
    float* X1  = X0 + nd;
    float* X2  = X1 + nd;
    float* Yf  = X2 + nd;
    float* Mm  = Yf + nd;
    float* Wtr = Mm + ed;
    float* W1r = Wtr + (size_t)T * D * D;
    float* W2r = W1r + (size_t)D * D;
    __half* Hh  = hb;
    __half* Yh  = Hh + ne;
    __half* Mmh = Yh + nd;

    unsigned* amaxY = sc + 0;
    float* sY = (float*)(sc + 1);
    float* uY = (float*)(sc + 2);
    unsigned* amaxM = sc + 3;
    float* sM = (float*)(sc + 4);
    float* uM = (float*)(sc + 5);

    // dynamic smem sizes
    const int smemG  = STAGES * (BM * (BK + 4) + BK * (BN + 8)) * 4;     // tf32
    const int smemHT = HST * (HBK * (BM + 8) + HBK * (BN + 8)) * 2;      // fp16 trans
    const int smemHN = HST * (BM * (HBK + 8) + HBK * (BN + 8)) * 2;      // fp16 non-trans
    static bool attr_done = false;
    if (!attr_done) {
        cudaFuncSetAttribute(gemm256,      cudaFuncAttributeMaxDynamicSharedMemorySize, smemG);
        cudaFuncSetAttribute(hgemm<true>,  cudaFuncAttributeMaxDynamicSharedMemorySize, smemHT);
        cudaFuncSetAttribute(hgemm<false>, cudaFuncAttributeMaxDynamicSharedMemorySize, smemHN);
        attr_done = true;
    }

    dim3 blk(256);
    int mt_n = (N + BM - 1) / BM;       // 79
    int mt_e = (E + BM - 1) / BM;       // 32
    const int S1 = 9;                   // split-K for Hh^T @ Yh (K=N): 288 CTAs
    const int S2 = 4;                   // split-K for Hh @ Mmh  (K=E): 316 CTAs
    int ch1 = chunk64(N, S1);
    int ch2 = chunk64(E, S2);
    int zt_ = 256;
    const int RB = 1024;

    // ---- prep: round weights (tf32 B operands); convert H -> fp16 ----
    int wt_n4 = T * D * D / 4, w_n4 = D * D / 4;
    round_tf32_kernel<<<(wt_n4 + 255) / 256, 256>>>(Wtr, Wt, wt_n4);
    round_tf32_kernel<<<(w_n4 + 255) / 256, 256>>>(W1r, W1, w_n4);
    round_tf32_kernel<<<(w_n4 + 255) / 256, 256>>>(W2r, W2, w_n4);
    long long h8 = (long long)(ne / 8);
    f2h_dyn<<<(int)((h8 + 255) / 256), 256>>>(Hh, H, h8, nullptr);

    // ---- X0: per-type projection with fused type-select ----
    gemm256<<<dim3(mt_n, 1, T), blk, smemG>>>(
        emb, Wtr, X0, N, bt, nullptr, tid, D * D, D);

    for (int layer = 0; layer < 2; layer++) {
        const float* Xin = (layer == 0) ? X0 : X1;
        float* Xout      = (layer == 0) ? X1 : X2;
        const float* W   = (layer == 0) ? W1r : W2r;
        const float* b   = (layer == 0) ? b1 : b2;

        // Yf = dv * (Xin @ W + b)
        gemm256<<<dim3(mt_n, 1, 1), blk, smemG>>>(
            Xin, W, Yf, N, b, dv, nullptr, 0, 0);
        // dynamic scale + convert Y
        reset_amax<<<1, 1>>>(amaxY);
        absmax_kernel<<<RB, 256>>>(Yf, (long long)(nd / 4), amaxY);
        make_scale<<<1, 1>>>(amaxY, sY, uY);
        f2h_dyn<<<(int)((nd / 8 + 255) / 256), 256>>>(Yh, Yf, (long long)(nd / 8), sY);
        // Mm = de * (Hh^T @ Yh) * undoY
        zero_kernel<<<(int)((ed + zt_ - 1) / zt_), zt_>>>(Mm, (int)ed);
        hgemm<true><<<dim3(mt_e, S1, 1), blk, smemHT>>>(Hh, Yh, Mm, E, N, E, de, uY, ch1);
        // dynamic scale + convert Mm
        reset_amax<<<1, 1>>>(amaxM);
        absmax_kernel<<<RB, 256>>>(Mm, (long long)(ed / 4), amaxM);
        make_scale<<<1, 1>>>(amaxM, sM, uM);
        f2h_dyn<<<(int)((ed / 8 + 255) / 256), 256>>>(Mmh, Mm, (long long)(ed / 8), sM);
        // Xout = dv * (Hh @ Mmh) * undoM
        zero_kernel<<<(int)((nd + zt_ - 1) / zt_), zt_>>>(Xout, (int)nd);
        hgemm<false><<<dim3(mt_n, S2, 1), blk, smemHN>>>(Hh, Mmh, Xout, N, E, E, dv, uM, ch2);
    }

    // ---- fusion ----
    fusion_kernel<<<(int)((nd + zt_ - 1) / zt_), zt_>>>(
        fw, X0, X1, X2, (float*)d_out, (int)nd);
}

// round 11
// speedup vs baseline: 2.6779x; 1.0516x over previous
#include <cuda_runtime.h>
#include <cuda_fp16.h>
#include <math.h>

// ----------------------------------------------------------------------------
// HyperGraphModel on GB300.
//  - 4 big H-GEMMs in fp16 (HMMA m16n8k16, fp32 accum, ldmatrix fragments,
//    3-stage BK=64 cp.async pipeline, ONE barrier per k-tile).
//  - fp16 intermediates use DYNAMIC power-of-2 scaling (absmax -> 2^-k,
//    undone in consuming epilogue; exponent-only => exact).
//  - small D x D GEMMs stay tf32 mma.sync (pre-rounded B weights).
//  - H->fp16 conversion (130us, DRAM-bound) runs on a forked side stream,
//    overlapped with the ~85us pre-hgemm chain (graph fork/join via events).
//  - split-K retuned for wave quantization: non-trans S2=7 (4 waves x 1152
//    beats 3 waves x 2048).
// ----------------------------------------------------------------------------

#define BM 256
#define BN 128
#define BK 32            // tf32 kernel k-tile
#define HBK 64           // fp16 kernel k-tile
#define STAGES 3         // tf32 stages
#define HST 3            // fp16 stages

// fp32 scratch: X0,X1,X2,Yf (4*N*D) + Mm (E*D) + Wtr + W1r + W2r
__device__ float g_buf[11400000];
// fp16 scratch: Hh (N*E) + Yh (N*D) + Mmh (E*D)
__device__ __align__(256) __half g_hbuf[163600000];
// scale slots: [0]=amaxY bits, [1]=sY, [2]=uY, [3]=amaxM, [4]=sM, [5]=uM
__device__ unsigned g_sc[8];

// ---------------- common helpers ----------------
__device__ __forceinline__ unsigned f2tf32(unsigned x) {
    unsigned r;
    asm("cvt.rna.tf32.f32 %0, %1;" : "=r"(r) : "r"(x));
    return r;
}
__device__ __forceinline__ float roundtf(float x) {
    return __uint_as_float(f2tf32(__float_as_uint(x)));
}
__device__ __forceinline__ void mma_tf32(float* c, const unsigned* a, const unsigned* b) {
    asm volatile(
        "mma.sync.aligned.m16n8k8.row.col.f32.tf32.tf32.f32 "
        "{%0,%1,%2,%3}, {%4,%5,%6,%7}, {%8,%9}, {%0,%1,%2,%3};\n"
        : "+f"(c[0]), "+f"(c[1]), "+f"(c[2]), "+f"(c[3])
        : "r"(a[0]), "r"(a[1]), "r"(a[2]), "r"(a[3]), "r"(b[0]), "r"(b[1]));
}
__device__ __forceinline__ void mma_f16(float* c, const unsigned* a, const unsigned* b) {
    asm volatile(
        "mma.sync.aligned.m16n8k16.row.col.f32.f16.f16.f32 "
        "{%0,%1,%2,%3}, {%4,%5,%6,%7}, {%8,%9}, {%0,%1,%2,%3};\n"
        : "+f"(c[0]), "+f"(c[1]), "+f"(c[2]), "+f"(c[3])
        : "r"(a[0]), "r"(a[1]), "r"(a[2]), "r"(a[3]), "r"(b[0]), "r"(b[1]));
}
__device__ __forceinline__ void cpa16(void* dst, const void* src, bool pred) {
    unsigned daddr = (unsigned)__cvta_generic_to_shared(dst);
    int sz = pred ? 16 : 0;   // sz=0 -> 16B zero-fill (used for M/K edges)
    asm volatile("cp.async.cg.shared.global [%0], [%1], 16, %2;\n"
                 :: "r"(daddr), "l"(src), "r"(sz));
}
__device__ __forceinline__ void cpa_commit() {
    asm volatile("cp.async.commit_group;\n");
}
__device__ __forceinline__ void ldsm_x4(unsigned* r, unsigned a) {
    asm volatile("ldmatrix.sync.aligned.m8n8.x4.shared.b16 {%0,%1,%2,%3}, [%4];"
                 : "=r"(r[0]), "=r"(r[1]), "=r"(r[2]), "=r"(r[3]) : "r"(a));
}
__device__ __forceinline__ void ldsm_x4t(unsigned* r, unsigned a) {
    asm volatile("ldmatrix.sync.aligned.m8n8.x4.trans.shared.b16 {%0,%1,%2,%3}, [%4];"
                 : "=r"(r[0]), "=r"(r[1]), "=r"(r[2]), "=r"(r[3]) : "r"(a));
}

// ============================================================================
// fp16 GEMM: C[M,128] += (*undoPtr) * rowscale[m] * (op(A)[M,K] @ B[K,128]),
// atomic split-K into pre-zeroed fp32 C.
//  TRANS_A=false: A row-major [M,K] fp16 (lda = K)
//  TRANS_A=true : A stored [K,M] fp16, element (m,k) = A[k*lda+m]
// Requires: kChunk % 64 == 0, K % 32 == 0, M % 8 == 0. K edges zero-filled.
// ============================================================================
template <bool TRANS_A>
__global__ void __launch_bounds__(256, 1)
hgemm(const __half* __restrict__ A, const __half* __restrict__ B,
      float* __restrict__ C, int M, int K, int lda,
      const float* __restrict__ rowscale, const float* __restrict__ undoPtr,
      int kChunk)
{
    constexpr int APITCH = TRANS_A ? (BM + 8) : (HBK + 8);    // halves
    constexpr int ASZ = TRANS_A ? HBK * (BM + 8) : BM * (HBK + 8);
    constexpr int BPITCH = BN + 8;
    constexpr int BSZ = HBK * BPITCH;
    extern __shared__ char smraw[];
    __half* hsm = (__half*)smraw;

    const int m0 = blockIdx.x * BM;
    const int kBegin = blockIdx.y * kChunk;
    const int kEnd = min(K, kBegin + kChunk);
    if (kBegin >= K) return;
    const int kTiles = (kEnd - kBegin + HBK - 1) / HBK;

    const int tidx = threadIdx.x;
    const int lane = tidx & 31;
    const int g  = lane >> 2;
    const int tg = lane & 3;
    const int wm = (tidx >> 5) & 3;   // warp row (64 M)
    const int wn = (tidx >> 7);       // warp col (64 N)
    const int lt = lane >> 3;         // ldmatrix tile id 0..3
    const int lr = lane & 7;          // ldmatrix row in tile

    float acc[4][8][4];
#pragma unroll
    for (int mi = 0; mi < 4; mi++)
#pragma unroll
        for (int ni = 0; ni < 8; ni++)
#pragma unroll
            for (int j = 0; j < 4; j++) acc[mi][ni][j] = 0.f;

    auto load_tile = [&](int t, int stage) {
        int kt = kBegin + t * HBK;
        __half* as = hsm + stage * (ASZ + BSZ);
        __half* bs = as + ASZ;
        if (!TRANS_A) {
            // A [m][k]: 256 rows x 64 halves = 2048 x 16B chunks
#pragma unroll
            for (int i = 0; i < 8; i++) {
                int idx = tidx + i * 256;
                int m  = idx >> 3;               // 0..255
                int k8 = (idx & 7) << 3;         // 0..56
                bool p = (m0 + m < M) && (kt + k8 < kEnd);
                const __half* src = p ? &A[(size_t)(m0 + m) * lda + kt + k8] : A;
                cpa16(&as[m * APITCH + k8], src, p);
            }
        } else {
            // A [k][m]: 64 rows x 256 halves
#pragma unroll
            for (int i = 0; i < 8; i++) {
                int idx = tidx + i * 256;
                int k  = idx >> 5;               // 0..63
                int m8 = (idx & 31) << 3;        // 0..248
                int gm = m0 + m8;
                bool p = (gm < M) && (kt + k < kEnd);
                const __half* src = p ? &A[(size_t)(kt + k) * lda + gm] : A;
                cpa16(&as[k * APITCH + m8], src, p);
            }
        }
        // B [k][n]: 64 x 128 halves = 1024 chunks
#pragma unroll
        for (int i = 0; i < 4; i++) {
            int idx = tidx + i * 256;
            int k  = idx >> 4;                   // 0..63
            int n8 = (idx & 15) << 3;
            bool p = (kt + k < kEnd);
            const __half* src = p ? &B[(size_t)(kt + k) * 128 + n8] : (const __half*)B;
            cpa16(&bs[k * BPITCH + n8], src, p);
        }
        cpa_commit();
    };

    // prologue: HST-1 groups in flight
    int pre = kTiles < (HST - 1) ? kTiles : (HST - 1);
    for (int t = 0; t < pre; t++) load_tile(t, t % HST);
    for (int t = pre; t < HST - 1; t++) cpa_commit();

    unsigned smBase = (unsigned)__cvta_generic_to_shared(hsm);

    for (int t = 0; t < kTiles; t++) {
        // retire tile t; one barrier per tile (all warps done reading stage (t-1)%HST)
        asm volatile("cp.async.wait_group %0;\n" :: "n"(HST - 2));
        __syncthreads();
        if (t + HST - 1 < kTiles) load_tile(t + HST - 1, (t + HST - 1) % HST);
        else cpa_commit();

        unsigned as_u = smBase + (unsigned)((t % HST) * (ASZ + BSZ) * 2);
        unsigned bs_u = as_u + ASZ * 2;

#pragma unroll
        for (int kk = 0; kk < HBK; kk += 16) {
            unsigned af[4][4];
#pragma unroll
            for (int mi = 0; mi < 4; mi++) {
                int bm = wm * 64 + mi * 16;
                if (!TRANS_A) {
                    unsigned a = as_u + (unsigned)(((bm + (lt & 1) * 8 + lr) * APITCH
                                                   + kk + (lt >> 1) * 8) * 2);
                    ldsm_x4(af[mi], a);
                } else {
                    unsigned a = as_u + (unsigned)(((kk + (lt >> 1) * 8 + lr) * APITCH
                                                   + bm + (lt & 1) * 8) * 2);
                    ldsm_x4t(af[mi], a);
                }
            }
            unsigned bf[8][2];
#pragma unroll
            for (int nj = 0; nj < 4; nj++) {
                unsigned r[4];
                unsigned a = bs_u + (unsigned)(((kk + (lt & 1) * 8 + lr) * BPITCH
                                               + wn * 64 + nj * 16 + (lt >> 1) * 8) * 2);
                ldsm_x4t(r, a);
                bf[2 * nj    ][0] = r[0]; bf[2 * nj    ][1] = r[1];
                bf[2 * nj + 1][0] = r[2]; bf[2 * nj + 1][1] = r[3];
            }
#pragma unroll
            for (int mi = 0; mi < 4; mi++)
#pragma unroll
                for (int ni = 0; ni < 8; ni++)
                    mma_f16(acc[mi][ni], af[mi], bf[ni]);
        }
    }

    // ---- epilogue: atomic split-K with rowscale * dynamic undo-scale ----
    const float undo = *undoPtr;
#pragma unroll
    for (int mi = 0; mi < 4; mi++) {
#pragma unroll
        for (int h = 0; h < 2; h++) {
            int r = m0 + wm * 64 + mi * 16 + g + h * 8;
            if (r >= M) continue;
            float rs = rowscale[r] * undo;
#pragma unroll
            for (int ni = 0; ni < 8; ni++) {
                int cc = wn * 64 + ni * 8 + tg * 2;
                atomicAdd(&C[(size_t)r * 128 + cc    ], acc[mi][ni][h * 2 + 0] * rs);
                atomicAdd(&C[(size_t)r * 128 + cc + 1], acc[mi][ni][h * 2 + 1] * rs);
            }
        }
    }
}

// ============================================================================
// tf32 GEMM for the small K=128 GEMMs (fp32 out).
// C[m,n] = rowscale[m]*(A[M,128] @ B[128,128] + bias); rowsel gating with
// blockIdx.z selecting B/bias slabs.
// ============================================================================
__global__ void __launch_bounds__(256, 1)
gemm256(const float* __restrict__ A, const float* __restrict__ B,
        float* __restrict__ C, int M,
        const float* __restrict__ bias, const float* __restrict__ rowscale,
        const int* __restrict__ rowsel, int ldbz, int biasz)
{
    constexpr int K = 128;
    constexpr int APITCH = BK + 4;
    constexpr int ASZ = BM * APITCH;
    constexpr int BPITCH = BN + 8;
    constexpr int BSZ = BK * BPITCH;
    extern __shared__ char smraw[];
    unsigned* sm = (unsigned*)smraw;

    const int m0 = blockIdx.x * BM;
    const int zt = blockIdx.z;
    B += (size_t)zt * ldbz;
    if (bias) bias += (size_t)zt * biasz;

    const int tidx = threadIdx.x;
    const int lane = tidx & 31;
    const int g  = lane >> 2;
    const int tg = lane & 3;
    const int wm = (tidx >> 5) & 3;
    const int wn = (tidx >> 7);

    float acc[4][8][4];
#pragma unroll
    for (int mi = 0; mi < 4; mi++)
#pragma unroll
        for (int ni = 0; ni < 8; ni++)
#pragma unroll
            for (int j = 0; j < 4; j++) acc[mi][ni][j] = 0.f;

    auto load_tile = [&](int t, int stage) {
        int kt = t * BK;
        unsigned* as = sm + stage * (ASZ + BSZ);
        unsigned* bs = as + ASZ;
#pragma unroll
        for (int i = 0; i < 8; i++) {
            int idx = tidx + i * 256;
            int m  = idx >> 3;
            int k4 = (idx & 7) << 2;
            bool p = (m0 + m < M);
            const float* src = p ? &A[(size_t)(m0 + m) * K + kt + k4] : A;
            cpa16(&as[m * APITCH + k4], src, p);
        }
#pragma unroll
        for (int i = 0; i < 4; i++) {
            int idx = tidx + i * 256;
            int k  = idx >> 5;
            int n4 = (idx & 31) << 2;
            cpa16(&bs[k * BPITCH + n4], &B[(size_t)(kt + k) * 128 + n4], true);
        }
        cpa_commit();
    };

    const int kTiles = K / BK;   // 4
    int pre = kTiles < (STAGES - 1) ? kTiles : (STAGES - 1);
    for (int t = 0; t < pre; t++) load_tile(t, t % STAGES);
    for (int t = pre; t < STAGES - 1; t++) cpa_commit();

    for (int t = 0; t < kTiles; t++) {
        asm volatile("cp.async.wait_group %0;\n" :: "n"(STAGES - 2));
        __syncthreads();
        if (t + STAGES - 1 < kTiles) load_tile(t + STAGES - 1, (t + STAGES - 1) % STAGES);
        else cpa_commit();

        const unsigned* as = sm + (t % STAGES) * (ASZ + BSZ);
        const unsigned* bs = as + ASZ;

#pragma unroll
        for (int kk = 0; kk < BK; kk += 8) {
            unsigned af[4][4];
#pragma unroll
            for (int mi = 0; mi < 4; mi++) {
                int bm = wm * 64 + mi * 16;
                af[mi][0] = f2tf32(as[(bm + g    ) * APITCH + kk + tg    ]);
                af[mi][1] = f2tf32(as[(bm + g + 8) * APITCH + kk + tg    ]);
                af[mi][2] = f2tf32(as[(bm + g    ) * APITCH + kk + tg + 4]);
                af[mi][3] = f2tf32(as[(bm + g + 8) * APITCH + kk + tg + 4]);
            }
            unsigned bf[8][2];
#pragma unroll
            for (int ni = 0; ni < 8; ni++) {
                int bn = wn * 64 + ni * 8;
                bf[ni][0] = bs[(kk + tg    ) * BPITCH + bn + g];
                bf[ni][1] = bs[(kk + tg + 4) * BPITCH + bn + g];
            }
#pragma unroll
            for (int mi = 0; mi < 4; mi++)
#pragma unroll
                for (int ni = 0; ni < 8; ni++)
                    mma_tf32(acc[mi][ni], af[mi], bf[ni]);
        }
    }

#pragma unroll
    for (int mi = 0; mi < 4; mi++) {
#pragma unroll
        for (int h = 0; h < 2; h++) {
            int r = m0 + wm * 64 + mi * 16 + g + h * 8;
            if (r >= M) continue;
            if (rowsel && rowsel[r] != zt) continue;
            float rs = rowscale ? rowscale[r] : 1.f;
#pragma unroll
            for (int ni = 0; ni < 8; ni++) {
                int cc = wn * 64 + ni * 8 + tg * 2;
                float v0 = acc[mi][ni][h * 2 + 0];
                float v1 = acc[mi][ni][h * 2 + 1];
                if (bias) { v0 += bias[cc]; v1 += bias[cc + 1]; }
                C[(size_t)r * 128 + cc    ] = v0 * rs;
                C[(size_t)r * 128 + cc + 1] = v1 * rs;
            }
        }
    }
}

// ---------------- small kernels ----------------
__global__ void zero_kernel(float* __restrict__ p, int n) {
    int i = blockIdx.x * blockDim.x + threadIdx.x;
    if (i < n) p[i] = 0.f;
}
__global__ void reset_amax(unsigned* slot) { *slot = 0u; }

__global__ void absmax_kernel(const float* __restrict__ x, long long n4,
                              unsigned* __restrict__ out) {
    float m = 0.f;
    for (long long i = (long long)blockIdx.x * blockDim.x + threadIdx.x;
         i < n4; i += (long long)gridDim.x * blockDim.x) {
        float4 v = ((const float4*)x)[i];
        m = fmaxf(m, fmaxf(fmaxf(fabsf(v.x), fabsf(v.y)),
                           fmaxf(fabsf(v.z), fabsf(v.w))));
    }
#pragma unroll
    for (int o = 16; o; o >>= 1) m = fmaxf(m, __shfl_xor_sync(~0u, m, o));
    if ((threadIdx.x & 31) == 0) atomicMax(out, __float_as_uint(m));
}

// s = 2^-k so absmax*s <= 16384 (4x margin to 65504); undo = 2^k. Exact.
__global__ void make_scale(const unsigned* __restrict__ amax,
                           float* __restrict__ s, float* __restrict__ undo) {
    float m = __uint_as_float(*amax);
    int k = 0;
    if (m > 16384.f) k = (int)ceilf(log2f(m * (1.f / 16384.f)));
    if (k < 0) k = 0;
    *s = ldexpf(1.f, -k);
    *undo = ldexpf(1.f, k);
}

__global__ void f2h_dyn(__half* __restrict__ dst, const float* __restrict__ src,
                        long long n8, const float* __restrict__ sPtr) {
    float s = sPtr ? *sPtr : 1.f;
    long long i = (long long)blockIdx.x * blockDim.x + threadIdx.x;
    if (i < n8) {
        float4 a = ((const float4*)src)[2 * i];
        float4 b = ((const float4*)src)[2 * i + 1];
        __half2 h[4];
        h[0] = __floats2half2_rn(a.x * s, a.y * s);
        h[1] = __floats2half2_rn(a.z * s, a.w * s);
        h[2] = __floats2half2_rn(b.x * s, b.y * s);
        h[3] = __floats2half2_rn(b.z * s, b.w * s);
        ((uint4*)dst)[i] = *(uint4*)h;
    }
}

__global__ void round_tf32_kernel(float* __restrict__ dst, const float* __restrict__ src, int n4) {
    int i = blockIdx.x * blockDim.x + threadIdx.x;
    if (i < n4) {
        float4 v = ((const float4*)src)[i];
        v.x = roundtf(v.x); v.y = roundtf(v.y);
        v.z = roundtf(v.z); v.w = roundtf(v.w);
        ((float4*)dst)[i] = v;
    }
}

__global__ void fusion_kernel(const float* __restrict__ fw,
                              const float* __restrict__ X0,
                              const float* __restrict__ X1,
                              const float* __restrict__ X2,
                              float* __restrict__ out, int n) {
    float f0 = fw[0], f1 = fw[1], f2 = fw[2];
    float mx = fmaxf(f0, fmaxf(f1, f2));
    float e0 = expf(f0 - mx), e1 = expf(f1 - mx), e2 = expf(f2 - mx);
    float inv = 1.f / (e0 + e1 + e2);
    float w0 = e0 * inv, w1 = e1 * inv, w2 = e2 * inv;
    int i = blockIdx.x * blockDim.x + threadIdx.x;
    if (i < n) out[i] = w0 * X0[i] + w1 * X1[i] + w2 * X2[i];
}

static inline int chunk64(int K, int S) {
    int tiles = (K + HBK - 1) / HBK;
    int per = (tiles + S - 1) / S;
    return per * HBK;
}

extern "C" void kernel_launch(void* const* d_in, const int* in_sizes, int n_in,
                              void* d_out, int out_size) {
    const float* emb = (const float*)d_in[0];
    const float* Wt  = (const float*)d_in[1];
    const float* bt  = (const float*)d_in[2];
    const float* W1  = (const float*)d_in[3];
    const float* b1  = (const float*)d_in[4];
    const float* W2  = (const float*)d_in[5];
    const float* b2  = (const float*)d_in[6];
    const float* fw  = (const float*)d_in[7];
    const float* H   = (const float*)d_in[8];
    const float* dv  = (const float*)d_in[9];
    const float* de  = (const float*)d_in[10];
    const int*   tid = (const int*)d_in[11];

    const int D = in_sizes[4];          // 128
    const int N = in_sizes[9];          // 20000
    const int E = in_sizes[10];         // 8000
    const int T = in_sizes[2] / D;      // 5

    float* buf = nullptr;
    cudaGetSymbolAddress((void**)&buf, g_buf);
    __half* hb = nullptr;
    cudaGetSymbolAddress((void**)&hb, g_hbuf);
    unsigned* sc = nullptr;
    cudaGetSymbolAddress((void**)&sc, g_sc);

    size_t nd = (size_t)N * D, ed = (size_t)E * D, ne = (size_t)N * E;
    float* X0  = buf;
    float* X1  = X0 + nd;
    float* X2  = X1 + nd;
    float* Yf  = X2 + nd;
    float* Mm  = Yf + nd;
    float* Wtr = Mm + ed;
    float* W1r = Wtr + (size_t)T * D * D;
    float* W2r = W1r + (size_t)D * D;
    __half* Hh  = hb;
    __half* Yh  = Hh + ne;
    __half* Mmh = Yh + nd;

    unsigned* amaxY = sc + 0;
    float* sY = (float*)(sc + 1);
    float* uY = (float*)(sc + 2);
    unsigned* amaxM = sc + 3;
    float* sM = (float*)(sc + 4);
    float* uM = (float*)(sc + 5);

    // dynamic smem sizes
    const int smemG  = STAGES * (BM * (BK + 4) + BK * (BN + 8)) * 4;     // tf32
    const int smemHT = HST * (HBK * (BM + 8) + HBK * (BN + 8)) * 2;      // fp16 trans
    const int smemHN = HST * (BM * (HBK + 8) + HBK * (BN + 8)) * 2;      // fp16 non-trans

    // one-time setup (runs eagerly on the correctness call, before capture)
    static cudaStream_t s2 = nullptr;
    static cudaEvent_t evFork = nullptr, evHh = nullptr;
    static bool attr_done = false;
    if (!attr_done) {
        cudaFuncSetAttribute(gemm256,      cudaFuncAttributeMaxDynamicSharedMemorySize, smemG);
        cudaFuncSetAttribute(hgemm<true>,  cudaFuncAttributeMaxDynamicSharedMemorySize, smemHT);
        cudaFuncSetAttribute(hgemm<false>, cudaFuncAttributeMaxDynamicSharedMemorySize, smemHN);
        cudaStreamCreateWithFlags(&s2, cudaStreamNonBlocking);
        cudaEventCreateWithFlags(&evFork, cudaEventDisableTiming);
        cudaEventCreateWithFlags(&evHh, cudaEventDisableTiming);
        attr_done = true;
    }

    dim3 blk(256);
    int mt_n = (N + BM - 1) / BM;       // 79
    int mt_e = (E + BM - 1) / BM;       // 32
    const int S1 = 9;                   // split-K trans: 288 CTAs = ~2 clean waves
    const int S2 = 7;                   // split-K non-trans: 553 CTAs = 4 waves x 1152
    int ch1 = chunk64(N, S1);
    int ch2 = chunk64(E, S2);
    int zt_ = 256;
    const int RB = 1024;

    // ---- fork: H -> fp16 conversion (130us DRAM-bound) on side stream ----
    cudaEventRecord(evFork, 0);
    cudaStreamWaitEvent(s2, evFork, 0);
    long long h8 = (long long)(ne / 8);
    f2h_dyn<<<(int)((h8 + 255) / 256), 256, 0, s2>>>(Hh, H, h8, nullptr);
    cudaEventRecord(evHh, s2);

    // ---- main chain (overlapped with H conversion) ----
    int wt_n4 = T * D * D / 4, w_n4 = D * D / 4;
    round_tf32_kernel<<<(wt_n4 + 255) / 256, 256>>>(Wtr, Wt, wt_n4);
    round_tf32_kernel<<<(w_n4 + 255) / 256, 256>>>(W1r, W1, w_n4);
    round_tf32_kernel<<<(w_n4 + 255) / 256, 256>>>(W2r, W2, w_n4);

    // X0: per-type projection with fused type-select
    gemm256<<<dim3(mt_n, 1, T), blk, smemG>>>(
        emb, Wtr, X0, N, bt, nullptr, tid, D * D, D);

    bool joined = false;
    for (int layer = 0; layer < 2; layer++) {
        const float* Xin = (layer == 0) ? X0 : X1;
        float* Xout      = (layer == 0) ? X1 : X2;
        const float* W   = (layer == 0) ? W1r : W2r;
        const float* b   = (layer == 0) ? b1 : b2;

        // Yf = dv * (Xin @ W + b)
        gemm256<<<dim3(mt_n, 1, 1), blk, smemG>>>(
            Xin, W, Yf, N, b, dv, nullptr, 0, 0);
        // dynamic scale + convert Y
        reset_amax<<<1, 1>>>(amaxY);
        absmax_kernel<<<RB, 256>>>(Yf, (long long)(nd / 4), amaxY);
        make_scale<<<1, 1>>>(amaxY, sY, uY);
        f2h_dyn<<<(int)((nd / 8 + 255) / 256), 256>>>(Yh, Yf, (long long)(nd / 8), sY);
        // Mm = de * (Hh^T @ Yh) * undoY  (join with H conversion before 1st use)
        zero_kernel<<<(int)((ed + zt_ - 1) / zt_), zt_>>>(Mm, (int)ed);
        if (!joined) { cudaStreamWaitEvent(0, evHh, 0); joined = true; }
        hgemm<true><<<dim3(mt_e, S1, 1), blk, smemHT>>>(Hh, Yh, Mm, E, N, E, de, uY, ch1);
        // dynamic scale + convert Mm
        reset_amax<<<1, 1>>>(amaxM);
        absmax_kernel<<<RB, 256>>>(Mm, (long long)(ed / 4), amaxM);
        make_scale<<<1, 1>>>(amaxM, sM, uM);
        f2h_dyn<<<(int)((ed / 8 + 255) / 256), 256>>>(Mmh, Mm, (long long)(ed / 8), sM);
        // Xout = dv * (Hh @ Mmh) * undoM
        zero_kernel<<<(int)((nd + zt_ - 1) / zt_), zt_>>>(Xout, (int)nd);
        hgemm<false><<<dim3(mt_n, S2, 1), blk, smemHN>>>(Hh, Mmh, Xout, N, E, E, dv, uM, ch2);
    }

    // ---- fusion ----
    fusion_kernel<<<(int)((nd + zt_ - 1) / zt_), zt_>>>(
        fw, X0, X1, X2, (float*)d_out, (int)nd);
}

// round 13
// speedup vs baseline: 2.8296x; 1.0567x over previous
#include <cuda_runtime.h>
#include <cuda_fp16.h>
#include <math.h>

// ----------------------------------------------------------------------------
// HyperGraphModel on GB300.
//  - 4 big H-GEMMs in fp16 (HMMA m16n8k16, fp32 accum, ldmatrix fragments,
//    3-stage BK=64 cp.async pipeline, ONE barrier per k-tile).
//    CTA tile 128x128 -> 2 CTAs/SM (16 warps) for latency hiding.
//  - fp16 intermediates use DYNAMIC power-of-2 scaling (absmax -> 2^-k,
//    undone in consuming epilogue; exponent-only => exact).
//  - small D x D GEMMs stay tf32 mma.sync (pre-rounded B weights).
//  - H->fp16 conversion runs on a forked side stream, overlapped with the
//    pre-hgemm chain.
//  NOTE: tcgen05 is NOT available — this toolchain's ptxas targets sm_103
//  (no 'a'), which rejects all tcgen05 instructions (verified round 12).
// ----------------------------------------------------------------------------

#define BM 256           // tf32 kernel M tile
#define BK 32            // tf32 kernel k-tile
#define HBM 128          // fp16 kernel M tile (2 CTAs/SM)
#define HBK 64           // fp16 kernel k-tile
#define STAGES 3         // tf32 stages
#define HST 3            // fp16 stages

// fp32 scratch: X0,X1,X2,Yf (4*N*D) + Mm (E*D) + Wtr + W1r + W2r
__device__ float g_buf[11400000];
// fp16 scratch: Hh (N*E) + Yh (N*D) + Mmh (E*D)
__device__ __align__(256) __half g_hbuf[163600000];
// scale slots: [0]=amaxY bits, [1]=sY, [2]=uY, [3]=amaxM, [4]=sM, [5]=uM
__device__ unsigned g_sc[8];

// ---------------- common helpers ----------------
__device__ __forceinline__ unsigned f2tf32(unsigned x) {
    unsigned r;
    asm("cvt.rna.tf32.f32 %0, %1;" : "=r"(r) : "r"(x));
    return r;
}
__device__ __forceinline__ float roundtf(float x) {
    return __uint_as_float(f2tf32(__float_as_uint(x)));
}
__device__ __forceinline__ void mma_tf32(float* c, const unsigned* a, const unsigned* b) {
    asm volatile(
        "mma.sync.aligned.m16n8k8.row.col.f32.tf32.tf32.f32 "
        "{%0,%1,%2,%3}, {%4,%5,%6,%7}, {%8,%9}, {%0,%1,%2,%3};\n"
        : "+f"(c[0]), "+f"(c[1]), "+f"(c[2]), "+f"(c[3])
        : "r"(a[0]), "r"(a[1]), "r"(a[2]), "r"(a[3]), "r"(b[0]), "r"(b[1]));
}
__device__ __forceinline__ void mma_f16(float* c, const unsigned* a, const unsigned* b) {
    asm volatile(
        "mma.sync.aligned.m16n8k16.row.col.f32.f16.f16.f32 "
        "{%0,%1,%2,%3}, {%4,%5,%6,%7}, {%8,%9}, {%0,%1,%2,%3};\n"
        : "+f"(c[0]), "+f"(c[1]), "+f"(c[2]), "+f"(c[3])
        : "r"(a[0]), "r"(a[1]), "r"(a[2]), "r"(a[3]), "r"(b[0]), "r"(b[1]));
}
__device__ __forceinline__ void cpa16(void* dst, const void* src, bool pred) {
    unsigned daddr = (unsigned)__cvta_generic_to_shared(dst);
    int sz = pred ? 16 : 0;   // sz=0 -> 16B zero-fill (M/K edges)
    asm volatile("cp.async.cg.shared.global [%0], [%1], 16, %2;\n"
                 :: "r"(daddr), "l"(src), "r"(sz));
}
__device__ __forceinline__ void cpa_commit() {
    asm volatile("cp.async.commit_group;\n");
}
__device__ __forceinline__ void ldsm_x4(unsigned* r, unsigned a) {
    asm volatile("ldmatrix.sync.aligned.m8n8.x4.shared.b16 {%0,%1,%2,%3}, [%4];"
                 : "=r"(r[0]), "=r"(r[1]), "=r"(r[2]), "=r"(r[3]) : "r"(a));
}
__device__ __forceinline__ void ldsm_x4t(unsigned* r, unsigned a) {
    asm volatile("ldmatrix.sync.aligned.m8n8.x4.trans.shared.b16 {%0,%1,%2,%3}, [%4];"
                 : "=r"(r[0]), "=r"(r[1]), "=r"(r[2]), "=r"(r[3]) : "r"(a));
}

// ============================================================================
// fp16 GEMM: C[M,128] += (*undoPtr) * rowscale[m] * (op(A)[M,K] @ B[K,128]),
// atomic split-K into pre-zeroed fp32 C.
//  TRANS_A=false: A row-major [M,K] fp16 (lda = K)
//  TRANS_A=true : A stored [K,M] fp16, element (m,k) = A[k*lda+m]
// CTA tile 128x128x64, 8 warps (warp 32x64), 2 CTAs/SM, 3-stage cp.async.
// Requires: kChunk % 64 == 0, K % 32 == 0, M % 8 == 0. K edges zero-filled.
// ============================================================================
template <bool TRANS_A>
__global__ void __launch_bounds__(256, 2)
hgemm(const __half* __restrict__ A, const __half* __restrict__ B,
      float* __restrict__ C, int M, int K, int lda,
      const float* __restrict__ rowscale, const float* __restrict__ undoPtr,
      int kChunk)
{
    constexpr int APITCH = TRANS_A ? (HBM + 8) : (HBK + 8);   // halves
    constexpr int ASZ = TRANS_A ? HBK * (HBM + 8) : HBM * (HBK + 8);
    constexpr int BPITCH = 128 + 8;
    constexpr int BSZ = HBK * BPITCH;
    extern __shared__ char smraw[];
    __half* hsm = (__half*)smraw;

    const int m0 = blockIdx.x * HBM;
    const int kBegin = blockIdx.y * kChunk;
    const int kEnd = min(K, kBegin + kChunk);
    if (kBegin >= K) return;
    const int kTiles = (kEnd - kBegin + HBK - 1) / HBK;

    const int tidx = threadIdx.x;
    const int lane = tidx & 31;
    const int g  = lane >> 2;
    const int tg = lane & 3;
    const int wm = (tidx >> 5) & 3;   // warp row (32 M)
    const int wn = (tidx >> 7);       // warp col (64 N)
    const int lt = lane >> 3;         // ldmatrix tile id 0..3
    const int lr = lane & 7;          // ldmatrix row in tile

    float acc[2][8][4];
#pragma unroll
    for (int mi = 0; mi < 2; mi++)
#pragma unroll
        for (int ni = 0; ni < 8; ni++)
#pragma unroll
            for (int j = 0; j < 4; j++) acc[mi][ni][j] = 0.f;

    auto load_tile = [&](int t, int stage) {
        int kt = kBegin + t * HBK;
        __half* as = hsm + stage * (ASZ + BSZ);
        __half* bs = as + ASZ;
        if (!TRANS_A) {
            // A [m][k]: 128 rows x 64 halves = 1024 x 16B chunks
#pragma unroll
            for (int i = 0; i < 4; i++) {
                int idx = tidx + i * 256;
                int m  = idx >> 3;               // 0..127
                int k8 = (idx & 7) << 3;         // 0..56
                bool p = (m0 + m < M) && (kt + k8 < kEnd);
                const __half* src = p ? &A[(size_t)(m0 + m) * lda + kt + k8] : A;
                cpa16(&as[m * APITCH + k8], src, p);
            }
        } else {
            // A [k][m]: 64 rows x 128 halves = 1024 chunks
#pragma unroll
            for (int i = 0; i < 4; i++) {
                int idx = tidx + i * 256;
                int k  = idx >> 4;               // 0..63
                int m8 = (idx & 15) << 3;        // 0..120
                int gm = m0 + m8;
                bool p = (gm < M) && (kt + k < kEnd);
                const __half* src = p ? &A[(size_t)(kt + k) * lda + gm] : A;
                cpa16(&as[k * APITCH + m8], src, p);
            }
        }
        // B [k][n]: 64 x 128 halves = 1024 chunks
#pragma unroll
        for (int i = 0; i < 4; i++) {
            int idx = tidx + i * 256;
            int k  = idx >> 4;                   // 0..63
            int n8 = (idx & 15) << 3;
            bool p = (kt + k < kEnd);
            const __half* src = p ? &B[(size_t)(kt + k) * 128 + n8] : (const __half*)B;
            cpa16(&bs[k * BPITCH + n8], src, p);
        }
        cpa_commit();
    };

    int pre = kTiles < (HST - 1) ? kTiles : (HST - 1);
    for (int t = 0; t < pre; t++) load_tile(t, t % HST);
    for (int t = pre; t < HST - 1; t++) cpa_commit();

    unsigned smBase = (unsigned)__cvta_generic_to_shared(hsm);

    for (int t = 0; t < kTiles; t++) {
        // retire tile t; one barrier per tile
        asm volatile("cp.async.wait_group %0;\n" :: "n"(HST - 2));
        __syncthreads();
        if (t + HST - 1 < kTiles) load_tile(t + HST - 1, (t + HST - 1) % HST);
        else cpa_commit();

        unsigned as_u = smBase + (unsigned)((t % HST) * (ASZ + BSZ) * 2);
        unsigned bs_u = as_u + ASZ * 2;

#pragma unroll
        for (int kk = 0; kk < HBK; kk += 16) {
            unsigned af[2][4];
#pragma unroll
            for (int mi = 0; mi < 2; mi++) {
                int bm = wm * 32 + mi * 16;
                if (!TRANS_A) {
                    unsigned a = as_u + (unsigned)(((bm + (lt & 1) * 8 + lr) * APITCH
                                                   + kk + (lt >> 1) * 8) * 2);
                    ldsm_x4(af[mi], a);
                } else {
                    unsigned a = as_u + (unsigned)(((kk + (lt >> 1) * 8 + lr) * APITCH
                                                   + bm + (lt & 1) * 8) * 2);
                    ldsm_x4t(af[mi], a);
                }
            }
            unsigned bf[8][2];
#pragma unroll
            for (int nj = 0; nj < 4; nj++) {
                unsigned r[4];
                unsigned a = bs_u + (unsigned)(((kk + (lt & 1) * 8 + lr) * BPITCH
                                               + wn * 64 + nj * 16 + (lt >> 1) * 8) * 2);
                ldsm_x4t(r, a);
                bf[2 * nj    ][0] = r[0]; bf[2 * nj    ][1] = r[1];
                bf[2 * nj + 1][0] = r[2]; bf[2 * nj + 1][1] = r[3];
            }
#pragma unroll
            for (int mi = 0; mi < 2; mi++)
#pragma unroll
                for (int ni = 0; ni < 8; ni++)
                    mma_f16(acc[mi][ni], af[mi], bf[ni]);
        }
    }

    // ---- epilogue: atomic split-K with rowscale * dynamic undo-scale ----
    const float undo = *undoPtr;
#pragma unroll
    for (int mi = 0; mi < 2; mi++) {
#pragma unroll
        for (int h = 0; h < 2; h++) {
            int r = m0 + wm * 32 + mi * 16 + g + h * 8;
            if (r >= M) continue;
            float rs = rowscale[r] * undo;
#pragma unroll
            for (int ni = 0; ni < 8; ni++) {
                int cc = wn * 64 + ni * 8 + tg * 2;
                atomicAdd(&C[(size_t)r * 128 + cc    ], acc[mi][ni][h * 2 + 0] * rs);
                atomicAdd(&C[(size_t)r * 128 + cc + 1], acc[mi][ni][h * 2 + 1] * rs);
            }
        }
    }
}

// ============================================================================
// tf32 GEMM for the small K=128 GEMMs (fp32 out). Unchanged from round 10.
// ============================================================================
__global__ void __launch_bounds__(256, 1)
gemm256(const float* __restrict__ A, const float* __restrict__ B,
        float* __restrict__ C, int M,
        const float* __restrict__ bias, const float* __restrict__ rowscale,
        const int* __restrict__ rowsel, int ldbz, int biasz)
{
    constexpr int K = 128;
    constexpr int APITCH = BK + 4;
    constexpr int ASZ = BM * APITCH;
    constexpr int BPITCH = 128 + 8;
    constexpr int BSZ = BK * BPITCH;
    extern __shared__ char smraw[];
    unsigned* sm = (unsigned*)smraw;

    const int m0 = blockIdx.x * BM;
    const int zt = blockIdx.z;
    B += (size_t)zt * ldbz;
    if (bias) bias += (size_t)zt * biasz;

    const int tidx = threadIdx.x;
    const int lane = tidx & 31;
    const int g  = lane >> 2;
    const int tg = lane & 3;
    const int wm = (tidx >> 5) & 3;
    const int wn = (tidx >> 7);

    float acc[4][8][4];
#pragma unroll
    for (int mi = 0; mi < 4; mi++)
#pragma unroll
        for (int ni = 0; ni < 8; ni++)
#pragma unroll
            for (int j = 0; j < 4; j++) acc[mi][ni][j] = 0.f;

    auto load_tile = [&](int t, int stage) {
        int kt = t * BK;
        unsigned* as = sm + stage * (ASZ + BSZ);
        unsigned* bs = as + ASZ;
#pragma unroll
        for (int i = 0; i < 8; i++) {
            int idx = tidx + i * 256;
            int m  = idx >> 3;
            int k4 = (idx & 7) << 2;
            bool p = (m0 + m < M);
            const float* src = p ? &A[(size_t)(m0 + m) * K + kt + k4] : A;
            cpa16(&as[m * APITCH + k4], src, p);
        }
#pragma unroll
        for (int i = 0; i < 4; i++) {
            int idx = tidx + i * 256;
            int k  = idx >> 5;
            int n4 = (idx & 31) << 2;
            cpa16(&bs[k * BPITCH + n4], &B[(size_t)(kt + k) * 128 + n4], true);
        }
        cpa_commit();
    };

    const int kTiles = K / BK;
    int pre = kTiles < (STAGES - 1) ? kTiles : (STAGES - 1);
    for (int t = 0; t < pre; t++) load_tile(t, t % STAGES);
    for (int t = pre; t < STAGES - 1; t++) cpa_commit();

    for (int t = 0; t < kTiles; t++) {
        asm volatile("cp.async.wait_group %0;\n" :: "n"(STAGES - 2));
        __syncthreads();
        if (t + STAGES - 1 < kTiles) load_tile(t + STAGES - 1, (t + STAGES - 1) % STAGES);
        else cpa_commit();

        const unsigned* as = sm + (t % STAGES) * (ASZ + BSZ);
        const unsigned* bs = as + ASZ;

#pragma unroll
        for (int kk = 0; kk < BK; kk += 8) {
            unsigned af[4][4];
#pragma unroll
            for (int mi = 0; mi < 4; mi++) {
                int bm = wm * 64 + mi * 16;
                af[mi][0] = f2tf32(as[(bm + g    ) * APITCH + kk + tg    ]);
                af[mi][1] = f2tf32(as[(bm + g + 8) * APITCH + kk + tg    ]);
                af[mi][2] = f2tf32(as[(bm + g    ) * APITCH + kk + tg + 4]);
                af[mi][3] = f2tf32(as[(bm + g + 8) * APITCH + kk + tg + 4]);
            }
            unsigned bf[8][2];
#pragma unroll
            for (int ni = 0; ni < 8; ni++) {
                int bn = wn * 64 + ni * 8;
                bf[ni][0] = bs[(kk + tg    ) * BPITCH + bn + g];
                bf[ni][1] = bs[(kk + tg + 4) * BPITCH + bn + g];
            }
#pragma unroll
            for (int mi = 0; mi < 4; mi++)
#pragma unroll
                for (int ni = 0; ni < 8; ni++)
                    mma_tf32(acc[mi][ni], af[mi], bf[ni]);
        }
    }

#pragma unroll
    for (int mi = 0; mi < 4; mi++) {
#pragma unroll
        for (int h = 0; h < 2; h++) {
            int r = m0 + wm * 64 + mi * 16 + g + h * 8;
            if (r >= M) continue;
            if (rowsel && rowsel[r] != zt) continue;
            float rs = rowscale ? rowscale[r] : 1.f;
#pragma unroll
            for (int ni = 0; ni < 8; ni++) {
                int cc = wn * 64 + ni * 8 + tg * 2;
                float v0 = acc[mi][ni][h * 2 + 0];
                float v1 = acc[mi][ni][h * 2 + 1];
                if (bias) { v0 += bias[cc]; v1 += bias[cc + 1]; }
                C[(size_t)r * 128 + cc    ] = v0 * rs;
                C[(size_t)r * 128 + cc + 1] = v1 * rs;
            }
        }
    }
}

// ---------------- small kernels ----------------
__global__ void zero_kernel(float* __restrict__ p, int n) {
    int i = blockIdx.x * blockDim.x + threadIdx.x;
    if (i < n) p[i] = 0.f;
}
__global__ void reset_amax(unsigned* slot) { *slot = 0u; }

__global__ void absmax_kernel(const float* __restrict__ x, long long n4,
                              unsigned* __restrict__ out) {
    float m = 0.f;
    for (long long i = (long long)blockIdx.x * blockDim.x + threadIdx.x;
         i < n4; i += (long long)gridDim.x * blockDim.x) {
        float4 v = ((const float4*)x)[i];
        m = fmaxf(m, fmaxf(fmaxf(fabsf(v.x), fabsf(v.y)),
                           fmaxf(fabsf(v.z), fabsf(v.w))));
    }
#pragma unroll
    for (int o = 16; o; o >>= 1) m = fmaxf(m, __shfl_xor_sync(~0u, m, o));
    if ((threadIdx.x & 31) == 0) atomicMax(out, __float_as_uint(m));
}

__global__ void make_scale(const unsigned* __restrict__ amax,
                           float* __restrict__ s, float* __restrict__ undo) {
    float m = __uint_as_float(*amax);
    int k = 0;
    if (m > 16384.f) k = (int)ceilf(log2f(m * (1.f / 16384.f)));
    if (k < 0) k = 0;
    *s = ldexpf(1.f, -k);
    *undo = ldexpf(1.f, k);
}

__global__ void f2h_dyn(__half* __restrict__ dst, const float* __restrict__ src,
                        long long n8, const float* __restrict__ sPtr) {
    float s = sPtr ? *sPtr : 1.f;
    long long i = (long long)blockIdx.x * blockDim.x + threadIdx.x;
    if (i < n8) {
        float4 a = ((const float4*)src)[2 * i];
        float4 b = ((const float4*)src)[2 * i + 1];
        __half2 h[4];
        h[0] = __floats2half2_rn(a.x * s, a.y * s);
        h[1] = __floats2half2_rn(a.z * s, a.w * s);
        h[2] = __floats2half2_rn(b.x * s, b.y * s);
        h[3] = __floats2half2_rn(b.z * s, b.w * s);
        ((uint4*)dst)[i] = *(uint4*)h;
    }
}

__global__ void round_tf32_kernel(float* __restrict__ dst, const float* __restrict__ src, int n4) {
    int i = blockIdx.x * blockDim.x + threadIdx.x;
    if (i < n4) {
        float4 v = ((const float4*)src)[i];
        v.x = roundtf(v.x); v.y = roundtf(v.y);
        v.z = roundtf(v.z); v.w = roundtf(v.w);
        ((float4*)dst)[i] = v;
    }
}

__global__ void fusion_kernel(const float* __restrict__ fw,
                              const float* __restrict__ X0,
                              const float* __restrict__ X1,
                              const float* __restrict__ X2,
                              float* __restrict__ out, int n) {
    float f0 = fw[0], f1 = fw[1], f2 = fw[2];
    float mx = fmaxf(f0, fmaxf(f1, f2));
    float e0 = expf(f0 - mx), e1 = expf(f1 - mx), e2 = expf(f2 - mx);
    float inv = 1.f / (e0 + e1 + e2);
    float w0 = e0 * inv, w1 = e1 * inv, w2 = e2 * inv;
    int i = blockIdx.x * blockDim.x + threadIdx.x;
    if (i < n) out[i] = w0 * X0[i] + w1 * X1[i] + w2 * X2[i];
}

static inline int chunk64(int K, int S) {
    int tiles = (K + HBK - 1) / HBK;
    int per = (tiles + S - 1) / S;
    return per * HBK;
}

extern "C" void kernel_launch(void* const* d_in, const int* in_sizes, int n_in,
                              void* d_out, int out_size) {
    const float* emb = (const float*)d_in[0];
    const float* Wt  = (const float*)d_in[1];
    const float* bt  = (const float*)d_in[2];
    const float* W1  = (const float*)d_in[3];
    const float* b1  = (const float*)d_in[4];
    const float* W2  = (const float*)d_in[5];
    const float* b2  = (const float*)d_in[6];
    const float* fw  = (const float*)d_in[7];
    const float* H   = (const float*)d_in[8];
    const float* dv  = (const float*)d_in[9];
    const float* de  = (const float*)d_in[10];
    const int*   tid = (const int*)d_in[11];

    const int D = in_sizes[4];          // 128
    const int N = in_sizes[9];          // 20000
    const int E = in_sizes[10];         // 8000
    const int T = in_sizes[2] / D;      // 5

    float* buf = nullptr;
    cudaGetSymbolAddress((void**)&buf, g_buf);
    __half* hb = nullptr;
    cudaGetSymbolAddress((void**)&hb, g_hbuf);
    unsigned* sc = nullptr;
    cudaGetSymbolAddress((void**)&sc, g_sc);

    size_t nd = (size_t)N * D, ed = (size_t)E * D, ne = (size_t)N * E;
    float* X0  = buf;
    float* X1  = X0 + nd;
    float* X2  = X1 + nd;
    float* Yf  = X2 + nd;
    float* Mm  = Yf + nd;
    float* Wtr = Mm + ed;
    float* W1r = Wtr + (size_t)T * D * D;
    float* W2r = W1r + (size_t)D * D;
    __half* Hh  = hb;
    __half* Yh  = Hh + ne;
    __half* Mmh = Yh + nd;

    unsigned* amaxY = sc + 0;
    float* sY = (float*)(sc + 1);
    float* uY = (float*)(sc + 2);
    unsigned* amaxM = sc + 3;
    float* sM = (float*)(sc + 4);
    float* uM = (float*)(sc + 5);

    // dynamic smem sizes
    const int smemG  = STAGES * (BM * (BK + 4) + BK * (128 + 8)) * 4;      // tf32
    const int smemHT = HST * (HBK * (HBM + 8) + HBK * (128 + 8)) * 2;      // fp16 trans
    const int smemHN = HST * (HBM * (HBK + 8) + HBK * (128 + 8)) * 2;      // fp16 non-trans

    static cudaStream_t s2 = nullptr;
    static cudaEvent_t evFork = nullptr, evHh = nullptr;
    static bool attr_done = false;
    if (!attr_done) {
        cudaFuncSetAttribute(gemm256,      cudaFuncAttributeMaxDynamicSharedMemorySize, smemG);
        cudaFuncSetAttribute(hgemm<true>,  cudaFuncAttributeMaxDynamicSharedMemorySize, smemHT);
        cudaFuncSetAttribute(hgemm<false>, cudaFuncAttributeMaxDynamicSharedMemorySize, smemHN);
        cudaStreamCreateWithFlags(&s2, cudaStreamNonBlocking);
        cudaEventCreateWithFlags(&evFork, cudaEventDisableTiming);
        cudaEventCreateWithFlags(&evHh, cudaEventDisableTiming);
        attr_done = true;
    }

    dim3 blk(256);
    int mt_n  = (N + BM - 1) / BM;      // 79 (tf32)
    int ht_n  = (N + HBM - 1) / HBM;    // 157 (fp16 non-trans M tiles)
    int ht_e  = (E + HBM - 1) / HBM;    // 63 (fp16 trans M tiles)
    const int S1 = 9;                   // trans split-K: 567 CTAs ~ 1.9 waves of 592
    const int S2 = 7;                   // non-trans: 1099 CTAs ~ 3.7 waves, 18 tiles/CTA
    int ch1 = chunk64(N, S1);
    int ch2 = chunk64(E, S2);
    int zt_ = 256;
    const int RB = 1024;

    // ---- fork: H -> fp16 conversion on side stream ----
    cudaEventRecord(evFork, 0);
    cudaStreamWaitEvent(s2, evFork, 0);
    long long h8 = (long long)(ne / 8);
    f2h_dyn<<<(int)((h8 + 255) / 256), 256, 0, s2>>>(Hh, H, h8, nullptr);
    cudaEventRecord(evHh, s2);

    // ---- main chain (overlapped with H conversion) ----
    int wt_n4 = T * D * D / 4, w_n4 = D * D / 4;
    round_tf32_kernel<<<(wt_n4 + 255) / 256, 256>>>(Wtr, Wt, wt_n4);
    round_tf32_kernel<<<(w_n4 + 255) / 256, 256>>>(W1r, W1, w_n4);
    round_tf32_kernel<<<(w_n4 + 255) / 256, 256>>>(W2r, W2, w_n4);

    gemm256<<<dim3(mt_n, 1, T), blk, smemG>>>(
        emb, Wtr, X0, N, bt, nullptr, tid, D * D, D);

    bool joined = false;
    for (int layer = 0; layer < 2; layer++) {
        const float* Xin = (layer == 0) ? X0 : X1;
        float* Xout      = (layer == 0) ? X1 : X2;
        const float* W   = (layer == 0) ? W1r : W2r;
        const float* b   = (layer == 0) ? b1 : b2;

        // Yf = dv * (Xin @ W + b)
        gemm256<<<dim3(mt_n, 1, 1), blk, smemG>>>(
            Xin, W, Yf, N, b, dv, nullptr, 0, 0);
        // dynamic scale + convert Y
        reset_amax<<<1, 1>>>(amaxY);
        absmax_kernel<<<RB, 256>>>(Yf, (long long)(nd / 4), amaxY);
        make_scale<<<1, 1>>>(amaxY, sY, uY);
        f2h_dyn<<<(int)((nd / 8 + 255) / 256), 256>>>(Yh, Yf, (long long)(nd / 8), sY);
        // Mm = de * (Hh^T @ Yh) * undoY  (join with H conversion before 1st use)
        zero_kernel<<<(int)((ed + zt_ - 1) / zt_), zt_>>>(Mm, (int)ed);
        if (!joined) { cudaStreamWaitEvent(0, evHh, 0); joined = true; }
        hgemm<true><<<dim3(ht_e, S1, 1), blk, smemHT>>>(Hh, Yh, Mm, E, N, E, de, uY, ch1);
        // dynamic scale + convert Mm
        reset_amax<<<1, 1>>>(amaxM);
        absmax_kernel<<<RB, 256>>>(Mm, (long long)(ed / 4), amaxM);
        make_scale<<<1, 1>>>(amaxM, sM, uM);
        f2h_dyn<<<(int)((ed / 8 + 255) / 256), 256>>>(Mmh, Mm, (long long)(ed / 8), sM);
        // Xout = dv * (Hh @ Mmh) * undoM
        zero_kernel<<<(int)((nd + zt_ - 1) / zt_), zt_>>>(Xout, (int)nd);
        hgemm<false><<<dim3(ht_n, S2, 1), blk, smemHN>>>(Hh, Mmh, Xout, N, E, E, dv, uM, ch2);
    }

    // ---- fusion ----
    fusion_kernel<<<(int)((nd + zt_ - 1) / zt_), zt_>>>(
        fw, X0, X1, X2, (float*)d_out, (int)nd);
}

// round 14
// speedup vs baseline: 2.8968x; 1.0238x over previous
#include <cuda_runtime.h>
#include <cuda_fp16.h>
#include <math.h>

// ----------------------------------------------------------------------------
// HyperGraphModel on GB300.
//  - 4 big H-GEMMs in fp16 (HMMA m16n8k16, fp32 accum, ldmatrix fragments,
//    3-stage BK=64 cp.async pipeline, ONE barrier per k-tile, 2 CTAs/SM).
//  - fp16 intermediates use DYNAMIC power-of-2 scaling. absmax is FUSED into
//    the producing GEMM epilogue; consumers (f2h / hgemm) derive the scale
//    from the raw amax bits in-kernel (identical deterministic formula) —
//    no make_scale launches.
//  - independent prep (weight rounding, zero-fills, amax resets, H->fp16)
//    runs on a forked side stream, joined before the first hgemm.
//  NOTE: tcgen05 unavailable — ptxas here targets sm_103 (no 'a'), verified
//  round 12.
// ----------------------------------------------------------------------------

#define BM 256           // tf32 kernel M tile
#define BK 32            // tf32 kernel k-tile
#define HBM 128          // fp16 kernel M tile (2 CTAs/SM)
#define HBK 64           // fp16 kernel k-tile
#define STAGES 3         // tf32 stages
#define HST 3            // fp16 stages

// fp32 scratch: X0,X1,X2,Yf (4*N*D) + Mm (E*D) + Wtr + W1r + W2r
__device__ float g_buf[11400000];
// fp16 scratch: Hh (N*E) + Yh (N*D) + Mmh (E*D)
__device__ __align__(256) __half g_hbuf[163600000];
// scale slots: [0]=amaxY bits, [1]=amaxM bits
__device__ unsigned g_sc[8];

// ---------------- common helpers ----------------
__device__ __forceinline__ unsigned f2tf32(unsigned x) {
    unsigned r;
    asm("cvt.rna.tf32.f32 %0, %1;" : "=r"(r) : "r"(x));
    return r;
}
__device__ __forceinline__ float roundtf(float x) {
    return __uint_as_float(f2tf32(__float_as_uint(x)));
}
// scale exponent from raw amax bits: k such that amax*2^-k <= 16384 (4x margin)
__device__ __forceinline__ int amax_k(const unsigned* amaxPtr) {
    float m = __uint_as_float(*amaxPtr);
    int k = 0;
    if (m > 16384.f) k = (int)ceilf(log2f(m * (1.f / 16384.f)));
    if (k < 0) k = 0;
    return k;
}
__device__ __forceinline__ void mma_tf32(float* c, const unsigned* a, const unsigned* b) {
    asm volatile(
        "mma.sync.aligned.m16n8k8.row.col.f32.tf32.tf32.f32 "
        "{%0,%1,%2,%3}, {%4,%5,%6,%7}, {%8,%9}, {%0,%1,%2,%3};\n"
        : "+f"(c[0]), "+f"(c[1]), "+f"(c[2]), "+f"(c[3])
        : "r"(a[0]), "r"(a[1]), "r"(a[2]), "r"(a[3]), "r"(b[0]), "r"(b[1]));
}
__device__ __forceinline__ void mma_f16(float* c, const unsigned* a, const unsigned* b) {
    asm volatile(
        "mma.sync.aligned.m16n8k16.row.col.f32.f16.f16.f32 "
        "{%0,%1,%2,%3}, {%4,%5,%6,%7}, {%8,%9}, {%0,%1,%2,%3};\n"
        : "+f"(c[0]), "+f"(c[1]), "+f"(c[2]), "+f"(c[3])
        : "r"(a[0]), "r"(a[1]), "r"(a[2]), "r"(a[3]), "r"(b[0]), "r"(b[1]));
}
__device__ __forceinline__ void cpa16(void* dst, const void* src, bool pred) {
    unsigned daddr = (unsigned)__cvta_generic_to_shared(dst);
    int sz = pred ? 16 : 0;   // sz=0 -> 16B zero-fill (M/K edges)
    asm volatile("cp.async.cg.shared.global [%0], [%1], 16, %2;\n"
                 :: "r"(daddr), "l"(src), "r"(sz));
}
__device__ __forceinline__ void cpa_commit() {
    asm volatile("cp.async.commit_group;\n");
}
__device__ __forceinline__ void ldsm_x4(unsigned* r, unsigned a) {
    asm volatile("ldmatrix.sync.aligned.m8n8.x4.shared.b16 {%0,%1,%2,%3}, [%4];"
                 : "=r"(r[0]), "=r"(r[1]), "=r"(r[2]), "=r"(r[3]) : "r"(a));
}
__device__ __forceinline__ void ldsm_x4t(unsigned* r, unsigned a) {
    asm volatile("ldmatrix.sync.aligned.m8n8.x4.trans.shared.b16 {%0,%1,%2,%3}, [%4];"
                 : "=r"(r[0]), "=r"(r[1]), "=r"(r[2]), "=r"(r[3]) : "r"(a));
}

// ============================================================================
// fp16 GEMM: C[M,128] += 2^k(amax) * rowscale[m] * (op(A)[M,K] @ B[K,128]),
// atomic split-K into pre-zeroed fp32 C.
//  TRANS_A=false: A row-major [M,K] fp16 (lda = K)
//  TRANS_A=true : A stored [K,M] fp16, element (m,k) = A[k*lda+m]
// CTA tile 128x128x64, 8 warps (warp 32x64), 2 CTAs/SM, 3-stage cp.async.
// ============================================================================
template <bool TRANS_A>
__global__ void __launch_bounds__(256, 2)
hgemm(const __half* __restrict__ A, const __half* __restrict__ B,
      float* __restrict__ C, int M, int K, int lda,
      const float* __restrict__ rowscale, const unsigned* __restrict__ amaxPtr,
      int kChunk)
{
    constexpr int APITCH = TRANS_A ? (HBM + 8) : (HBK + 8);   // halves
    constexpr int ASZ = TRANS_A ? HBK * (HBM + 8) : HBM * (HBK + 8);
    constexpr int BPITCH = 128 + 8;
    constexpr int BSZ = HBK * BPITCH;
    extern __shared__ char smraw[];
    __half* hsm = (__half*)smraw;

    const int m0 = blockIdx.x * HBM;
    const int kBegin = blockIdx.y * kChunk;
    const int kEnd = min(K, kBegin + kChunk);
    if (kBegin >= K) return;
    const int kTiles = (kEnd - kBegin + HBK - 1) / HBK;

    const int tidx = threadIdx.x;
    const int lane = tidx & 31;
    const int g  = lane >> 2;
    const int tg = lane & 3;
    const int wm = (tidx >> 5) & 3;
    const int wn = (tidx >> 7);
    const int lt = lane >> 3;
    const int lr = lane & 7;

    float acc[2][8][4];
#pragma unroll
    for (int mi = 0; mi < 2; mi++)
#pragma unroll
        for (int ni = 0; ni < 8; ni++)
#pragma unroll
            for (int j = 0; j < 4; j++) acc[mi][ni][j] = 0.f;

    auto load_tile = [&](int t, int stage) {
        int kt = kBegin + t * HBK;
        __half* as = hsm + stage * (ASZ + BSZ);
        __half* bs = as + ASZ;
        if (!TRANS_A) {
#pragma unroll
            for (int i = 0; i < 4; i++) {
                int idx = tidx + i * 256;
                int m  = idx >> 3;
                int k8 = (idx & 7) << 3;
                bool p = (m0 + m < M) && (kt + k8 < kEnd);
                const __half* src = p ? &A[(size_t)(m0 + m) * lda + kt + k8] : A;
                cpa16(&as[m * APITCH + k8], src, p);
            }
        } else {
#pragma unroll
            for (int i = 0; i < 4; i++) {
                int idx = tidx + i * 256;
                int k  = idx >> 4;
                int m8 = (idx & 15) << 3;
                int gm = m0 + m8;
                bool p = (gm < M) && (kt + k < kEnd);
                const __half* src = p ? &A[(size_t)(kt + k) * lda + gm] : A;
                cpa16(&as[k * APITCH + m8], src, p);
            }
        }
#pragma unroll
        for (int i = 0; i < 4; i++) {
            int idx = tidx + i * 256;
            int k  = idx >> 4;
            int n8 = (idx & 15) << 3;
            bool p = (kt + k < kEnd);
            const __half* src = p ? &B[(size_t)(kt + k) * 128 + n8] : (const __half*)B;
            cpa16(&bs[k * BPITCH + n8], src, p);
        }
        cpa_commit();
    };

    int pre = kTiles < (HST - 1) ? kTiles : (HST - 1);
    for (int t = 0; t < pre; t++) load_tile(t, t % HST);
    for (int t = pre; t < HST - 1; t++) cpa_commit();

    unsigned smBase = (unsigned)__cvta_generic_to_shared(hsm);

    for (int t = 0; t < kTiles; t++) {
        asm volatile("cp.async.wait_group %0;\n" :: "n"(HST - 2));
        __syncthreads();
        if (t + HST - 1 < kTiles) load_tile(t + HST - 1, (t + HST - 1) % HST);
        else cpa_commit();

        unsigned as_u = smBase + (unsigned)((t % HST) * (ASZ + BSZ) * 2);
        unsigned bs_u = as_u + ASZ * 2;

#pragma unroll
        for (int kk = 0; kk < HBK; kk += 16) {
            unsigned af[2][4];
#pragma unroll
            for (int mi = 0; mi < 2; mi++) {
                int bm = wm * 32 + mi * 16;
                if (!TRANS_A) {
                    unsigned a = as_u + (unsigned)(((bm + (lt & 1) * 8 + lr) * APITCH
                                                   + kk + (lt >> 1) * 8) * 2);
                    ldsm_x4(af[mi], a);
                } else {
                    unsigned a = as_u + (unsigned)(((kk + (lt >> 1) * 8 + lr) * APITCH
                                                   + bm + (lt & 1) * 8) * 2);
                    ldsm_x4t(af[mi], a);
                }
            }
            unsigned bf[8][2];
#pragma unroll
            for (int nj = 0; nj < 4; nj++) {
                unsigned r[4];
                unsigned a = bs_u + (unsigned)(((kk + (lt & 1) * 8 + lr) * BPITCH
                                               + wn * 64 + nj * 16 + (lt >> 1) * 8) * 2);
                ldsm_x4t(r, a);
                bf[2 * nj    ][0] = r[0]; bf[2 * nj    ][1] = r[1];
                bf[2 * nj + 1][0] = r[2]; bf[2 * nj + 1][1] = r[3];
            }
#pragma unroll
            for (int mi = 0; mi < 2; mi++)
#pragma unroll
                for (int ni = 0; ni < 8; ni++)
                    mma_f16(acc[mi][ni], af[mi], bf[ni]);
        }
    }

    // ---- epilogue: atomic split-K with rowscale * 2^k(amax) ----
    const float undo = ldexpf(1.f, amax_k(amaxPtr));
#pragma unroll
    for (int mi = 0; mi < 2; mi++) {
#pragma unroll
        for (int h = 0; h < 2; h++) {
            int r = m0 + wm * 32 + mi * 16 + g + h * 8;
            if (r >= M) continue;
            float rs = rowscale[r] * undo;
#pragma unroll
            for (int ni = 0; ni < 8; ni++) {
                int cc = wn * 64 + ni * 8 + tg * 2;
                atomicAdd(&C[(size_t)r * 128 + cc    ], acc[mi][ni][h * 2 + 0] * rs);
                atomicAdd(&C[(size_t)r * 128 + cc + 1], acc[mi][ni][h * 2 + 1] * rs);
            }
        }
    }
}

// ============================================================================
// tf32 GEMM for the small K=128 GEMMs (fp32 out) with FUSED absmax.
// C[m,n] = rowscale[m]*(A[M,128] @ B[128,128] + bias); rowsel gating with
// blockIdx.z selecting B/bias slabs. amaxOut (nullable): atomicMax of |C|.
// ============================================================================
__global__ void __launch_bounds__(256, 1)
gemm256(const float* __restrict__ A, const float* __restrict__ B,
        float* __restrict__ C, int M,
        const float* __restrict__ bias, const float* __restrict__ rowscale,
        const int* __restrict__ rowsel, int ldbz, int biasz,
        unsigned* __restrict__ amaxOut)
{
    constexpr int K = 128;
    constexpr int APITCH = BK + 4;
    constexpr int ASZ = BM * APITCH;
    constexpr int BPITCH = 128 + 8;
    constexpr int BSZ = BK * BPITCH;
    extern __shared__ char smraw[];
    unsigned* sm = (unsigned*)smraw;

    const int m0 = blockIdx.x * BM;
    const int zt = blockIdx.z;
    B += (size_t)zt * ldbz;
    if (bias) bias += (size_t)zt * biasz;

    const int tidx = threadIdx.x;
    const int lane = tidx & 31;
    const int g  = lane >> 2;
    const int tg = lane & 3;
    const int wm = (tidx >> 5) & 3;
    const int wn = (tidx >> 7);

    float acc[4][8][4];
#pragma unroll
    for (int mi = 0; mi < 4; mi++)
#pragma unroll
        for (int ni = 0; ni < 8; ni++)
#pragma unroll
            for (int j = 0; j < 4; j++) acc[mi][ni][j] = 0.f;

    auto load_tile = [&](int t, int stage) {
        int kt = t * BK;
        unsigned* as = sm + stage * (ASZ + BSZ);
        unsigned* bs = as + ASZ;
#pragma unroll
        for (int i = 0; i < 8; i++) {
            int idx = tidx + i * 256;
            int m  = idx >> 3;
            int k4 = (idx & 7) << 2;
            bool p = (m0 + m < M);
            const float* src = p ? &A[(size_t)(m0 + m) * K + kt + k4] : A;
            cpa16(&as[m * APITCH + k4], src, p);
        }
#pragma unroll
        for (int i = 0; i < 4; i++) {
            int idx = tidx + i * 256;
            int k  = idx >> 5;
            int n4 = (idx & 31) << 2;
            cpa16(&bs[k * BPITCH + n4], &B[(size_t)(kt + k) * 128 + n4], true);
        }
        cpa_commit();
    };

    const int kTiles = K / BK;
    int pre = kTiles < (STAGES - 1) ? kTiles : (STAGES - 1);
    for (int t = 0; t < pre; t++) load_tile(t, t % STAGES);
    for (int t = pre; t < STAGES - 1; t++) cpa_commit();

    for (int t = 0; t < kTiles; t++) {
        asm volatile("cp.async.wait_group %0;\n" :: "n"(STAGES - 2));
        __syncthreads();
        if (t + STAGES - 1 < kTiles) load_tile(t + STAGES - 1, (t + STAGES - 1) % STAGES);
        else cpa_commit();

        const unsigned* as = sm + (t % STAGES) * (ASZ + BSZ);
        const unsigned* bs = as + ASZ;

#pragma unroll
        for (int kk = 0; kk < BK; kk += 8) {
            unsigned af[4][4];
#pragma unroll
            for (int mi = 0; mi < 4; mi++) {
                int bm = wm * 64 + mi * 16;
                af[mi][0] = f2tf32(as[(bm + g    ) * APITCH + kk + tg    ]);
                af[mi][1] = f2tf32(as[(bm + g + 8) * APITCH + kk + tg    ]);
                af[mi][2] = f2tf32(as[(bm + g    ) * APITCH + kk + tg + 4]);
                af[mi][3] = f2tf32(as[(bm + g + 8) * APITCH + kk + tg + 4]);
            }
            unsigned bf[8][2];
#pragma unroll
            for (int ni = 0; ni < 8; ni++) {
                int bn = wn * 64 + ni * 8;
                bf[ni][0] = bs[(kk + tg    ) * BPITCH + bn + g];
                bf[ni][1] = bs[(kk + tg + 4) * BPITCH + bn + g];
            }
#pragma unroll
            for (int mi = 0; mi < 4; mi++)
#pragma unroll
                for (int ni = 0; ni < 8; ni++)
                    mma_tf32(acc[mi][ni], af[mi], bf[ni]);
        }
    }

    float lmax = 0.f;
#pragma unroll
    for (int mi = 0; mi < 4; mi++) {
#pragma unroll
        for (int h = 0; h < 2; h++) {
            int r = m0 + wm * 64 + mi * 16 + g + h * 8;
            if (r >= M) continue;
            if (rowsel && rowsel[r] != zt) continue;
            float rs = rowscale ? rowscale[r] : 1.f;
#pragma unroll
            for (int ni = 0; ni < 8; ni++) {
                int cc = wn * 64 + ni * 8 + tg * 2;
                float v0 = acc[mi][ni][h * 2 + 0];
                float v1 = acc[mi][ni][h * 2 + 1];
                if (bias) { v0 += bias[cc]; v1 += bias[cc + 1]; }
                v0 *= rs; v1 *= rs;
                C[(size_t)r * 128 + cc    ] = v0;
                C[(size_t)r * 128 + cc + 1] = v1;
                lmax = fmaxf(lmax, fmaxf(fabsf(v0), fabsf(v1)));
            }
        }
    }
    if (amaxOut) {
#pragma unroll
        for (int o = 16; o; o >>= 1) lmax = fmaxf(lmax, __shfl_xor_sync(~0u, lmax, o));
        if (lane == 0) atomicMax(amaxOut, __float_as_uint(lmax));
    }
}

// ---------------- small kernels ----------------
__global__ void zero_kernel(float* __restrict__ p, int n) {
    int i = blockIdx.x * blockDim.x + threadIdx.x;
    if (i < n) p[i] = 0.f;
}
__global__ void reset_amax(unsigned* slot) { *slot = 0u; }

__global__ void absmax_kernel(const float* __restrict__ x, long long n4,
                              unsigned* __restrict__ out) {
    float m = 0.f;
    for (long long i = (long long)blockIdx.x * blockDim.x + threadIdx.x;
         i < n4; i += (long long)gridDim.x * blockDim.x) {
        float4 v = ((const float4*)x)[i];
        m = fmaxf(m, fmaxf(fmaxf(fabsf(v.x), fabsf(v.y)),
                           fmaxf(fabsf(v.z), fabsf(v.w))));
    }
#pragma unroll
    for (int o = 16; o; o >>= 1) m = fmaxf(m, __shfl_xor_sync(~0u, m, o));
    if ((threadIdx.x & 31) == 0) atomicMax(out, __float_as_uint(m));
}

// fp32 -> fp16 (RN), scaled by 2^-k(amax) (amaxPtr null => scale 1)
__global__ void f2h_dyn(__half* __restrict__ dst, const float* __restrict__ src,
                        long long n8, const unsigned* __restrict__ amaxPtr) {
    float s = amaxPtr ? ldexpf(1.f, -amax_k(amaxPtr)) : 1.f;
    long long i = (long long)blockIdx.x * blockDim.x + threadIdx.x;
    if (i < n8) {
        float4 a = ((const float4*)src)[2 * i];
        float4 b = ((const float4*)src)[2 * i + 1];
        __half2 h[4];
        h[0] = __floats2half2_rn(a.x * s, a.y * s);
        h[1] = __floats2half2_rn(a.z * s, a.w * s);
        h[2] = __floats2half2_rn(b.x * s, b.y * s);
        h[3] = __floats2half2_rn(b.z * s, b.w * s);
        ((uint4*)dst)[i] = *(uint4*)h;
    }
}

__global__ void round_tf32_kernel(float* __restrict__ dst, const float* __restrict__ src, int n4) {
    int i = blockIdx.x * blockDim.x + threadIdx.x;
    if (i < n4) {
        float4 v = ((const float4*)src)[i];
        v.x = roundtf(v.x); v.y = roundtf(v.y);
        v.z = roundtf(v.z); v.w = roundtf(v.w);
        ((float4*)dst)[i] = v;
    }
}

__global__ void fusion_kernel(const float* __restrict__ fw,
                              const float* __restrict__ X0,
                              const float* __restrict__ X1,
                              const float* __restrict__ X2,
                              float* __restrict__ out, int n) {
    float f0 = fw[0], f1 = fw[1], f2 = fw[2];
    float mx = fmaxf(f0, fmaxf(f1, f2));
    float e0 = expf(f0 - mx), e1 = expf(f1 - mx), e2 = expf(f2 - mx);
    float inv = 1.f / (e0 + e1 + e2);
    float w0 = e0 * inv, w1 = e1 * inv, w2 = e2 * inv;
    int i = blockIdx.x * blockDim.x + threadIdx.x;
    if (i < n) out[i] = w0 * X0[i] + w1 * X1[i] + w2 * X2[i];
}

static inline int chunk64(int K, int S) {
    int tiles = (K + HBK - 1) / HBK;
    int per = (tiles + S - 1) / S;
    return per * HBK;
}

extern "C" void kernel_launch(void* const* d_in, const int* in_sizes, int n_in,
                              void* d_out, int out_size) {
    const float* emb = (const float*)d_in[0];
    const float* Wt  = (const float*)d_in[1];
    const float* bt  = (const float*)d_in[2];
    const float* W1  = (const float*)d_in[3];
    const float* b1  = (const float*)d_in[4];
    const float* W2  = (const float*)d_in[5];
    const float* b2  = (const float*)d_in[6];
    const float* fw  = (const float*)d_in[7];
    const float* H   = (const float*)d_in[8];
    const float* dv  = (const float*)d_in[9];
    const float* de  = (const float*)d_in[10];
    const int*   tid = (const int*)d_in[11];

    const int D = in_sizes[4];          // 128
    const int N = in_sizes[9];          // 20000
    const int E = in_sizes[10];         // 8000
    const int T = in_sizes[2] / D;      // 5

    float* buf = nullptr;
    cudaGetSymbolAddress((void**)&buf, g_buf);
    __half* hb = nullptr;
    cudaGetSymbolAddress((void**)&hb, g_hbuf);
    unsigned* sc = nullptr;
    cudaGetSymbolAddress((void**)&sc, g_sc);

    size_t nd = (size_t)N * D, ed = (size_t)E * D, ne = (size_t)N * E;
    float* X0  = buf;
    float* X1  = X0 + nd;
    float* X2  = X1 + nd;
    float* Yf  = X2 + nd;
    float* Mm  = Yf + nd;
    float* Wtr = Mm + ed;
    float* W1r = Wtr + (size_t)T * D * D;
    float* W2r = W1r + (size_t)D * D;
    __half* Hh  = hb;
    __half* Yh  = Hh + ne;
    __half* Mmh = Yh + nd;

    unsigned* amaxY = sc + 0;
    unsigned* amaxM = sc + 1;

    const int smemG  = STAGES * (BM * (BK + 4) + BK * (128 + 8)) * 4;
    const int smemHT = HST * (HBK * (HBM + 8) + HBK * (128 + 8)) * 2;
    const int smemHN = HST * (HBM * (HBK + 8) + HBK * (128 + 8)) * 2;

    static cudaStream_t s2 = nullptr;
    static cudaEvent_t evFork = nullptr, evSide = nullptr;
    static bool attr_done = false;
    if (!attr_done) {
        cudaFuncSetAttribute(gemm256,      cudaFuncAttributeMaxDynamicSharedMemorySize, smemG);
        cudaFuncSetAttribute(hgemm<true>,  cudaFuncAttributeMaxDynamicSharedMemorySize, smemHT);
        cudaFuncSetAttribute(hgemm<false>, cudaFuncAttributeMaxDynamicSharedMemorySize, smemHN);
        cudaStreamCreateWithFlags(&s2, cudaStreamNonBlocking);
        cudaEventCreateWithFlags(&evFork, cudaEventDisableTiming);
        cudaEventCreateWithFlags(&evSide, cudaEventDisableTiming);
        attr_done = true;
    }

    dim3 blk(256);
    int mt_n  = (N + BM - 1) / BM;      // 79 (tf32)
    int ht_n  = (N + HBM - 1) / HBM;    // 157
    int ht_e  = (E + HBM - 1) / HBM;    // 63
    const int S1 = 9;                   // trans split-K: 567 CTAs
    const int S2 = 7;                   // non-trans: 1099 CTAs
    int ch1 = chunk64(N, S1);
    int ch2 = chunk64(E, S2);
    int zt_ = 256;
    const int RB = 1024;
    int w_n4 = D * D / 4;

    // ---- fork: all independent prep on side stream ----
    cudaEventRecord(evFork, 0);
    cudaStreamWaitEvent(s2, evFork, 0);
    {
        // resets must precede first producer epilogues (joined before hgemm1,
        // and amaxY atomicMax happens on main AFTER join-ordered reset? No:
        // layer-1 gemm256 epilogue writes amaxY before the join. So amaxY
        // reset goes on MAIN before that launch; only amaxM reset + zeros +
        // weight rounding + H conversion ride the side stream.)
        reset_amax<<<1, 1, 0, s2>>>(amaxM);
        round_tf32_kernel<<<(w_n4 + 255) / 256, 256, 0, s2>>>(W1r, W1, w_n4);
        round_tf32_kernel<<<(w_n4 + 255) / 256, 256, 0, s2>>>(W2r, W2, w_n4);
        zero_kernel<<<(int)((ed + zt_ - 1) / zt_), zt_, 0, s2>>>(Mm, (int)ed);
        zero_kernel<<<(int)((nd + zt_ - 1) / zt_), zt_, 0, s2>>>(X1, (int)nd);
        zero_kernel<<<(int)((nd + zt_ - 1) / zt_), zt_, 0, s2>>>(X2, (int)nd);
        long long h8 = (long long)(ne / 8);
        f2h_dyn<<<(int)((h8 + 255) / 256), 256, 0, s2>>>(Hh, H, h8, nullptr);
        cudaEventRecord(evSide, s2);
    }

    // ---- main chain (overlapped with side stream) ----
    int wt_n4 = T * D * D / 4;
    round_tf32_kernel<<<(wt_n4 + 255) / 256, 256>>>(Wtr, Wt, wt_n4);
    reset_amax<<<1, 1>>>(amaxY);

    gemm256<<<dim3(mt_n, 1, T), blk, smemG>>>(
        emb, Wtr, X0, N, bt, nullptr, tid, D * D, D, nullptr);

    bool joined = false;
    for (int layer = 0; layer < 2; layer++) {
        const float* Xin = (layer == 0) ? X0 : X1;
        float* Xout      = (layer == 0) ? X1 : X2;
        const float* W   = (layer == 0) ? W1r : W2r;
        const float* b   = (layer == 0) ? b1 : b2;

        if (layer == 0) {
            // W1r ready only after join for layer 0's gemm256? W1r is rounded
            // on s2; gemm256 below needs it -> join here (also covers zeros/H).
            cudaStreamWaitEvent(0, evSide, 0);
            joined = true;
        }
        // Yf = dv * (Xin @ W + b); fused absmax -> amaxY
        gemm256<<<dim3(mt_n, 1, 1), blk, smemG>>>(
            Xin, W, Yf, N, b, dv, nullptr, 0, 0, amaxY);
        // convert Y with scale derived in-kernel from amaxY
        f2h_dyn<<<(int)((nd / 8 + 255) / 256), 256>>>(Yh, Yf, (long long)(nd / 8), amaxY);
        // Mm = de * (Hh^T @ Yh) * 2^kY
        hgemm<true><<<dim3(ht_e, S1, 1), blk, smemHT>>>(Hh, Yh, Mm, E, N, E, de, amaxY, ch1);
        // absmax + convert Mm
        absmax_kernel<<<RB, 256>>>(Mm, (long long)(ed / 4), amaxM);
        f2h_dyn<<<(int)((ed / 8 + 255) / 256), 256>>>(Mmh, Mm, (long long)(ed / 8), amaxM);
        // Xout = dv * (Hh @ Mmh) * 2^kM
        hgemm<false><<<dim3(ht_n, S2, 1), blk, smemHN>>>(Hh, Mmh, Xout, N, E, E, dv, amaxM, ch2);

        if (layer == 0) {
            // recycle scratch for layer 2 (cheap, ordered on main stream)
            reset_amax<<<1, 1>>>(amaxY);
            reset_amax<<<1, 1>>>(amaxM);
            zero_kernel<<<(int)((ed + zt_ - 1) / zt_), zt_>>>(Mm, (int)ed);
        }
    }

    // ---- fusion ----
    fusion_kernel<<<(int)((nd + zt_ - 1) / zt_), zt_>>>(
        fw, X0, X1, X2, (float*)d_out, (int)nd);
}